// round 2
// baseline (speedup 1.0000x reference)
#include <cuda_runtime.h>
#include <math.h>

#define Bc 2
#define Tc 4096
#define Ec 1024
#define Hc 16
#define Dc 64
#define Pc 64
#define PMc 512
#define CHc 128
#define NCc 32
#define BHc 32

typedef unsigned long long u64;

// ---- packed fp32x2 helpers (FFMA2) -----------------------------------------
__device__ __forceinline__ u64 dup2(float v) {
    u64 r; asm("mov.b64 %0,{%1,%2};" : "=l"(r) : "f"(v), "f"(v)); return r;
}
__device__ __forceinline__ float2 up2(u64 v) {
    float2 r; asm("mov.b64 {%0,%1},%2;" : "=f"(r.x), "=f"(r.y) : "l"(v)); return r;
}
__device__ __forceinline__ void fma2(u64 &d, u64 a, u64 b) {
    asm("fma.rn.f32x2 %0,%1,%2,%0;" : "+l"(d) : "l"(a), "l"(b));
}

// ---------------- scratch (device globals; no allocations allowed) ----------
__device__ float g_qkv[(size_t)Bc*Tc*3*Ec];
__device__ float g_qn [(size_t)BHc*Tc*Dc];
__device__ float g_kn [(size_t)BHc*Tc*Dc];
__device__ float g_v  [(size_t)BHc*Tc*Dc];
__device__ float g_qf [(size_t)BHc*NCc*PMc*CHc];     // (b,h,c, f, i)
__device__ float g_kf [(size_t)BHc*NCc*PMc*CHc];
__device__ float g_ckv[(size_t)BHc*NCc*PMc*Dc];      // (b,h,c, f, d)
__device__ float g_ks [(size_t)BHc*NCc*PMc];
__device__ float g_o  [(size_t)BHc*Tc*Dc];
__device__ float g_nrm[(size_t)BHc*Tc];

// ---------------- generic fp32 GEMM: C[M,N] = A[M,K] @ W[N,K]^T + bias ------
__global__ __launch_bounds__(256) void gemm_bias_k(
    const float* __restrict__ A, const float* __restrict__ W,
    const float* __restrict__ bias, float* __restrict__ C, int N, int K)
{
    __shared__ float2 As2[16][128];   // A duplicated: {a,a}
    __shared__ float  Bs[16][128];
    int tid = threadIdx.x;
    int bm = blockIdx.y * 128, bn = blockIdx.x * 128;
    int tm = (tid >> 4) << 3, tn = (tid & 15) << 3;
    u64 acc[8][4] = {};
    for (int k0 = 0; k0 < K; k0 += 16) {
        #pragma unroll
        for (int l = 0; l < 2; l++) {
            int idx = tid * 2 + l;
            int r = idx >> 2, c = (idx & 3) << 2;
            float4 va = *(const float4*)(A + (size_t)(bm + r) * K + k0 + c);
            As2[c+0][r] = make_float2(va.x, va.x);
            As2[c+1][r] = make_float2(va.y, va.y);
            As2[c+2][r] = make_float2(va.z, va.z);
            As2[c+3][r] = make_float2(va.w, va.w);
            float4 vb = *(const float4*)(W + (size_t)(bn + r) * K + k0 + c);
            Bs[c+0][r]=vb.x; Bs[c+1][r]=vb.y; Bs[c+2][r]=vb.z; Bs[c+3][r]=vb.w;
        }
        __syncthreads();
        #pragma unroll
        for (int kk = 0; kk < 16; kk++) {
            u64 a[8], b[4];
            { ulonglong2 t = *(const ulonglong2*)&As2[kk][tm+0]; a[0]=t.x; a[1]=t.y; }
            { ulonglong2 t = *(const ulonglong2*)&As2[kk][tm+2]; a[2]=t.x; a[3]=t.y; }
            { ulonglong2 t = *(const ulonglong2*)&As2[kk][tm+4]; a[4]=t.x; a[5]=t.y; }
            { ulonglong2 t = *(const ulonglong2*)&As2[kk][tm+6]; a[6]=t.x; a[7]=t.y; }
            { ulonglong2 t = *(const ulonglong2*)&Bs[kk][tn];   b[0]=t.x; b[1]=t.y; }
            { ulonglong2 t = *(const ulonglong2*)&Bs[kk][tn+4]; b[2]=t.x; b[3]=t.y; }
            #pragma unroll
            for (int i = 0; i < 8; i++)
                #pragma unroll
                for (int j = 0; j < 4; j++) fma2(acc[i][j], a[i], b[j]);
        }
        __syncthreads();
    }
    #pragma unroll
    for (int i = 0; i < 8; i++) {
        float2 p0 = up2(acc[i][0]), p1 = up2(acc[i][1]);
        float2 p2 = up2(acc[i][2]), p3 = up2(acc[i][3]);
        float4 o0, o1;
        o0.x = p0.x + bias[bn+tn+0]; o0.y = p0.y + bias[bn+tn+1];
        o0.z = p1.x + bias[bn+tn+2]; o0.w = p1.y + bias[bn+tn+3];
        o1.x = p2.x + bias[bn+tn+4]; o1.y = p2.y + bias[bn+tn+5];
        o1.z = p3.x + bias[bn+tn+6]; o1.w = p3.y + bias[bn+tn+7];
        *(float4*)(C + (size_t)(bm+tm+i)*N + bn+tn)     = o0;
        *(float4*)(C + (size_t)(bm+tm+i)*N + bn+tn + 4) = o1;
    }
}

// ---------------- output GEMM: reads A from g_o (B,H,T,D) layout ------------
__global__ __launch_bounds__(256) void gemm_out_k(
    const float* __restrict__ W, const float* __restrict__ bias, float* __restrict__ C)
{
    __shared__ float2 As2[16][128];
    __shared__ float  Bs[16][128];
    const int K = Ec, N = Ec;
    int tid = threadIdx.x;
    int bm = blockIdx.y * 128, bn = blockIdx.x * 128;
    int tm = (tid >> 4) << 3, tn = (tid & 15) << 3;
    u64 acc[8][4] = {};
    for (int k0 = 0; k0 < K; k0 += 16) {
        int h = k0 >> 6;
        #pragma unroll
        for (int l = 0; l < 2; l++) {
            int idx = tid * 2 + l;
            int r = idx >> 2, cc = (idx & 3) << 2;
            int rg = bm + r;
            int b = rg >> 12, t = rg & 4095;
            int d = (k0 & 63) + cc;
            float4 va = *(const float4*)(g_o + ((size_t)(b*Hc + h)*Tc + t)*Dc + d);
            As2[cc+0][r] = make_float2(va.x, va.x);
            As2[cc+1][r] = make_float2(va.y, va.y);
            As2[cc+2][r] = make_float2(va.z, va.z);
            As2[cc+3][r] = make_float2(va.w, va.w);
            float4 vb = *(const float4*)(W + (size_t)(bn + r)*K + k0 + cc);
            Bs[cc+0][r]=vb.x; Bs[cc+1][r]=vb.y; Bs[cc+2][r]=vb.z; Bs[cc+3][r]=vb.w;
        }
        __syncthreads();
        #pragma unroll
        for (int kk = 0; kk < 16; kk++) {
            u64 a[8], b[4];
            { ulonglong2 t = *(const ulonglong2*)&As2[kk][tm+0]; a[0]=t.x; a[1]=t.y; }
            { ulonglong2 t = *(const ulonglong2*)&As2[kk][tm+2]; a[2]=t.x; a[3]=t.y; }
            { ulonglong2 t = *(const ulonglong2*)&As2[kk][tm+4]; a[4]=t.x; a[5]=t.y; }
            { ulonglong2 t = *(const ulonglong2*)&As2[kk][tm+6]; a[6]=t.x; a[7]=t.y; }
            { ulonglong2 t = *(const ulonglong2*)&Bs[kk][tn];   b[0]=t.x; b[1]=t.y; }
            { ulonglong2 t = *(const ulonglong2*)&Bs[kk][tn+4]; b[2]=t.x; b[3]=t.y; }
            #pragma unroll
            for (int i = 0; i < 8; i++)
                #pragma unroll
                for (int j = 0; j < 4; j++) fma2(acc[i][j], a[i], b[j]);
        }
        __syncthreads();
    }
    #pragma unroll
    for (int i = 0; i < 8; i++) {
        float2 p0 = up2(acc[i][0]), p1 = up2(acc[i][1]);
        float2 p2 = up2(acc[i][2]), p3 = up2(acc[i][3]);
        float4 o0, o1;
        o0.x = p0.x + bias[bn+tn+0]; o0.y = p0.y + bias[bn+tn+1];
        o0.z = p1.x + bias[bn+tn+2]; o0.w = p1.y + bias[bn+tn+3];
        o1.x = p2.x + bias[bn+tn+4]; o1.y = p2.y + bias[bn+tn+5];
        o1.z = p3.x + bias[bn+tn+6]; o1.w = p3.y + bias[bn+tn+7];
        *(float4*)(C + (size_t)(bm+tm+i)*N + bn+tn)     = o0;
        *(float4*)(C + (size_t)(bm+tm+i)*N + bn+tn + 4) = o1;
    }
}

// ---------------- split qkv into heads, l2-normalize q,k --------------------
__global__ void split_norm_k()
{
    int gid = blockIdx.x;
    int h = gid & 15;
    int bt = gid >> 4;
    int lane = threadIdx.x;
    const float* row = g_qkv + (size_t)bt * (3*Ec);
    int col = h*64 + lane;
    float q0 = row[col],        q1 = row[col+32];
    float k0 = row[Ec+col],     k1 = row[Ec+col+32];
    float v0 = row[2*Ec+col],   v1 = row[2*Ec+col+32];
    float sq = q0*q0 + q1*q1;
    float sk = k0*k0 + k1*k1;
    #pragma unroll
    for (int off = 16; off > 0; off >>= 1) {
        sq += __shfl_xor_sync(0xffffffffu, sq, off);
        sk += __shfl_xor_sync(0xffffffffu, sk, off);
    }
    float rq = 1.f / fmaxf(sqrtf(sq), 1e-12f);
    float rk = 1.f / fmaxf(sqrtf(sk), 1e-12f);
    int b = bt >> 12, t = bt & 4095;
    size_t o = ((size_t)(b*Hc + h)*Tc + t)*Dc + lane;
    g_qn[o] = q0*rq; g_qn[o+32] = q1*rq;
    g_kn[o] = k0*rk; g_kn[o+32] = k1*rk;
    g_v[o]  = v0;    g_v[o+32]  = v1;
}

// ---------------- feature map: (poly x prf) per chunk, token-minor layout ---
__global__ __launch_bounds__(256) void features_k(
    const float* __restrict__ omega, const float* __restrict__ poly_w,
    const float* __restrict__ qnodes, const float* __restrict__ qweights)
{
    __shared__ float xs[64*129];
    __shared__ float om[64*8];
    __shared__ float prf[128*8];
    int bhc = blockIdx.x;
    int isK = blockIdx.y;
    int bh = bhc >> 5, c = bhc & 31;
    int h = bh & 15;
    const float* src = (isK ? g_kn : g_qn) + ((size_t)bh*Tc + c*CHc)*Dc;
    float* dst = (isK ? g_kf : g_qf) + (size_t)bhc*PMc*CHc;
    int tid = threadIdx.x;
    #pragma unroll
    for (int l = 0; l < 32; l++) {
        int idx = tid + l*256;
        int i = idx >> 6, d = idx & 63;
        xs[d*129 + i] = src[(size_t)i*64 + d];
    }
    om[tid]       = omega[h*512 + tid];
    om[tid + 256] = omega[h*512 + tid + 256];
    __syncthreads();
    float s0 = qnodes[0];
    float sq2s = sqrtf(fmaxf(2.f*s0, 0.f));
    float wq = sqrtf(fmaxf(qweights[0], 0.f));
    float prescale = 0.3535533905932738f * wq;
    #pragma unroll
    for (int l = 0; l < 4; l++) {
        int pair = tid + l*256;
        int i = pair >> 3, m = pair & 7;
        float a = 0.f;
        #pragma unroll
        for (int d = 0; d < 64; d++) a += xs[d*129 + i] * om[d*8 + m];
        float e = fminf(fmaxf(a * sq2s - s0, -20.f), 20.f);
        prf[i*8 + m] = expf(e) * prescale;
    }
    __syncthreads();
    int ti = (tid >> 4) << 3, tp = (tid & 15) << 2;
    u64 acc2[8][2] = {};
    const float* pwp = poly_w + h*4096;
    for (int d = 0; d < 64; d++) {
        float a[8];
        #pragma unroll
        for (int x = 0; x < 8; x++) a[x] = xs[d*129 + ti + x];
        ulonglong2 bb = *(const ulonglong2*)(pwp + d*64 + tp);
        #pragma unroll
        for (int i2 = 0; i2 < 8; i2++) {
            u64 ad = dup2(a[i2]);
            fma2(acc2[i2][0], ad, bb.x);
            fma2(acc2[i2][1], ad, bb.y);
        }
    }
    float acc[8][4];
    #pragma unroll
    for (int i2 = 0; i2 < 8; i2++) {
        float2 p0 = up2(acc2[i2][0]), p1 = up2(acc2[i2][1]);
        acc[i2][0] = p0.x*p0.x*0.125f;
        acc[i2][1] = p0.y*p0.y*0.125f;
        acc[i2][2] = p1.x*p1.x*0.125f;
        acc[i2][3] = p1.y*p1.y*0.125f;
    }
    #pragma unroll
    for (int j = 0; j < 4; j++) {
        int p = tp + j;
        #pragma unroll
        for (int m = 0; m < 8; m++) {
            float vals[8];
            #pragma unroll
            for (int i2 = 0; i2 < 8; i2++) vals[i2] = acc[i2][j] * prf[(ti+i2)*8 + m];
            float* outp = dst + (size_t)(p*8 + m)*CHc + ti;
            *(float4*)outp     = *(float4*)vals;
            *(float4*)(outp+4) = *(float4*)(vals+4);
        }
    }
}

// ---------------- pass A: per-chunk kv[f][d] = sum_i kf[f][i] v[i][d] -------
// tile: 256 f x 64 d, K=128 over i, 256 threads, 8x8 micro-tile, FFMA2
__global__ __launch_bounds__(256) void passA_k()
{
    __shared__ float2 kfs2[16][256];   // [ii][f] duplicated
    __shared__ float  vs[16][64];      // [ii][d]
    int bhc = blockIdx.x;
    int f0 = blockIdx.y << 8;
    int bh = bhc >> 5, c = bhc & 31;
    const float* kfbase = g_kf + (size_t)bhc*PMc*CHc;
    const float* vbase  = g_v  + ((size_t)bh*Tc + c*CHc)*Dc;
    int tid = threadIdx.x;
    int tf = (tid >> 3) << 3, td = (tid & 7) << 3;
    int frow = tid >> 2, iq = tid & 3;
    u64 acc[8][4] = {};
    float ks_acc[4] = {};
    for (int i0 = 0; i0 < 128; i0 += 16) {
        #pragma unroll
        for (int p = 0; p < 4; p++) {
            int fl = frow + p*64;
            float4 v4 = *(const float4*)(kfbase + (size_t)(f0 + fl)*CHc + i0 + iq*4);
            kfs2[iq*4+0][fl] = make_float2(v4.x, v4.x);
            kfs2[iq*4+1][fl] = make_float2(v4.y, v4.y);
            kfs2[iq*4+2][fl] = make_float2(v4.z, v4.z);
            kfs2[iq*4+3][fl] = make_float2(v4.w, v4.w);
            ks_acc[p] += v4.x + v4.y + v4.z + v4.w;
        }
        {
            int r = tid >> 4, cc = (tid & 15) << 2;
            *(float4*)&vs[r][cc] = *(const float4*)(vbase + (size_t)(i0+r)*64 + cc);
        }
        __syncthreads();
        #pragma unroll
        for (int kk = 0; kk < 16; kk++) {
            u64 a[8], b[4];
            { ulonglong2 t = *(const ulonglong2*)&kfs2[kk][tf+0]; a[0]=t.x; a[1]=t.y; }
            { ulonglong2 t = *(const ulonglong2*)&kfs2[kk][tf+2]; a[2]=t.x; a[3]=t.y; }
            { ulonglong2 t = *(const ulonglong2*)&kfs2[kk][tf+4]; a[4]=t.x; a[5]=t.y; }
            { ulonglong2 t = *(const ulonglong2*)&kfs2[kk][tf+6]; a[6]=t.x; a[7]=t.y; }
            { ulonglong2 t = *(const ulonglong2*)&vs[kk][td];     b[0]=t.x; b[1]=t.y; }
            { ulonglong2 t = *(const ulonglong2*)&vs[kk][td+4];   b[2]=t.x; b[3]=t.y; }
            #pragma unroll
            for (int i = 0; i < 8; i++)
                #pragma unroll
                for (int j = 0; j < 4; j++) fma2(acc[i][j], a[i], b[j]);
        }
        __syncthreads();
    }
    float* outp = g_ckv + (size_t)bhc*PMc*Dc + (size_t)f0*Dc;
    #pragma unroll
    for (int i = 0; i < 8; i++) {
        float2 p0 = up2(acc[i][0]), p1 = up2(acc[i][1]);
        float2 p2 = up2(acc[i][2]), p3 = up2(acc[i][3]);
        *(float4*)(outp + (size_t)(tf+i)*64 + td)     = make_float4(p0.x,p0.y,p1.x,p1.y);
        *(float4*)(outp + (size_t)(tf+i)*64 + td + 4) = make_float4(p2.x,p2.y,p3.x,p3.y);
    }
    #pragma unroll
    for (int p = 0; p < 4; p++) {
        float s = ks_acc[p];
        s += __shfl_xor_sync(0xffffffffu, s, 1);
        s += __shfl_xor_sync(0xffffffffu, s, 2);
        if (iq == 0) g_ks[(size_t)bhc*PMc + f0 + frow + p*64] = s;
    }
}

// ---------------- exclusive prefix over chunks -------------------------------
__global__ void prefix_kv_k()
{
    size_t idx = (size_t)blockIdx.x*256 + threadIdx.x;
    size_t bh = idx / (PMc*Dc);
    size_t rem = idx % (PMc*Dc);
    float acc = 0.f;
    #pragma unroll
    for (int c = 0; c < NCc; c++) {
        size_t p = (bh*NCc + c)*(size_t)(PMc*Dc) + rem;
        float v = g_ckv[p];
        g_ckv[p] = acc;
        acc += v;
    }
}
__global__ void prefix_ks_k()
{
    size_t idx = (size_t)blockIdx.x*256 + threadIdx.x;
    size_t bh = idx / PMc;
    size_t rem = idx % PMc;
    float acc = 0.f;
    #pragma unroll
    for (int c = 0; c < NCc; c++) {
        size_t p = (bh*NCc + c)*(size_t)PMc + rem;
        float v = g_ks[p];
        g_ks[p] = acc;
        acc += v;
    }
}

// ---------------- pass C1: masked scores, intra context, row sums -----------
__global__ __launch_bounds__(256) void chunk_scores_k()
{
    extern __shared__ float sm[];
    float* S = sm;                                 // [128][129]
    float2 (*qs2)[128] = (float2(*)[128])(sm + 128*129);  // dup q tile
    float* ksm = sm + 128*129 + 16*256;            // [16][128]
    int bhc = blockIdx.x;
    int bh = bhc >> 5, c = bhc & 31;
    const float* qb = g_qf + (size_t)bhc*PMc*CHc;
    const float* kb = g_kf + (size_t)bhc*PMc*CHc;
    int tid = threadIdx.x;
    int tm = (tid >> 4) << 3, tn = (tid & 15) << 3;
    u64 acc[8][4] = {};
    for (int k0 = 0; k0 < PMc; k0 += 16) {
        #pragma unroll
        for (int l = 0; l < 2; l++) {
            int idx = tid*2 + l;
            int r = idx >> 5, cc = (idx & 31) << 2;
            float4 va = *(const float4*)(qb + (size_t)(k0+r)*CHc + cc);
            qs2[r][cc+0] = make_float2(va.x, va.x);
            qs2[r][cc+1] = make_float2(va.y, va.y);
            qs2[r][cc+2] = make_float2(va.z, va.z);
            qs2[r][cc+3] = make_float2(va.w, va.w);
            *(float4*)&ksm[r*128 + cc] = *(const float4*)(kb + (size_t)(k0+r)*CHc + cc);
        }
        __syncthreads();
        #pragma unroll
        for (int kk = 0; kk < 16; kk++) {
            u64 a[8], b[4];
            { ulonglong2 t = *(const ulonglong2*)&qs2[kk][tm+0]; a[0]=t.x; a[1]=t.y; }
            { ulonglong2 t = *(const ulonglong2*)&qs2[kk][tm+2]; a[2]=t.x; a[3]=t.y; }
            { ulonglong2 t = *(const ulonglong2*)&qs2[kk][tm+4]; a[4]=t.x; a[5]=t.y; }
            { ulonglong2 t = *(const ulonglong2*)&qs2[kk][tm+6]; a[6]=t.x; a[7]=t.y; }
            { ulonglong2 t = *(const ulonglong2*)&ksm[kk*128+tn];   b[0]=t.x; b[1]=t.y; }
            { ulonglong2 t = *(const ulonglong2*)&ksm[kk*128+tn+4]; b[2]=t.x; b[3]=t.y; }
            #pragma unroll
            for (int i = 0; i < 8; i++)
                #pragma unroll
                for (int j = 0; j < 4; j++) fma2(acc[i][j], a[i], b[j]);
        }
        __syncthreads();
    }
    // unpack, mask, stash S, row sums
    #pragma unroll
    for (int i = 0; i < 8; i++) {
        float accf[8];
        float2 p0 = up2(acc[i][0]), p1 = up2(acc[i][1]);
        float2 p2 = up2(acc[i][2]), p3 = up2(acc[i][3]);
        accf[0]=p0.x; accf[1]=p0.y; accf[2]=p1.x; accf[3]=p1.y;
        accf[4]=p2.x; accf[5]=p2.y; accf[6]=p3.x; accf[7]=p3.y;
        int ri = tm + i;
        float s = 0.f;
        #pragma unroll
        for (int j = 0; j < 8; j++) {
            int cj = tn + j;
            float v = (cj <= ri) ? accf[j] : 0.f;
            S[ri*129 + cj] = v;
            s += v;
        }
        #pragma unroll
        for (int off = 8; off > 0; off >>= 1) s += __shfl_xor_sync(0xffffffffu, s, off);
        if ((tid & 15) == 0) g_nrm[(size_t)bh*Tc + c*CHc + ri] = s;
    }
    __syncthreads();
    // phase 2: intra = S @ v
    float* vsm = sm + 128*129;                     // [128][64]
    #pragma unroll
    for (int l = 0; l < 8; l++) {
        int idx = tid + l*256;
        int ii = idx >> 4, d = (idx & 15) << 2;
        *(float4*)&vsm[ii*64 + d] =
            *(const float4*)(g_v + ((size_t)bh*Tc + c*CHc + ii)*Dc + d);
    }
    __syncthreads();
    int ti = tm;
    int td = (tid & 15) << 2;
    float o[8][4] = {};
    for (int k = 0; k < 128; k++) {
        float4 bv = *(const float4*)&vsm[k*64 + td];
        #pragma unroll
        for (int i = 0; i < 8; i++) {
            float a = S[(ti+i)*129 + k];
            o[i][0]+=a*bv.x; o[i][1]+=a*bv.y; o[i][2]+=a*bv.z; o[i][3]+=a*bv.w;
        }
    }
    #pragma unroll
    for (int i = 0; i < 8; i++) {
        float4 ov = make_float4(o[i][0],o[i][1],o[i][2],o[i][3]);
        *(float4*)(g_o + ((size_t)bh*Tc + c*CHc + ti + i)*Dc + td) = ov;
    }
}

// ---------------- pass C2: history context + norm + finalize ----------------
// 128 threads, tile 128 tokens x 64 d, 8x8 micro-tile, FFMA2
__global__ __launch_bounds__(128) void chunk_hist_k()
{
    __shared__ float2 qs2[16][128];
    __shared__ float  kvs[16][64];
    __shared__ float  kst[16];
    int bhc = blockIdx.x;
    int bh = bhc >> 5, c = bhc & 31;
    const float* qb  = g_qf  + (size_t)bhc*PMc*CHc;
    const float* kvb = g_ckv + (size_t)bhc*PMc*Dc;
    const float* ksb = g_ks  + (size_t)bhc*PMc;
    int tid = threadIdx.x;
    int ti = (tid >> 3) << 3, td = (tid & 7) << 3;
    u64 acc[8][4] = {};
    u64 an2[8] = {};
    for (int k0 = 0; k0 < PMc; k0 += 16) {
        #pragma unroll
        for (int l = 0; l < 4; l++) {
            int idx = tid + l*128;
            int r = idx >> 5, cc = (idx & 31) << 2;
            float4 va = *(const float4*)(qb + (size_t)(k0+r)*CHc + cc);
            qs2[r][cc+0] = make_float2(va.x, va.x);
            qs2[r][cc+1] = make_float2(va.y, va.y);
            qs2[r][cc+2] = make_float2(va.z, va.z);
            qs2[r][cc+3] = make_float2(va.w, va.w);
        }
        #pragma unroll
        for (int l = 0; l < 2; l++) {
            int idx = tid*2 + l;
            int r = idx >> 4, cc = (idx & 15) << 2;
            *(float4*)&kvs[r][cc] = *(const float4*)(kvb + (size_t)(k0+r)*Dc + cc);
        }
        if (tid < 16) kst[tid] = ksb[k0 + tid];
        __syncthreads();
        #pragma unroll
        for (int kk = 0; kk < 16; kk++) {
            u64 a[8], b[4];
            { ulonglong2 t = *(const ulonglong2*)&qs2[kk][ti+0]; a[0]=t.x; a[1]=t.y; }
            { ulonglong2 t = *(const ulonglong2*)&qs2[kk][ti+2]; a[2]=t.x; a[3]=t.y; }
            { ulonglong2 t = *(const ulonglong2*)&qs2[kk][ti+4]; a[4]=t.x; a[5]=t.y; }
            { ulonglong2 t = *(const ulonglong2*)&qs2[kk][ti+6]; a[6]=t.x; a[7]=t.y; }
            { ulonglong2 t = *(const ulonglong2*)&kvs[kk][td];   b[0]=t.x; b[1]=t.y; }
            { ulonglong2 t = *(const ulonglong2*)&kvs[kk][td+4]; b[2]=t.x; b[3]=t.y; }
            u64 kd = dup2(kst[kk]);
            #pragma unroll
            for (int i = 0; i < 8; i++) {
                fma2(an2[i], a[i], kd);
                #pragma unroll
                for (int j = 0; j < 4; j++) fma2(acc[i][j], a[i], b[j]);
            }
        }
        __syncthreads();
    }
    #pragma unroll
    for (int i = 0; i < 8; i++) {
        size_t tok = (size_t)bh*Tc + c*CHc + ti + i;
        float nrm = up2(an2[i]).x + g_nrm[tok] + 1e-6f;
        float inv = 1.f / nrm;
        float2 p0 = up2(acc[i][0]), p1 = up2(acc[i][1]);
        float2 p2 = up2(acc[i][2]), p3 = up2(acc[i][3]);
        float4* po0 = (float4*)(g_o + tok*Dc + td);
        float4* po1 = (float4*)(g_o + tok*Dc + td + 4);
        float4 c0 = *po0, c1 = *po1;
        c0.x = (c0.x + p0.x) * inv; c0.y = (c0.y + p0.y) * inv;
        c0.z = (c0.z + p1.x) * inv; c0.w = (c0.w + p1.y) * inv;
        c1.x = (c1.x + p2.x) * inv; c1.y = (c1.y + p2.y) * inv;
        c1.z = (c1.z + p3.x) * inv; c1.w = (c1.w + p3.y) * inv;
        *po0 = c0; *po1 = c1;
    }
}

// ---------------- host launcher ---------------------------------------------
extern "C" void kernel_launch(void* const* d_in, const int* in_sizes, int n_in,
                              void* d_out, int out_size)
{
    const float* x        = (const float*)d_in[0];
    const float* qkv_w    = (const float*)d_in[1];
    const float* qkv_b    = (const float*)d_in[2];
    const float* out_w    = (const float*)d_in[3];
    const float* out_b    = (const float*)d_in[4];
    const float* omega    = (const float*)d_in[5];
    const float* poly_w   = (const float*)d_in[6];
    const float* qnodes   = (const float*)d_in[7];
    const float* qweights = (const float*)d_in[8];
    float* out = (float*)d_out;

    float* qkv_ptr = 0;
    cudaGetSymbolAddress((void**)&qkv_ptr, g_qkv);

    gemm_bias_k<<<dim3(3*Ec/128, (Bc*Tc)/128), 256>>>(x, qkv_w, qkv_b, qkv_ptr, 3*Ec, Ec);
    split_norm_k<<<Bc*Tc*Hc, 32>>>();
    features_k<<<dim3(BHc*NCc, 2), 256>>>(omega, poly_w, qnodes, qweights);
    passA_k<<<dim3(BHc*NCc, 2), 256>>>();
    prefix_kv_k<<<(BHc*PMc*Dc)/256, 256>>>();
    prefix_ks_k<<<(BHc*PMc)/256, 256>>>();
    cudaFuncSetAttribute(chunk_scores_k, cudaFuncAttributeMaxDynamicSharedMemorySize, 98816);
    chunk_scores_k<<<BHc*NCc, 256, 98816>>>();
    chunk_hist_k<<<BHc*NCc, 128>>>();
    gemm_out_k<<<dim3(Ec/128, (Bc*Tc)/128), 256>>>(out_w, out_b, out);
}

// round 4
// speedup vs baseline: 1.6366x; 1.6366x over previous
#include <cuda_runtime.h>
#include <cuda_bf16.h>
#include <math.h>

#define Bc 2
#define Tc 4096
#define Ec 1024
#define Hc 16
#define Dc 64
#define Pc 64
#define PMc 512
#define CHc 128
#define NCc 32
#define BHc 32

typedef unsigned long long u64;
typedef unsigned int u32;

// ---------------- scratch (device globals; no allocations allowed) ----------
__device__ float g_qkv[(size_t)Bc*Tc*3*Ec];
__device__ float g_qn [(size_t)BHc*Tc*Dc];
__device__ float g_kn [(size_t)BHc*Tc*Dc];
__device__ float g_v  [(size_t)BHc*Tc*Dc];
__device__ float g_qf [(size_t)BHc*NCc*PMc*CHc];     // (b,h,c, f, i)
__device__ float g_kf [(size_t)BHc*NCc*PMc*CHc];
__device__ float g_ckv[(size_t)BHc*NCc*PMc*Dc];      // (b,h,c, f, d)
__device__ float g_ks [(size_t)BHc*NCc*PMc];
__device__ float g_o  [(size_t)BHc*Tc*Dc];
__device__ float g_nrm[(size_t)BHc*Tc];
// bf16 split operands for tensor-core GEMMs
__device__ __align__(16) __nv_bfloat16 g_ah[(size_t)Bc*Tc*Ec];
__device__ __align__(16) __nv_bfloat16 g_al[(size_t)Bc*Tc*Ec];
__device__ __align__(16) __nv_bfloat16 g_wh[(size_t)3*Ec*Ec];
__device__ __align__(16) __nv_bfloat16 g_wl[(size_t)3*Ec*Ec];

// ================= helpers ===================================================
__device__ __forceinline__ u32 smem_u32(const void* p) {
    u32 a; asm("{ .reg .u64 t; cvta.to.shared.u64 t, %1; cvt.u32.u64 %0, t; }"
               : "=r"(a) : "l"(p));
    return a;
}
#define CP_ASYNC16(dst, src) \
    asm volatile("cp.async.cg.shared.global [%0], [%1], 16;\n" :: "r"(dst), "l"(src))
#define CP_COMMIT() asm volatile("cp.async.commit_group;\n" ::: "memory")
#define CP_WAIT1()  asm volatile("cp.async.wait_group 1;\n" ::: "memory")
#define CP_WAIT0()  asm volatile("cp.async.wait_group 0;\n" ::: "memory")

__device__ __forceinline__ void ldsm4(u32 &r0, u32 &r1, u32 &r2, u32 &r3, u32 a) {
    asm volatile("ldmatrix.sync.aligned.m8n8.x4.shared.b16 {%0,%1,%2,%3}, [%4];\n"
                 : "=r"(r0), "=r"(r1), "=r"(r2), "=r"(r3) : "r"(a));
}
__device__ __forceinline__ void mma16816(float* c, const u32* a, u32 b0, u32 b1) {
    asm volatile(
        "mma.sync.aligned.m16n8k16.row.col.f32.bf16.bf16.f32 "
        "{%0,%1,%2,%3},{%4,%5,%6,%7},{%8,%9},{%0,%1,%2,%3};\n"
        : "+f"(c[0]), "+f"(c[1]), "+f"(c[2]), "+f"(c[3])
        : "r"(a[0]), "r"(a[1]), "r"(a[2]), "r"(a[3]), "r"(b0), "r"(b1));
}

// ================= fp32 -> bf16 hi/lo split ==================================
__global__ void split_bf16_k(const float* __restrict__ s,
                             __nv_bfloat16* __restrict__ h,
                             __nv_bfloat16* __restrict__ l)
{
    size_t i = ((size_t)blockIdx.x*256 + threadIdx.x)*4;
    float4 v = *(const float4*)(s + i);
    __nv_bfloat16 h0=__float2bfloat16(v.x), h1=__float2bfloat16(v.y);
    __nv_bfloat16 h2=__float2bfloat16(v.z), h3=__float2bfloat16(v.w);
    __nv_bfloat162 ha = {h0,h1}, hb = {h2,h3};
    __nv_bfloat162 la = {__float2bfloat16(v.x-__bfloat162float(h0)),
                         __float2bfloat16(v.y-__bfloat162float(h1))};
    __nv_bfloat162 lb = {__float2bfloat16(v.z-__bfloat162float(h2)),
                         __float2bfloat16(v.w-__bfloat162float(h3))};
    *(__nv_bfloat162*)(h+i) = ha; *(__nv_bfloat162*)(h+i+2) = hb;
    *(__nv_bfloat162*)(l+i) = la; *(__nv_bfloat162*)(l+i+2) = lb;
}

// ------ reshape g_o (B,H,T,D) -> rows (b*T+t, h*64+d), bf16 hi/lo ------------
__global__ void o2rows_k()
{
    size_t gidx = ((size_t)blockIdx.x*256 + threadIdx.x)*2;
    float2 v = *(const float2*)(g_o + gidx);
    int d = (int)(gidx & 63), t = (int)((gidx >> 6) & 4095);
    int h = (int)((gidx >> 18) & 15), b = (int)(gidx >> 22);
    size_t dst = ((size_t)(b*Tc + t))*Ec + h*64 + d;
    __nv_bfloat16 h0=__float2bfloat16(v.x), h1=__float2bfloat16(v.y);
    *(__nv_bfloat162*)(g_ah+dst) = {h0,h1};
    *(__nv_bfloat162*)(g_al+dst) = {__float2bfloat16(v.x-__bfloat162float(h0)),
                                    __float2bfloat16(v.y-__bfloat162float(h1))};
}

// ================= HMMA GEMM: C[M,N] = A @ W^T + bias (bf16x3 split) ========
// CTA tile 128x128, 8 warps (warp tile 32m x 64n), K=1024 in 32 chunks of 32.
// smem per stage: Ah,Al,Bh,Bl each 128 rows x 40 bf16 (pad) = 10240 B.
#define S_STRIDE 40
#define S_ARR 10240
#define S_STAGE 40960

__global__ __launch_bounds__(256, 1)
void gemm_mma_k(const __nv_bfloat16* __restrict__ Abase_h,
                const __nv_bfloat16* __restrict__ Abase_l,
                const __nv_bfloat16* __restrict__ Wbase_h,
                const __nv_bfloat16* __restrict__ Wbase_l,
                const float* __restrict__ bias, float* __restrict__ C, int N)
{
    extern __shared__ char smem[];
    u32 sb = smem_u32(smem);
    const int K = 1024;
    int tid = threadIdx.x;
    int lane = tid & 31, warp = tid >> 5;
    int wm = warp >> 1, wn = warp & 1;           // 4 x 2 warp grid
    int bm = blockIdx.y * 128, bn = blockIdx.x * 128;

    const __nv_bfloat16* Ah = Abase_h + (size_t)bm * K;
    const __nv_bfloat16* Al = Abase_l + (size_t)bm * K;
    const __nv_bfloat16* Wh = Wbase_h + (size_t)bn * K;
    const __nv_bfloat16* Wl = Wbase_l + (size_t)bn * K;

    // gmem->smem task: idx in [0,512) per array; row=idx>>2, seg=idx&3
    int r0 = (tid*2) >> 2, s0 = (tid*2) & 3;
    int r1 = (tid*2+1) >> 2, s1 = (tid*2+1) & 3;

    // ldmatrix lane address offsets
    int lr = lane & 7;
    int a_row = (lr + (((lane >> 3) & 1) << 3));         // + m-tile base
    int a_col = ((lane >> 4) & 1) << 3;                  // k offset within k16
    int b_row = (lr + (((lane >> 4) & 1) << 3));         // + n-tile base
    int b_col = ((lane >> 3) & 1) << 3;

    float acc[2][8][4];
    #pragma unroll
    for (int i = 0; i < 2; i++)
        #pragma unroll
        for (int j = 0; j < 8; j++)
            #pragma unroll
            for (int q = 0; q < 4; q++) acc[i][j][q] = 0.f;

    auto load_chunk = [&](int ch, int stage) {
        int k0 = ch * 32;
        u32 st = sb + stage * S_STAGE;
        u32 d0 = st + r0*80 + s0*16;
        u32 d1 = st + r1*80 + s1*16;
        const __nv_bfloat16* ga0 = Ah + (size_t)r0*K + k0 + s0*8;
        const __nv_bfloat16* ga1 = Ah + (size_t)r1*K + k0 + s1*8;
        CP_ASYNC16(d0, ga0); CP_ASYNC16(d1, ga1);
        CP_ASYNC16(d0 + S_ARR, Al + (size_t)r0*K + k0 + s0*8);
        CP_ASYNC16(d1 + S_ARR, Al + (size_t)r1*K + k0 + s1*8);
        CP_ASYNC16(d0 + 2*S_ARR, Wh + (size_t)r0*K + k0 + s0*8);
        CP_ASYNC16(d1 + 2*S_ARR, Wh + (size_t)r1*K + k0 + s1*8);
        CP_ASYNC16(d0 + 3*S_ARR, Wl + (size_t)r0*K + k0 + s0*8);
        CP_ASYNC16(d1 + 3*S_ARR, Wl + (size_t)r1*K + k0 + s1*8);
        CP_COMMIT();
    };

    load_chunk(0, 0);

    for (int ch = 0; ch < 32; ch++) {
        int stage = ch & 1;
        if (ch + 1 < 32) {
            load_chunk(ch + 1, stage ^ 1);
            CP_WAIT1();
        } else {
            CP_WAIT0();
        }
        __syncthreads();

        u32 st = sb + stage * S_STAGE;
        #pragma unroll
        for (int ks = 0; ks < 2; ks++) {
            u32 afh[2][4], afl[2][4], bfh[4][4], bfl[4][4];
            #pragma unroll
            for (int mi = 0; mi < 2; mi++) {
                u32 addr = st + ((wm*32 + mi*16 + a_row)*S_STRIDE + ks*16 + a_col)*2;
                ldsm4(afh[mi][0], afh[mi][1], afh[mi][2], afh[mi][3], addr);
                ldsm4(afl[mi][0], afl[mi][1], afl[mi][2], afl[mi][3], addr + S_ARR);
            }
            #pragma unroll
            for (int nj = 0; nj < 4; nj++) {
                u32 addr = st + 2*S_ARR +
                           ((wn*64 + nj*16 + b_row)*S_STRIDE + ks*16 + b_col)*2;
                ldsm4(bfh[nj][0], bfh[nj][1], bfh[nj][2], bfh[nj][3], addr);
                ldsm4(bfl[nj][0], bfl[nj][1], bfl[nj][2], bfl[nj][3], addr + S_ARR);
            }
            #pragma unroll
            for (int mi = 0; mi < 2; mi++) {
                #pragma unroll
                for (int ni = 0; ni < 8; ni++) {
                    int nj = ni >> 1, off = (ni & 1) << 1;
                    mma16816(acc[mi][ni], afh[mi], bfh[nj][off], bfh[nj][off+1]);
                    mma16816(acc[mi][ni], afh[mi], bfl[nj][off], bfl[nj][off+1]);
                    mma16816(acc[mi][ni], afl[mi], bfh[nj][off], bfh[nj][off+1]);
                }
            }
        }
        __syncthreads();
    }

    // epilogue
    #pragma unroll
    for (int mi = 0; mi < 2; mi++) {
        #pragma unroll
        for (int ni = 0; ni < 8; ni++) {
            int m = bm + wm*32 + mi*16 + (lane >> 2);
            int n = bn + wn*64 + ni*8 + (lane & 3)*2;
            float2 o0, o1;
            o0.x = acc[mi][ni][0] + bias[n];
            o0.y = acc[mi][ni][1] + bias[n+1];
            o1.x = acc[mi][ni][2] + bias[n];
            o1.y = acc[mi][ni][3] + bias[n+1];
            *(float2*)(C + (size_t)m*N + n)       = o0;
            *(float2*)(C + (size_t)(m+8)*N + n)   = o1;
        }
    }
}

// ---------------- split qkv into heads, l2-normalize q,k --------------------
__global__ void split_norm_k()
{
    int gid = blockIdx.x;
    int h = gid & 15;
    int bt = gid >> 4;
    int lane = threadIdx.x;
    const float* row = g_qkv + (size_t)bt * (3*Ec);
    int col = h*64 + lane;
    float q0 = row[col],        q1 = row[col+32];
    float k0 = row[Ec+col],     k1 = row[Ec+col+32];
    float v0 = row[2*Ec+col],   v1 = row[2*Ec+col+32];
    float sq = q0*q0 + q1*q1;
    float sk = k0*k0 + k1*k1;
    #pragma unroll
    for (int off = 16; off > 0; off >>= 1) {
        sq += __shfl_xor_sync(0xffffffffu, sq, off);
        sk += __shfl_xor_sync(0xffffffffu, sk, off);
    }
    float rq = 1.f / fmaxf(sqrtf(sq), 1e-12f);
    float rk = 1.f / fmaxf(sqrtf(sk), 1e-12f);
    int b = bt >> 12, t = bt & 4095;
    size_t o = ((size_t)(b*Hc + h)*Tc + t)*Dc + lane;
    g_qn[o] = q0*rq; g_qn[o+32] = q1*rq;
    g_kn[o] = k0*rk; g_kn[o+32] = k1*rk;
    g_v[o]  = v0;    g_v[o+32]  = v1;
}

// ---------------- feature map: (poly x prf) per chunk, token-minor layout ---
__global__ __launch_bounds__(256) void features_k(
    const float* __restrict__ omega, const float* __restrict__ poly_w,
    const float* __restrict__ qnodes, const float* __restrict__ qweights)
{
    __shared__ float xs[64*129];
    __shared__ float om[64*8];
    __shared__ float prf[128*8];
    int bhc = blockIdx.x;
    int isK = blockIdx.y;
    int bh = bhc >> 5, c = bhc & 31;
    int h = bh & 15;
    const float* src = (isK ? g_kn : g_qn) + ((size_t)bh*Tc + c*CHc)*Dc;
    float* dst = (isK ? g_kf : g_qf) + (size_t)bhc*PMc*CHc;
    int tid = threadIdx.x;
    #pragma unroll
    for (int l = 0; l < 32; l++) {
        int idx = tid + l*256;
        int i = idx >> 6, d = idx & 63;
        xs[d*129 + i] = src[(size_t)i*64 + d];
    }
    om[tid]       = omega[h*512 + tid];
    om[tid + 256] = omega[h*512 + tid + 256];
    __syncthreads();
    float s0 = qnodes[0];
    float sq2s = sqrtf(fmaxf(2.f*s0, 0.f));
    float wq = sqrtf(fmaxf(qweights[0], 0.f));
    float prescale = 0.3535533905932738f * wq;
    #pragma unroll
    for (int l = 0; l < 4; l++) {
        int pair = tid + l*256;
        int i = pair >> 3, m = pair & 7;
        float a = 0.f;
        #pragma unroll
        for (int d = 0; d < 64; d++) a += xs[d*129 + i] * om[d*8 + m];
        float e = fminf(fmaxf(a * sq2s - s0, -20.f), 20.f);
        prf[i*8 + m] = expf(e) * prescale;
    }
    __syncthreads();
    int ti = (tid >> 4) << 3, tp = (tid & 15) << 2;
    float acc[8][4] = {};
    const float* pwp = poly_w + h*4096;
    for (int d = 0; d < 64; d++) {
        float a[8];
        #pragma unroll
        for (int x = 0; x < 8; x++) a[x] = xs[d*129 + ti + x];
        float4 bb = *(const float4*)(pwp + d*64 + tp);
        #pragma unroll
        for (int i2 = 0; i2 < 8; i2++) {
            acc[i2][0] += a[i2]*bb.x; acc[i2][1] += a[i2]*bb.y;
            acc[i2][2] += a[i2]*bb.z; acc[i2][3] += a[i2]*bb.w;
        }
    }
    #pragma unroll
    for (int i2 = 0; i2 < 8; i2++)
        #pragma unroll
        for (int j = 0; j < 4; j++)
            acc[i2][j] = acc[i2][j]*acc[i2][j]*0.125f;
    #pragma unroll
    for (int j = 0; j < 4; j++) {
        int p = tp + j;
        #pragma unroll
        for (int m = 0; m < 8; m++) {
            float vals[8];
            #pragma unroll
            for (int i2 = 0; i2 < 8; i2++) vals[i2] = acc[i2][j] * prf[(ti+i2)*8 + m];
            float* outp = dst + (size_t)(p*8 + m)*CHc + ti;
            *(float4*)outp     = *(float4*)vals;
            *(float4*)(outp+4) = *(float4*)(vals+4);
        }
    }
}

// ---------------- pass A: per-chunk  kv[f][d] = sum_i kf[f][i] v[i][d] ------
__global__ __launch_bounds__(256) void passA_k()
{
    __shared__ float kfs[64*33];
    __shared__ float vs[32*64];
    int bhc = blockIdx.x;
    int f0 = blockIdx.y << 6;
    int bh = bhc >> 5, c = bhc & 31;
    const float* kfbase = g_kf + (size_t)bhc*PMc*CHc + (size_t)f0*CHc;
    const float* vbase = g_v + ((size_t)bh*Tc + c*CHc)*Dc;
    int tid = threadIdx.x;
    int tf = (tid >> 4) << 2, td = (tid & 15) << 2;
    float acc[4][4] = {};
    float kssum = 0.f;
    for (int i0 = 0; i0 < 128; i0 += 32) {
        #pragma unroll
        for (int l = 0; l < 8; l++) {
            int idx = tid + l*256;
            int f = idx >> 5, ii = idx & 31;
            kfs[f*33 + ii] = kfbase[(size_t)f*CHc + i0 + ii];
        }
        #pragma unroll
        for (int l = 0; l < 2; l++) {
            int idx = tid + l*256;
            int ii = idx >> 4, d = (idx & 15) << 2;
            *(float4*)&vs[ii*64 + d] = *(const float4*)(vbase + (size_t)(i0+ii)*64 + d);
        }
        __syncthreads();
        if (tid < 64) {
            float s = 0.f;
            #pragma unroll
            for (int ii = 0; ii < 32; ii++) s += kfs[tid*33 + ii];
            kssum += s;
        }
        #pragma unroll
        for (int kk = 0; kk < 32; kk++) {
            float a[4];
            #pragma unroll
            for (int x = 0; x < 4; x++) a[x] = kfs[(tf+x)*33 + kk];
            float4 bv = *(const float4*)&vs[kk*64 + td];
            #pragma unroll
            for (int i = 0; i < 4; i++) {
                acc[i][0]+=a[i]*bv.x; acc[i][1]+=a[i]*bv.y;
                acc[i][2]+=a[i]*bv.z; acc[i][3]+=a[i]*bv.w;
            }
        }
        __syncthreads();
    }
    float* outp = g_ckv + (size_t)bhc*PMc*Dc + (size_t)f0*Dc;
    #pragma unroll
    for (int i = 0; i < 4; i++) {
        float4 o = make_float4(acc[i][0],acc[i][1],acc[i][2],acc[i][3]);
        *(float4*)(outp + (size_t)(tf+i)*64 + td) = o;
    }
    if (tid < 64) g_ks[(size_t)bhc*PMc + f0 + tid] = kssum;
}

// ---------------- exclusive prefix over chunks -------------------------------
__global__ void prefix_kv_k()
{
    size_t idx = (size_t)blockIdx.x*256 + threadIdx.x;
    size_t bh = idx / (PMc*Dc);
    size_t rem = idx % (PMc*Dc);
    float acc = 0.f;
    #pragma unroll
    for (int c = 0; c < NCc; c++) {
        size_t p = (bh*NCc + c)*(size_t)(PMc*Dc) + rem;
        float v = g_ckv[p];
        g_ckv[p] = acc;
        acc += v;
    }
}
__global__ void prefix_ks_k()
{
    size_t idx = (size_t)blockIdx.x*256 + threadIdx.x;
    size_t bh = idx / PMc;
    size_t rem = idx % PMc;
    float acc = 0.f;
    #pragma unroll
    for (int c = 0; c < NCc; c++) {
        size_t p = (bh*NCc + c)*(size_t)PMc + rem;
        float v = g_ks[p];
        g_ks[p] = acc;
        acc += v;
    }
}

// ---------------- pass C1: masked scores, intra context, row sums -----------
__global__ __launch_bounds__(256) void chunk_scores_k()
{
    extern __shared__ float sm[];
    float* S = sm;                       // [128][129]
    float* tiles = sm + 128*129;
    float* qs  = tiles;                  // [16][128]
    float* ks2 = tiles + 16*128;         // [16][128]
    int bhc = blockIdx.x;
    int bh = bhc >> 5, c = bhc & 31;
    const float* qb = g_qf + (size_t)bhc*PMc*CHc;
    const float* kb = g_kf + (size_t)bhc*PMc*CHc;
    int tid = threadIdx.x;
    int tm = (tid >> 4) << 3, tn = (tid & 15) << 3;
    float acc[8][8] = {};
    for (int k0 = 0; k0 < PMc; k0 += 16) {
        #pragma unroll
        for (int l = 0; l < 2; l++) {
            int idx = tid*2 + l;
            int r = idx >> 5, cc = (idx & 31) << 2;
            *(float4*)&qs[r*128 + cc]  = *(const float4*)(qb + (size_t)(k0+r)*CHc + cc);
            *(float4*)&ks2[r*128 + cc] = *(const float4*)(kb + (size_t)(k0+r)*CHc + cc);
        }
        __syncthreads();
        #pragma unroll
        for (int kk = 0; kk < 16; kk++) {
            float a[8], b[8];
            *(float4*)(a)   = *(const float4*)&qs[kk*128 + tm];
            *(float4*)(a+4) = *(const float4*)&qs[kk*128 + tm + 4];
            *(float4*)(b)   = *(const float4*)&ks2[kk*128 + tn];
            *(float4*)(b+4) = *(const float4*)&ks2[kk*128 + tn + 4];
            #pragma unroll
            for (int i = 0; i < 8; i++)
                #pragma unroll
                for (int j = 0; j < 8; j++)
                    acc[i][j] += a[i]*b[j];
        }
        __syncthreads();
    }
    #pragma unroll
    for (int i = 0; i < 8; i++) {
        int ri = tm + i;
        float s = 0.f;
        #pragma unroll
        for (int j = 0; j < 8; j++) {
            int cj = tn + j;
            float v = (cj <= ri) ? acc[i][j] : 0.f;
            S[ri*129 + cj] = v;
            s += v;
        }
        #pragma unroll
        for (int off = 8; off > 0; off >>= 1) s += __shfl_xor_sync(0xffffffffu, s, off);
        if ((tid & 15) == 0) g_nrm[(size_t)bh*Tc + c*CHc + ri] = s;
    }
    __syncthreads();
    float* vsm = tiles;                  // [128][64]
    #pragma unroll
    for (int l = 0; l < 8; l++) {
        int idx = tid + l*256;
        int ii = idx >> 4, d = (idx & 15) << 2;
        *(float4*)&vsm[ii*64 + d] =
            *(const float4*)(g_v + ((size_t)bh*Tc + c*CHc + ii)*Dc + d);
    }
    __syncthreads();
    int ti = tm;
    int td = (tid & 15) << 2;
    float o[8][4] = {};
    for (int k = 0; k < 128; k++) {
        float4 bv = *(const float4*)&vsm[k*64 + td];
        #pragma unroll
        for (int i = 0; i < 8; i++) {
            float a = S[(ti+i)*129 + k];
            o[i][0]+=a*bv.x; o[i][1]+=a*bv.y; o[i][2]+=a*bv.z; o[i][3]+=a*bv.w;
        }
    }
    #pragma unroll
    for (int i = 0; i < 8; i++) {
        float4 ov = make_float4(o[i][0],o[i][1],o[i][2],o[i][3]);
        *(float4*)(g_o + ((size_t)bh*Tc + c*CHc + ti + i)*Dc + td) = ov;
    }
}

// ---------------- pass C2: history context + norm + finalize ----------------
__global__ __launch_bounds__(256) void chunk_hist_k()
{
    __shared__ float qs[16*128];
    __shared__ float kvs[16*64];
    __shared__ float kst[16];
    int bhc = blockIdx.x;
    int bh = bhc >> 5, c = bhc & 31;
    const float* qb  = g_qf  + (size_t)bhc*PMc*CHc;
    const float* kvb = g_ckv + (size_t)bhc*PMc*Dc;
    const float* ksb = g_ks  + (size_t)bhc*PMc;
    int tid = threadIdx.x;
    int ti = (tid >> 4) << 3, td = (tid & 15) << 2;
    float acc[8][4] = {};
    float an[8] = {};
    for (int k0 = 0; k0 < PMc; k0 += 16) {
        #pragma unroll
        for (int l = 0; l < 2; l++) {
            int idx = tid*2 + l;
            int r = idx >> 5, cc = (idx & 31) << 2;
            *(float4*)&qs[r*128 + cc] = *(const float4*)(qb + (size_t)(k0+r)*CHc + cc);
        }
        {
            int r = tid >> 4, cc = (tid & 15) << 2;
            *(float4*)&kvs[r*64 + cc] = *(const float4*)(kvb + (size_t)(k0+r)*Dc + cc);
        }
        if (tid < 16) kst[tid] = ksb[k0 + tid];
        __syncthreads();
        #pragma unroll
        for (int kk = 0; kk < 16; kk++) {
            float a[8];
            *(float4*)(a)   = *(const float4*)&qs[kk*128 + ti];
            *(float4*)(a+4) = *(const float4*)&qs[kk*128 + ti + 4];
            float4 bv = *(const float4*)&kvs[kk*64 + td];
            float ksv = kst[kk];
            #pragma unroll
            for (int i = 0; i < 8; i++) {
                an[i] += a[i]*ksv;
                acc[i][0]+=a[i]*bv.x; acc[i][1]+=a[i]*bv.y;
                acc[i][2]+=a[i]*bv.z; acc[i][3]+=a[i]*bv.w;
            }
        }
        __syncthreads();
    }
    #pragma unroll
    for (int i = 0; i < 8; i++) {
        size_t tok = (size_t)bh*Tc + c*CHc + ti + i;
        float nrm = an[i] + g_nrm[tok] + 1e-6f;
        float inv = 1.f / nrm;
        float4* po = (float4*)(g_o + tok*Dc + td);
        float4 cur = *po;
        cur.x = (cur.x + acc[i][0]) * inv;
        cur.y = (cur.y + acc[i][1]) * inv;
        cur.z = (cur.z + acc[i][2]) * inv;
        cur.w = (cur.w + acc[i][3]) * inv;
        *po = cur;
    }
}

// ---------------- host launcher ---------------------------------------------
extern "C" void kernel_launch(void* const* d_in, const int* in_sizes, int n_in,
                              void* d_out, int out_size)
{
    const float* x        = (const float*)d_in[0];
    const float* qkv_w    = (const float*)d_in[1];
    const float* qkv_b    = (const float*)d_in[2];
    const float* out_w    = (const float*)d_in[3];
    const float* out_b    = (const float*)d_in[4];
    const float* omega    = (const float*)d_in[5];
    const float* poly_w   = (const float*)d_in[6];
    const float* qnodes   = (const float*)d_in[7];
    const float* qweights = (const float*)d_in[8];
    float* out = (float*)d_out;

    float* qkv_ptr = 0;
    cudaGetSymbolAddress((void**)&qkv_ptr, g_qkv);
    __nv_bfloat16 *ah, *al, *wh, *wl;
    cudaGetSymbolAddress((void**)&ah, g_ah);
    cudaGetSymbolAddress((void**)&al, g_al);
    cudaGetSymbolAddress((void**)&wh, g_wh);
    cudaGetSymbolAddress((void**)&wl, g_wl);

    cudaFuncSetAttribute(gemm_mma_k, cudaFuncAttributeMaxDynamicSharedMemorySize,
                         2*S_STAGE);
    cudaFuncSetAttribute(chunk_scores_k, cudaFuncAttributeMaxDynamicSharedMemorySize, 98816);

    // 1) split operands to bf16 hi/lo
    split_bf16_k<<<(Bc*Tc*Ec)/1024, 256>>>(x, ah, al);
    split_bf16_k<<<(3*Ec*Ec)/1024, 256>>>(qkv_w, wh, wl);
    // 2) QKV GEMM on tensor cores (HMMA): (8192 x 3072), K=1024
    gemm_mma_k<<<dim3(3*Ec/128, (Bc*Tc)/128), 256, 2*S_STAGE>>>(
        ah, al, wh, wl, qkv_b, qkv_ptr, 3*Ec);
    // 3) head split + l2norm
    split_norm_k<<<Bc*Tc*Hc, 32>>>();
    // 4) feature maps
    features_k<<<dim3(BHc*NCc, 2), 256>>>(omega, poly_w, qnodes, qweights);
    // 5) per-chunk kv + ks
    passA_k<<<dim3(BHc*NCc, PMc/64), 256>>>();
    // 6) exclusive prefix over chunks
    prefix_kv_k<<<(BHc*PMc*Dc)/256, 256>>>();
    prefix_ks_k<<<(BHc*PMc)/256, 256>>>();
    // 7) intra-chunk scores
    chunk_scores_k<<<BHc*NCc, 256, 98816>>>();
    // 8) history + normalize
    chunk_hist_k<<<BHc*NCc, 256>>>();
    // 9) reshape attention output + split; out_w split
    o2rows_k<<<(BHc*Tc*Dc)/512, 256>>>();
    split_bf16_k<<<(Ec*Ec)/1024, 256>>>(out_w, wh, wl);
    // 10) output GEMM on tensor cores (HMMA): (8192 x 1024), K=1024
    gemm_mma_k<<<dim3(Ec/128, (Bc*Tc)/128), 256, 2*S_STAGE>>>(
        ah, al, wh, wl, out_b, out, Ec);
}

// round 5
// speedup vs baseline: 2.1668x; 1.3240x over previous
#include <cuda_runtime.h>
#include <cuda_bf16.h>
#include <math.h>

#define Bc 2
#define Tc 4096
#define Ec 1024
#define Hc 16
#define Dc 64
#define Pc 64
#define PMc 512
#define CHc 128
#define NCc 32
#define BHc 32

typedef unsigned long long u64;
typedef unsigned int u32;

// ---------------- scratch (device globals; no allocations allowed) ----------
__device__ float g_qkv[(size_t)Bc*Tc*3*Ec];
__device__ float g_qn [(size_t)BHc*Tc*Dc];
__device__ float g_kn [(size_t)BHc*Tc*Dc];
__device__ float g_v  [(size_t)BHc*Tc*Dc];
__device__ float g_ckv[(size_t)BHc*NCc*PMc*Dc];      // (bhc, f, d) fp32
__device__ float g_ks [(size_t)BHc*NCc*PMc];
__device__ float g_o  [(size_t)BHc*Tc*Dc];
__device__ float g_nrm[(size_t)BHc*Tc];
// bf16 hi/lo features, [bhc][token 128][feature 512]
__device__ __align__(16) __nv_bfloat16 g_qfh[(size_t)BHc*NCc*CHc*PMc];
__device__ __align__(16) __nv_bfloat16 g_qfl[(size_t)BHc*NCc*CHc*PMc];
__device__ __align__(16) __nv_bfloat16 g_kfh[(size_t)BHc*NCc*CHc*PMc];
__device__ __align__(16) __nv_bfloat16 g_kfl[(size_t)BHc*NCc*CHc*PMc];
// bf16 hi/lo exclusive kv state, [bhc][f][d]
__device__ __align__(16) __nv_bfloat16 g_ckvh[(size_t)BHc*NCc*PMc*Dc];
__device__ __align__(16) __nv_bfloat16 g_ckvl[(size_t)BHc*NCc*PMc*Dc];
// bf16 split operands for dense GEMMs
__device__ __align__(16) __nv_bfloat16 g_ah[(size_t)Bc*Tc*Ec];
__device__ __align__(16) __nv_bfloat16 g_al[(size_t)Bc*Tc*Ec];
__device__ __align__(16) __nv_bfloat16 g_wh[(size_t)3*Ec*Ec];
__device__ __align__(16) __nv_bfloat16 g_wl[(size_t)3*Ec*Ec];

// ================= helpers ===================================================
__device__ __forceinline__ u32 smem_u32(const void* p) {
    u32 a; asm("{ .reg .u64 t; cvta.to.shared.u64 t, %1; cvt.u32.u64 %0, t; }"
               : "=r"(a) : "l"(p));
    return a;
}
#define CP_ASYNC16(dst, src) \
    asm volatile("cp.async.cg.shared.global [%0], [%1], 16;\n" :: "r"(dst), "l"(src))
#define CP_COMMIT() asm volatile("cp.async.commit_group;\n" ::: "memory")
#define CP_WAIT1()  asm volatile("cp.async.wait_group 1;\n" ::: "memory")
#define CP_WAIT0()  asm volatile("cp.async.wait_group 0;\n" ::: "memory")

__device__ __forceinline__ void ldsm4(u32 &r0, u32 &r1, u32 &r2, u32 &r3, u32 a) {
    asm volatile("ldmatrix.sync.aligned.m8n8.x4.shared.b16 {%0,%1,%2,%3}, [%4];\n"
                 : "=r"(r0), "=r"(r1), "=r"(r2), "=r"(r3) : "r"(a));
}
__device__ __forceinline__ void ldsm4t(u32 &r0, u32 &r1, u32 &r2, u32 &r3, u32 a) {
    asm volatile("ldmatrix.sync.aligned.m8n8.x4.trans.shared.b16 {%0,%1,%2,%3}, [%4];\n"
                 : "=r"(r0), "=r"(r1), "=r"(r2), "=r"(r3) : "r"(a));
}
__device__ __forceinline__ void mma16816(float* c, const u32* a, u32 b0, u32 b1) {
    asm volatile(
        "mma.sync.aligned.m16n8k16.row.col.f32.bf16.bf16.f32 "
        "{%0,%1,%2,%3},{%4,%5,%6,%7},{%8,%9},{%0,%1,%2,%3};\n"
        : "+f"(c[0]), "+f"(c[1]), "+f"(c[2]), "+f"(c[3])
        : "r"(a[0]), "r"(a[1]), "r"(a[2]), "r"(a[3]), "r"(b0), "r"(b1));
}

// ================= fp32 -> bf16 hi/lo split ==================================
__global__ void split_bf16_k(const float* __restrict__ s,
                             __nv_bfloat16* __restrict__ h,
                             __nv_bfloat16* __restrict__ l)
{
    size_t i = ((size_t)blockIdx.x*256 + threadIdx.x)*4;
    float4 v = *(const float4*)(s + i);
    __nv_bfloat16 h0=__float2bfloat16(v.x), h1=__float2bfloat16(v.y);
    __nv_bfloat16 h2=__float2bfloat16(v.z), h3=__float2bfloat16(v.w);
    __nv_bfloat162 ha = {h0,h1}, hb = {h2,h3};
    __nv_bfloat162 la = {__float2bfloat16(v.x-__bfloat162float(h0)),
                         __float2bfloat16(v.y-__bfloat162float(h1))};
    __nv_bfloat162 lb = {__float2bfloat16(v.z-__bfloat162float(h2)),
                         __float2bfloat16(v.w-__bfloat162float(h3))};
    *(__nv_bfloat162*)(h+i) = ha; *(__nv_bfloat162*)(h+i+2) = hb;
    *(__nv_bfloat162*)(l+i) = la; *(__nv_bfloat162*)(l+i+2) = lb;
}

// ------ reshape g_o (B,H,T,D) -> rows (b*T+t, h*64+d), bf16 hi/lo ------------
__global__ void o2rows_k()
{
    size_t gidx = ((size_t)blockIdx.x*256 + threadIdx.x)*2;
    float2 v = *(const float2*)(g_o + gidx);
    int d = (int)(gidx & 63), t = (int)((gidx >> 6) & 4095);
    int h = (int)((gidx >> 18) & 15), b = (int)(gidx >> 22);
    size_t dst = ((size_t)(b*Tc + t))*Ec + h*64 + d;
    __nv_bfloat16 h0=__float2bfloat16(v.x), h1=__float2bfloat16(v.y);
    *(__nv_bfloat162*)(g_ah+dst) = {h0,h1};
    *(__nv_bfloat162*)(g_al+dst) = {__float2bfloat16(v.x-__bfloat162float(h0)),
                                    __float2bfloat16(v.y-__bfloat162float(h1))};
}

// ------ g_ckv fp32 (exclusive states) -> bf16 hi/lo ---------------------------
__global__ void cvt_ckv_k()
{
    size_t i = ((size_t)blockIdx.x*256 + threadIdx.x)*4;
    float4 v = *(const float4*)(g_ckv + i);
    __nv_bfloat16 h0=__float2bfloat16(v.x), h1=__float2bfloat16(v.y);
    __nv_bfloat16 h2=__float2bfloat16(v.z), h3=__float2bfloat16(v.w);
    *(__nv_bfloat162*)(g_ckvh+i)   = {h0,h1};
    *(__nv_bfloat162*)(g_ckvh+i+2) = {h2,h3};
    *(__nv_bfloat162*)(g_ckvl+i)   = {__float2bfloat16(v.x-__bfloat162float(h0)),
                                      __float2bfloat16(v.y-__bfloat162float(h1))};
    *(__nv_bfloat162*)(g_ckvl+i+2) = {__float2bfloat16(v.z-__bfloat162float(h2)),
                                      __float2bfloat16(v.w-__bfloat162float(h3))};
}

// ================= HMMA GEMM: C[M,N] = A @ W^T + bias (bf16x3 split) ========
#define S_STRIDE 40
#define S_ARR 10240
#define S_STAGE 40960

__global__ __launch_bounds__(256, 1)
void gemm_mma_k(const __nv_bfloat16* __restrict__ Abase_h,
                const __nv_bfloat16* __restrict__ Abase_l,
                const __nv_bfloat16* __restrict__ Wbase_h,
                const __nv_bfloat16* __restrict__ Wbase_l,
                const float* __restrict__ bias, float* __restrict__ C, int N)
{
    extern __shared__ char smem[];
    u32 sb = smem_u32(smem);
    const int K = 1024;
    int tid = threadIdx.x;
    int lane = tid & 31, warp = tid >> 5;
    int wm = warp >> 1, wn = warp & 1;
    int bm = blockIdx.y * 128, bn = blockIdx.x * 128;

    const __nv_bfloat16* Ah = Abase_h + (size_t)bm * K;
    const __nv_bfloat16* Al = Abase_l + (size_t)bm * K;
    const __nv_bfloat16* Wh = Wbase_h + (size_t)bn * K;
    const __nv_bfloat16* Wl = Wbase_l + (size_t)bn * K;

    int r0 = (tid*2) >> 2, s0 = (tid*2) & 3;
    int r1 = (tid*2+1) >> 2, s1 = (tid*2+1) & 3;

    int lr = lane & 7;
    int a_row = lr + (((lane >> 3) & 1) << 3);
    int a_col = ((lane >> 4) & 1) << 3;
    int b_row = lr + (((lane >> 4) & 1) << 3);
    int b_col = ((lane >> 3) & 1) << 3;

    float acc[2][8][4];
    #pragma unroll
    for (int i = 0; i < 2; i++)
        #pragma unroll
        for (int j = 0; j < 8; j++)
            #pragma unroll
            for (int q = 0; q < 4; q++) acc[i][j][q] = 0.f;

    auto load_chunk = [&](int ch, int stage) {
        int k0 = ch * 32;
        u32 st = sb + stage * S_STAGE;
        u32 d0 = st + r0*80 + s0*16;
        u32 d1 = st + r1*80 + s1*16;
        CP_ASYNC16(d0, Ah + (size_t)r0*K + k0 + s0*8);
        CP_ASYNC16(d1, Ah + (size_t)r1*K + k0 + s1*8);
        CP_ASYNC16(d0 + S_ARR, Al + (size_t)r0*K + k0 + s0*8);
        CP_ASYNC16(d1 + S_ARR, Al + (size_t)r1*K + k0 + s1*8);
        CP_ASYNC16(d0 + 2*S_ARR, Wh + (size_t)r0*K + k0 + s0*8);
        CP_ASYNC16(d1 + 2*S_ARR, Wh + (size_t)r1*K + k0 + s1*8);
        CP_ASYNC16(d0 + 3*S_ARR, Wl + (size_t)r0*K + k0 + s0*8);
        CP_ASYNC16(d1 + 3*S_ARR, Wl + (size_t)r1*K + k0 + s1*8);
        CP_COMMIT();
    };

    load_chunk(0, 0);

    for (int ch = 0; ch < 32; ch++) {
        int stage = ch & 1;
        if (ch + 1 < 32) { load_chunk(ch + 1, stage ^ 1); CP_WAIT1(); }
        else             { CP_WAIT0(); }
        __syncthreads();

        u32 st = sb + stage * S_STAGE;
        #pragma unroll
        for (int ks = 0; ks < 2; ks++) {
            u32 afh[2][4], afl[2][4], bfh[4][4], bfl[4][4];
            #pragma unroll
            for (int mi = 0; mi < 2; mi++) {
                u32 addr = st + ((wm*32 + mi*16 + a_row)*S_STRIDE + ks*16 + a_col)*2;
                ldsm4(afh[mi][0], afh[mi][1], afh[mi][2], afh[mi][3], addr);
                ldsm4(afl[mi][0], afl[mi][1], afl[mi][2], afl[mi][3], addr + S_ARR);
            }
            #pragma unroll
            for (int nj = 0; nj < 4; nj++) {
                u32 addr = st + 2*S_ARR +
                           ((wn*64 + nj*16 + b_row)*S_STRIDE + ks*16 + b_col)*2;
                ldsm4(bfh[nj][0], bfh[nj][1], bfh[nj][2], bfh[nj][3], addr);
                ldsm4(bfl[nj][0], bfl[nj][1], bfl[nj][2], bfl[nj][3], addr + S_ARR);
            }
            #pragma unroll
            for (int mi = 0; mi < 2; mi++) {
                #pragma unroll
                for (int ni = 0; ni < 8; ni++) {
                    int nj = ni >> 1, off = (ni & 1) << 1;
                    mma16816(acc[mi][ni], afh[mi], bfh[nj][off], bfh[nj][off+1]);
                    mma16816(acc[mi][ni], afh[mi], bfl[nj][off], bfl[nj][off+1]);
                    mma16816(acc[mi][ni], afl[mi], bfh[nj][off], bfh[nj][off+1]);
                }
            }
        }
        __syncthreads();
    }

    #pragma unroll
    for (int mi = 0; mi < 2; mi++) {
        #pragma unroll
        for (int ni = 0; ni < 8; ni++) {
            int m = bm + wm*32 + mi*16 + (lane >> 2);
            int n = bn + wn*64 + ni*8 + (lane & 3)*2;
            float2 o0, o1;
            o0.x = acc[mi][ni][0] + bias[n];
            o0.y = acc[mi][ni][1] + bias[n+1];
            o1.x = acc[mi][ni][2] + bias[n];
            o1.y = acc[mi][ni][3] + bias[n+1];
            *(float2*)(C + (size_t)m*N + n)     = o0;
            *(float2*)(C + (size_t)(m+8)*N + n) = o1;
        }
    }
}

// ---------------- split qkv into heads, l2-normalize q,k --------------------
__global__ void split_norm_k()
{
    int gid = blockIdx.x;
    int h = gid & 15;
    int bt = gid >> 4;
    int lane = threadIdx.x;
    const float* row = g_qkv + (size_t)bt * (3*Ec);
    int col = h*64 + lane;
    float q0 = row[col],        q1 = row[col+32];
    float k0 = row[Ec+col],     k1 = row[Ec+col+32];
    float v0 = row[2*Ec+col],   v1 = row[2*Ec+col+32];
    float sq = q0*q0 + q1*q1;
    float sk = k0*k0 + k1*k1;
    #pragma unroll
    for (int off = 16; off > 0; off >>= 1) {
        sq += __shfl_xor_sync(0xffffffffu, sq, off);
        sk += __shfl_xor_sync(0xffffffffu, sk, off);
    }
    float rq = 1.f / fmaxf(sqrtf(sq), 1e-12f);
    float rk = 1.f / fmaxf(sqrtf(sk), 1e-12f);
    int b = bt >> 12, t = bt & 4095;
    size_t o = ((size_t)(b*Hc + h)*Tc + t)*Dc + lane;
    g_qn[o] = q0*rq; g_qn[o+32] = q1*rq;
    g_kn[o] = k0*rk; g_kn[o+32] = k1*rk;
    g_v[o]  = v0;    g_v[o+32]  = v1;
}

// ---------------- feature map -> bf16 hi/lo [token][feature] ----------------
__global__ __launch_bounds__(256) void features_k(
    const float* __restrict__ omega, const float* __restrict__ poly_w,
    const float* __restrict__ qnodes, const float* __restrict__ qweights)
{
    __shared__ float xs[64*129];
    __shared__ float om[64*8];
    __shared__ float prf[128*8];
    int bhc = blockIdx.x;
    int isK = blockIdx.y;
    int bh = bhc >> 5, c = bhc & 31;
    int h = bh & 15;
    const float* src = (isK ? g_kn : g_qn) + ((size_t)bh*Tc + c*CHc)*Dc;
    __nv_bfloat16* dh = (isK ? g_kfh : g_qfh) + (size_t)bhc*CHc*PMc;
    __nv_bfloat16* dl = (isK ? g_kfl : g_qfl) + (size_t)bhc*CHc*PMc;
    int tid = threadIdx.x;
    #pragma unroll
    for (int l = 0; l < 32; l++) {
        int idx = tid + l*256;
        int i = idx >> 6, d = idx & 63;
        xs[d*129 + i] = src[(size_t)i*64 + d];
    }
    om[tid]       = omega[h*512 + tid];
    om[tid + 256] = omega[h*512 + tid + 256];
    __syncthreads();
    float s0 = qnodes[0];
    float sq2s = sqrtf(fmaxf(2.f*s0, 0.f));
    float wq = sqrtf(fmaxf(qweights[0], 0.f));
    float prescale = 0.3535533905932738f * wq;
    #pragma unroll
    for (int l = 0; l < 4; l++) {
        int pair = tid + l*256;
        int i = pair >> 3, m = pair & 7;
        float a = 0.f;
        #pragma unroll
        for (int d = 0; d < 64; d++) a += xs[d*129 + i] * om[d*8 + m];
        float e = fminf(fmaxf(a * sq2s - s0, -20.f), 20.f);
        prf[i*8 + m] = expf(e) * prescale;
    }
    __syncthreads();
    int ti = (tid >> 4) << 3, tp = (tid & 15) << 2;
    float acc[8][4] = {};
    const float* pwp = poly_w + h*4096;
    for (int d = 0; d < 64; d++) {
        float a[8];
        #pragma unroll
        for (int x = 0; x < 8; x++) a[x] = xs[d*129 + ti + x];
        float4 bb = *(const float4*)(pwp + d*64 + tp);
        #pragma unroll
        for (int i2 = 0; i2 < 8; i2++) {
            acc[i2][0] += a[i2]*bb.x; acc[i2][1] += a[i2]*bb.y;
            acc[i2][2] += a[i2]*bb.z; acc[i2][3] += a[i2]*bb.w;
        }
    }
    #pragma unroll
    for (int i2 = 0; i2 < 8; i2++)
        #pragma unroll
        for (int j = 0; j < 4; j++)
            acc[i2][j] = acc[i2][j]*acc[i2][j]*0.125f;
    #pragma unroll
    for (int i2 = 0; i2 < 8; i2++) {
        int tok = ti + i2;
        __nv_bfloat16 hb[32], lb[32];
        #pragma unroll
        for (int j = 0; j < 4; j++)
            #pragma unroll
            for (int m = 0; m < 8; m++) {
                float v = acc[i2][j] * prf[tok*8 + m];
                __nv_bfloat16 hh = __float2bfloat16(v);
                hb[j*8+m] = hh;
                lb[j*8+m] = __float2bfloat16(v - __bfloat162float(hh));
            }
        __nv_bfloat16* ph = dh + (size_t)tok*PMc + tp*8;
        __nv_bfloat16* pl = dl + (size_t)tok*PMc + tp*8;
        #pragma unroll
        for (int s = 0; s < 4; s++) {
            *(uint4*)(ph + s*8) = *(uint4*)(hb + s*8);
            *(uint4*)(pl + s*8) = *(uint4*)(lb + s*8);
        }
    }
}

// ---------------- pass A (HMMA): kv[f][d] = sum_i kf[i][f] v[i][d] ----------
// block: (bhc, fb 0..3); smem: kf hi/lo [128 i][136], v hi/lo [128 i][72]
__global__ __launch_bounds__(256, 1) void passA_mma_k()
{
    extern __shared__ char sm[];
    u32 sb = smem_u32(sm);
    const u32 KFH = 0, KFL = 34816, VH = 69632, VL = 88064;
    int bhc = blockIdx.x, fb = blockIdx.y;
    int bh = bhc >> 5, c = bhc & 31;
    int tid = threadIdx.x, lane = tid & 31, warp = tid >> 5;
    int wm = warp >> 1, wn = warp & 1;

    const __nv_bfloat16* kh = g_kfh + (size_t)bhc*CHc*PMc + fb*128;
    const __nv_bfloat16* kl = g_kfl + (size_t)bhc*CHc*PMc + fb*128;
    // load kf tiles via cp.async
    #pragma unroll
    for (int l = 0; l < 8; l++) {
        int idx = tid + l*256;
        int row = idx >> 4, seg = idx & 15;
        u32 d = sb + KFH + row*272 + seg*16;
        CP_ASYNC16(d,              kh + (size_t)row*PMc + seg*8);
        CP_ASYNC16(d + (KFL-KFH),  kl + (size_t)row*PMc + seg*8);
    }
    CP_COMMIT();
    // load + convert v
    const float* vb = g_v + ((size_t)bh*Tc + c*CHc)*Dc;
    #pragma unroll
    for (int l = 0; l < 8; l++) {
        int idx = tid + l*256;
        int i = idx >> 4, dd = (idx & 15)*4;
        float4 v = *(const float4*)(vb + (size_t)i*64 + dd);
        __nv_bfloat16 h0=__float2bfloat16(v.x), h1=__float2bfloat16(v.y);
        __nv_bfloat16 h2=__float2bfloat16(v.z), h3=__float2bfloat16(v.w);
        u32 off = i*144 + dd*2;
        *(__nv_bfloat162*)(sm + VH + off)     = {h0,h1};
        *(__nv_bfloat162*)(sm + VH + off + 4) = {h2,h3};
        *(__nv_bfloat162*)(sm + VL + off)     = {__float2bfloat16(v.x-__bfloat162float(h0)),
                                                 __float2bfloat16(v.y-__bfloat162float(h1))};
        *(__nv_bfloat162*)(sm + VL + off + 4) = {__float2bfloat16(v.z-__bfloat162float(h2)),
                                                 __float2bfloat16(v.w-__bfloat162float(h3))};
    }
    CP_WAIT0();
    __syncthreads();

    // ks: column sums of kf
    if (tid < 128) {
        float s = 0.f;
        for (int i = 0; i < 128; i++) {
            s += __bfloat162float(*(const __nv_bfloat16*)(sm + KFH + i*272 + tid*2));
            s += __bfloat162float(*(const __nv_bfloat16*)(sm + KFL + i*272 + tid*2));
        }
        g_ks[(size_t)bhc*PMc + fb*128 + tid] = s;
    }

    int t_row = (lane & 7) + (((lane >> 4) & 1) << 3);
    int t_colbit = ((lane >> 3) & 1) << 3;

    float acc[2][4][4];
    #pragma unroll
    for (int i = 0; i < 2; i++)
        #pragma unroll
        for (int j = 0; j < 4; j++)
            #pragma unroll
            for (int q = 0; q < 4; q++) acc[i][j][q] = 0.f;

    #pragma unroll
    for (int ks16 = 0; ks16 < 8; ks16++) {
        int krow = ks16*16 + t_row;
        u32 afh[2][4], afl[2][4], bvh[2][4], bvl[2][4];
        #pragma unroll
        for (int mi = 0; mi < 2; mi++) {
            int fc = wm*32 + mi*16 + t_colbit;
            u32 addr = sb + KFH + krow*272 + fc*2;
            ldsm4t(afh[mi][0], afh[mi][1], afh[mi][2], afh[mi][3], addr);
            ldsm4t(afl[mi][0], afl[mi][1], afl[mi][2], afl[mi][3], addr + (KFL-KFH));
        }
        #pragma unroll
        for (int nj = 0; nj < 2; nj++) {
            int dc = wn*32 + nj*16 + t_colbit;
            u32 addr = sb + VH + krow*144 + dc*2;
            ldsm4t(bvh[nj][0], bvh[nj][1], bvh[nj][2], bvh[nj][3], addr);
            ldsm4t(bvl[nj][0], bvl[nj][1], bvl[nj][2], bvl[nj][3], addr + (VL-VH));
        }
        #pragma unroll
        for (int mi = 0; mi < 2; mi++) {
            #pragma unroll
            for (int ng = 0; ng < 4; ng++) {
                int nj = ng >> 1, sel = ng & 1;
                mma16816(acc[mi][ng], afh[mi], bvh[nj][sel], bvh[nj][2+sel]);
                mma16816(acc[mi][ng], afh[mi], bvl[nj][sel], bvl[nj][2+sel]);
                mma16816(acc[mi][ng], afl[mi], bvh[nj][sel], bvh[nj][2+sel]);
            }
        }
    }
    float* outp = g_ckv + (size_t)bhc*PMc*Dc + (size_t)fb*128*Dc;
    #pragma unroll
    for (int mi = 0; mi < 2; mi++) {
        #pragma unroll
        for (int ng = 0; ng < 4; ng++) {
            int f = wm*32 + mi*16 + (lane >> 2);
            int d = wn*32 + ng*8 + (lane & 3)*2;
            *(float2*)(outp + (size_t)f*64 + d)     = make_float2(acc[mi][ng][0], acc[mi][ng][1]);
            *(float2*)(outp + (size_t)(f+8)*64 + d) = make_float2(acc[mi][ng][2], acc[mi][ng][3]);
        }
    }
}

// ---------------- exclusive prefix over chunks -------------------------------
__global__ void prefix_kv_k()
{
    size_t idx = (size_t)blockIdx.x*256 + threadIdx.x;
    size_t bh = idx / (PMc*Dc);
    size_t rem = idx % (PMc*Dc);
    float acc = 0.f;
    #pragma unroll
    for (int c = 0; c < NCc; c++) {
        size_t p = (bh*NCc + c)*(size_t)(PMc*Dc) + rem;
        float v = g_ckv[p];
        g_ckv[p] = acc;
        acc += v;
    }
}
__global__ void prefix_ks_k()
{
    size_t idx = (size_t)blockIdx.x*256 + threadIdx.x;
    size_t bh = idx / PMc;
    size_t rem = idx % PMc;
    float acc = 0.f;
    #pragma unroll
    for (int c = 0; c < NCc; c++) {
        size_t p = (bh*NCc + c)*(size_t)PMc + rem;
        float v = g_ks[p];
        g_ks[p] = acc;
        acc += v;
    }
}

// ---------------- scores (HMMA): S = qf kf^T, mask, rowsum, intra = S v -----
__global__ __launch_bounds__(256, 1) void scores_mma_k()
{
    extern __shared__ char sm[];
    __shared__ float rowsum[128];
    u32 sb = smem_u32(sm);
    // phase1: stage s at s*40960; within stage QH 0, QL 10240, KH 20480, KL 30720
    // phase2: SH 0, SL 34816, VH2 69632, VL2 88064
    int bhc = blockIdx.x;
    int bh = bhc >> 5, c = bhc & 31;
    int tid = threadIdx.x, lane = tid & 31, warp = tid >> 5;
    int wm = warp >> 1, wn = warp & 1;
    if (tid < 128) rowsum[tid] = 0.f;

    const __nv_bfloat16* qh = g_qfh + (size_t)bhc*CHc*PMc;
    const __nv_bfloat16* ql = g_qfl + (size_t)bhc*CHc*PMc;
    const __nv_bfloat16* kh = g_kfh + (size_t)bhc*CHc*PMc;
    const __nv_bfloat16* kl = g_kfl + (size_t)bhc*CHc*PMc;

    int r0 = (tid*2) >> 2, s0 = (tid*2) & 3;
    int r1 = (tid*2+1) >> 2, s1 = (tid*2+1) & 3;
    int lr = lane & 7;
    int a_row = lr + (((lane >> 3) & 1) << 3);
    int a_col = ((lane >> 4) & 1) << 3;
    int b_row = lr + (((lane >> 4) & 1) << 3);
    int b_col = ((lane >> 3) & 1) << 3;

    float acc[2][8][4];
    #pragma unroll
    for (int i = 0; i < 2; i++)
        #pragma unroll
        for (int j = 0; j < 8; j++)
            #pragma unroll
            for (int q = 0; q < 4; q++) acc[i][j][q] = 0.f;

    auto load_chunk = [&](int ch, int stage) {
        int k0 = ch * 32;
        u32 st = sb + stage * 40960;
        u32 d0 = st + r0*80 + s0*16;
        u32 d1 = st + r1*80 + s1*16;
        CP_ASYNC16(d0,         qh + (size_t)r0*PMc + k0 + s0*8);
        CP_ASYNC16(d1,         qh + (size_t)r1*PMc + k0 + s1*8);
        CP_ASYNC16(d0 + 10240, ql + (size_t)r0*PMc + k0 + s0*8);
        CP_ASYNC16(d1 + 10240, ql + (size_t)r1*PMc + k0 + s1*8);
        CP_ASYNC16(d0 + 20480, kh + (size_t)r0*PMc + k0 + s0*8);
        CP_ASYNC16(d1 + 20480, kh + (size_t)r1*PMc + k0 + s1*8);
        CP_ASYNC16(d0 + 30720, kl + (size_t)r0*PMc + k0 + s0*8);
        CP_ASYNC16(d1 + 30720, kl + (size_t)r1*PMc + k0 + s1*8);
        CP_COMMIT();
    };

    load_chunk(0, 0);
    for (int ch = 0; ch < 16; ch++) {
        int stage = ch & 1;
        if (ch + 1 < 16) { load_chunk(ch + 1, stage ^ 1); CP_WAIT1(); }
        else             { CP_WAIT0(); }
        __syncthreads();
        u32 st = sb + stage * 40960;
        #pragma unroll
        for (int ks = 0; ks < 2; ks++) {
            u32 afh[2][4], afl[2][4], bfh[4][4], bfl[4][4];
            #pragma unroll
            for (int mi = 0; mi < 2; mi++) {
                u32 addr = st + ((wm*32 + mi*16 + a_row)*40 + ks*16 + a_col)*2;
                ldsm4(afh[mi][0], afh[mi][1], afh[mi][2], afh[mi][3], addr);
                ldsm4(afl[mi][0], afl[mi][1], afl[mi][2], afl[mi][3], addr + 10240);
            }
            #pragma unroll
            for (int nj = 0; nj < 4; nj++) {
                u32 addr = st + 20480 + ((wn*64 + nj*16 + b_row)*40 + ks*16 + b_col)*2;
                ldsm4(bfh[nj][0], bfh[nj][1], bfh[nj][2], bfh[nj][3], addr);
                ldsm4(bfl[nj][0], bfl[nj][1], bfl[nj][2], bfl[nj][3], addr + 10240);
            }
            #pragma unroll
            for (int mi = 0; mi < 2; mi++) {
                #pragma unroll
                for (int ni = 0; ni < 8; ni++) {
                    int nj = ni >> 1, off = (ni & 1) << 1;
                    mma16816(acc[mi][ni], afh[mi], bfh[nj][off], bfh[nj][off+1]);
                    mma16816(acc[mi][ni], afh[mi], bfl[nj][off], bfl[nj][off+1]);
                    mma16816(acc[mi][ni], afl[mi], bfh[nj][off], bfh[nj][off+1]);
                }
            }
        }
        __syncthreads();
    }

    // mask, rowsums, convert S to bf16 hi/lo in smem
    #pragma unroll
    for (int mi = 0; mi < 2; mi++) {
        float rs0 = 0.f, rs1 = 0.f;
        int ri0 = wm*32 + mi*16 + (lane >> 2);
        #pragma unroll
        for (int ni = 0; ni < 8; ni++) {
            int cj = wn*64 + ni*8 + (lane & 3)*2;
            float v00 = (cj   <= ri0)   ? acc[mi][ni][0] : 0.f;
            float v01 = (cj+1 <= ri0)   ? acc[mi][ni][1] : 0.f;
            float v10 = (cj   <= ri0+8) ? acc[mi][ni][2] : 0.f;
            float v11 = (cj+1 <= ri0+8) ? acc[mi][ni][3] : 0.f;
            rs0 += v00 + v01; rs1 += v10 + v11;
            __nv_bfloat16 h00=__float2bfloat16(v00), h01=__float2bfloat16(v01);
            __nv_bfloat16 h10=__float2bfloat16(v10), h11=__float2bfloat16(v11);
            u32 o0 = ri0*272 + cj*2, o1 = (ri0+8)*272 + cj*2;
            *(__nv_bfloat162*)(sm + o0)         = {h00,h01};
            *(__nv_bfloat162*)(sm + o1)         = {h10,h11};
            *(__nv_bfloat162*)(sm + 34816 + o0) = {__float2bfloat16(v00-__bfloat162float(h00)),
                                                   __float2bfloat16(v01-__bfloat162float(h01))};
            *(__nv_bfloat162*)(sm + 34816 + o1) = {__float2bfloat16(v10-__bfloat162float(h10)),
                                                   __float2bfloat16(v11-__bfloat162float(h11))};
        }
        rs0 += __shfl_xor_sync(0xffffffffu, rs0, 1);
        rs0 += __shfl_xor_sync(0xffffffffu, rs0, 2);
        rs1 += __shfl_xor_sync(0xffffffffu, rs1, 1);
        rs1 += __shfl_xor_sync(0xffffffffu, rs1, 2);
        if ((lane & 3) == 0) {
            atomicAdd(&rowsum[ri0], rs0);
            atomicAdd(&rowsum[ri0+8], rs1);
        }
    }
    // v -> bf16 hi/lo smem
    const float* vb = g_v + ((size_t)bh*Tc + c*CHc)*Dc;
    #pragma unroll
    for (int l = 0; l < 8; l++) {
        int idx = tid + l*256;
        int i = idx >> 4, dd = (idx & 15)*4;
        float4 v = *(const float4*)(vb + (size_t)i*64 + dd);
        __nv_bfloat16 h0=__float2bfloat16(v.x), h1=__float2bfloat16(v.y);
        __nv_bfloat16 h2=__float2bfloat16(v.z), h3=__float2bfloat16(v.w);
        u32 off = 69632 + i*144 + dd*2;
        *(__nv_bfloat162*)(sm + off)     = {h0,h1};
        *(__nv_bfloat162*)(sm + off + 4) = {h2,h3};
        *(__nv_bfloat162*)(sm + off + (88064-69632))     = {__float2bfloat16(v.x-__bfloat162float(h0)),
                                                            __float2bfloat16(v.y-__bfloat162float(h1))};
        *(__nv_bfloat162*)(sm + off + (88064-69632) + 4) = {__float2bfloat16(v.z-__bfloat162float(h2)),
                                                            __float2bfloat16(v.w-__bfloat162float(h3))};
    }
    __syncthreads();
    if (tid < 128) g_nrm[(size_t)bh*Tc + c*CHc + tid] = rowsum[tid];

    // phase 2: intra = S @ v
    int t_row = (lane & 7) + (((lane >> 4) & 1) << 3);
    int t_colbit = ((lane >> 3) & 1) << 3;
    float acc2[2][4][4];
    #pragma unroll
    for (int i = 0; i < 2; i++)
        #pragma unroll
        for (int j = 0; j < 4; j++)
            #pragma unroll
            for (int q = 0; q < 4; q++) acc2[i][j][q] = 0.f;

    #pragma unroll
    for (int ks16 = 0; ks16 < 8; ks16++) {
        u32 ah2[2][4], al2[2][4], bvh[2][4], bvl[2][4];
        #pragma unroll
        for (int mi = 0; mi < 2; mi++) {
            u32 addr = sb + ((wm*32 + mi*16 + a_row)*136 + ks16*16 + a_col)*2;
            ldsm4(ah2[mi][0], ah2[mi][1], ah2[mi][2], ah2[mi][3], addr);
            ldsm4(al2[mi][0], al2[mi][1], al2[mi][2], al2[mi][3], addr + 34816);
        }
        int krow = ks16*16 + t_row;
        #pragma unroll
        for (int nj = 0; nj < 2; nj++) {
            int dc = wn*32 + nj*16 + t_colbit;
            u32 addr = sb + 69632 + krow*144 + dc*2;
            ldsm4t(bvh[nj][0], bvh[nj][1], bvh[nj][2], bvh[nj][3], addr);
            ldsm4t(bvl[nj][0], bvl[nj][1], bvl[nj][2], bvl[nj][3], addr + (88064-69632));
        }
        #pragma unroll
        for (int mi = 0; mi < 2; mi++) {
            #pragma unroll
            for (int ng = 0; ng < 4; ng++) {
                int nj = ng >> 1, sel = ng & 1;
                mma16816(acc2[mi][ng], ah2[mi], bvh[nj][sel], bvh[nj][2+sel]);
                mma16816(acc2[mi][ng], ah2[mi], bvl[nj][sel], bvl[nj][2+sel]);
                mma16816(acc2[mi][ng], al2[mi], bvh[nj][sel], bvh[nj][2+sel]);
            }
        }
    }
    float* ob = g_o + ((size_t)bh*Tc + c*CHc)*Dc;
    #pragma unroll
    for (int mi = 0; mi < 2; mi++) {
        #pragma unroll
        for (int ng = 0; ng < 4; ng++) {
            int tok = wm*32 + mi*16 + (lane >> 2);
            int d = wn*32 + ng*8 + (lane & 3)*2;
            *(float2*)(ob + (size_t)tok*64 + d)     = make_float2(acc2[mi][ng][0], acc2[mi][ng][1]);
            *(float2*)(ob + (size_t)(tok+8)*64 + d) = make_float2(acc2[mi][ng][2], acc2[mi][ng][3]);
        }
    }
}

// ---------------- hist (HMMA): ctx = qf @ kv_state^T, + nrm finalize --------
__global__ __launch_bounds__(256, 1) void hist_mma_k()
{
    extern __shared__ char sm[];
    __shared__ float ks_sm[512];
    __shared__ float nrm_sm[128];
    u32 sb = smem_u32(sm);
    // stage s at s*29696: QH 0, QL 10240, KVH 20480, KVL 25088
    int bhc = blockIdx.x;
    int bh = bhc >> 5, c = bhc & 31;
    int tid = threadIdx.x, lane = tid & 31, warp = tid >> 5;
    int wm = warp >> 1, wn = warp & 1;

    const __nv_bfloat16* qh = g_qfh + (size_t)bhc*CHc*PMc;
    const __nv_bfloat16* ql = g_qfl + (size_t)bhc*CHc*PMc;
    const __nv_bfloat16* kvh = g_ckvh + (size_t)bhc*PMc*Dc;
    const __nv_bfloat16* kvl = g_ckvl + (size_t)bhc*PMc*Dc;
    const float* ksb = g_ks + (size_t)bhc*PMc;
    ks_sm[tid] = ksb[tid];
    ks_sm[tid+256] = ksb[tid+256];

    int r0 = (tid*2) >> 2, s0 = (tid*2) & 3;
    int r1 = (tid*2+1) >> 2, s1 = (tid*2+1) & 3;
    int kvr = tid >> 3, kvs = tid & 7;
    int lr = lane & 7;
    int a_row = lr + (((lane >> 3) & 1) << 3);
    int a_col = ((lane >> 4) & 1) << 3;
    int t_row = lr + (((lane >> 4) & 1) << 3);
    int t_colbit = ((lane >> 3) & 1) << 3;

    float acc[2][4][4];
    #pragma unroll
    for (int i = 0; i < 2; i++)
        #pragma unroll
        for (int j = 0; j < 4; j++)
            #pragma unroll
            for (int q = 0; q < 4; q++) acc[i][j][q] = 0.f;
    float nacc = 0.f;

    auto load_chunk = [&](int ch, int stage) {
        int k0 = ch * 32;
        u32 st = sb + stage * 29696;
        u32 d0 = st + r0*80 + s0*16;
        u32 d1 = st + r1*80 + s1*16;
        CP_ASYNC16(d0,         qh + (size_t)r0*PMc + k0 + s0*8);
        CP_ASYNC16(d1,         qh + (size_t)r1*PMc + k0 + s1*8);
        CP_ASYNC16(d0 + 10240, ql + (size_t)r0*PMc + k0 + s0*8);
        CP_ASYNC16(d1 + 10240, ql + (size_t)r1*PMc + k0 + s1*8);
        u32 dk = st + 20480 + kvr*144 + kvs*16;
        CP_ASYNC16(dk,        kvh + (size_t)(k0+kvr)*64 + kvs*8);
        CP_ASYNC16(dk + 4608, kvl + (size_t)(k0+kvr)*64 + kvs*8);
        CP_COMMIT();
    };

    load_chunk(0, 0);
    for (int ch = 0; ch < 16; ch++) {
        int stage = ch & 1;
        if (ch + 1 < 16) { load_chunk(ch + 1, stage ^ 1); CP_WAIT1(); }
        else             { CP_WAIT0(); }
        __syncthreads();
        u32 st = sb + stage * 29696;
        #pragma unroll
        for (int ks16 = 0; ks16 < 2; ks16++) {
            u32 afh[2][4], afl[2][4], bvh[2][4], bvl[2][4];
            #pragma unroll
            for (int mi = 0; mi < 2; mi++) {
                u32 addr = st + ((wm*32 + mi*16 + a_row)*40 + ks16*16 + a_col)*2;
                ldsm4(afh[mi][0], afh[mi][1], afh[mi][2], afh[mi][3], addr);
                ldsm4(afl[mi][0], afl[mi][1], afl[mi][2], afl[mi][3], addr + 10240);
            }
            int krow = ks16*16 + t_row;
            #pragma unroll
            for (int nj = 0; nj < 2; nj++) {
                int dc = wn*32 + nj*16 + t_colbit;
                u32 addr = st + 20480 + krow*144 + dc*2;
                ldsm4t(bvh[nj][0], bvh[nj][1], bvh[nj][2], bvh[nj][3], addr);
                ldsm4t(bvl[nj][0], bvl[nj][1], bvl[nj][2], bvl[nj][3], addr + 4608);
            }
            #pragma unroll
            for (int mi = 0; mi < 2; mi++) {
                #pragma unroll
                for (int ng = 0; ng < 4; ng++) {
                    int nj = ng >> 1, sel = ng & 1;
                    mma16816(acc[mi][ng], afh[mi], bvh[nj][sel], bvh[nj][2+sel]);
                    mma16816(acc[mi][ng], afh[mi], bvl[nj][sel], bvl[nj][2+sel]);
                    mma16816(acc[mi][ng], afl[mi], bvh[nj][sel], bvh[nj][2+sel]);
                }
            }
        }
        // scalar partial for nrm_hist: token = tid>>1, f half = tid&1
        {
            int tt = tid >> 1, fh = (tid & 1)*16;
            const __nv_bfloat16* qhs = (const __nv_bfloat16*)(sm + stage*29696 + tt*80);
            const __nv_bfloat16* qls = (const __nv_bfloat16*)(sm + stage*29696 + 10240 + tt*80);
            #pragma unroll
            for (int f = 0; f < 16; f++) {
                int fl = fh + f;
                float qv = __bfloat162float(qhs[fl]) + __bfloat162float(qls[fl]);
                nacc += qv * ks_sm[ch*32 + fl];
            }
        }
        __syncthreads();
    }
    nacc += __shfl_xor_sync(0xffffffffu, nacc, 1);
    if ((tid & 1) == 0) nrm_sm[tid >> 1] = nacc;
    __syncthreads();
    if (tid < 128) {
        float tot = nrm_sm[tid] + g_nrm[(size_t)bh*Tc + c*CHc + tid] + 1e-6f;
        nrm_sm[tid] = 1.f / tot;
    }
    __syncthreads();

    float* ob = g_o + ((size_t)bh*Tc + c*CHc)*Dc;
    #pragma unroll
    for (int mi = 0; mi < 2; mi++) {
        #pragma unroll
        for (int ng = 0; ng < 4; ng++) {
            int tok = wm*32 + mi*16 + (lane >> 2);
            int d = wn*32 + ng*8 + (lane & 3)*2;
            float inv0 = nrm_sm[tok], inv1 = nrm_sm[tok+8];
            float2* p0 = (float2*)(ob + (size_t)tok*64 + d);
            float2* p1 = (float2*)(ob + (size_t)(tok+8)*64 + d);
            float2 c0 = *p0, c1 = *p1;
            c0.x = (c0.x + acc[mi][ng][0]) * inv0;
            c0.y = (c0.y + acc[mi][ng][1]) * inv0;
            c1.x = (c1.x + acc[mi][ng][2]) * inv1;
            c1.y = (c1.y + acc[mi][ng][3]) * inv1;
            *p0 = c0; *p1 = c1;
        }
    }
}

// ---------------- host launcher ---------------------------------------------
extern "C" void kernel_launch(void* const* d_in, const int* in_sizes, int n_in,
                              void* d_out, int out_size)
{
    const float* x        = (const float*)d_in[0];
    const float* qkv_w    = (const float*)d_in[1];
    const float* qkv_b    = (const float*)d_in[2];
    const float* out_w    = (const float*)d_in[3];
    const float* out_b    = (const float*)d_in[4];
    const float* omega    = (const float*)d_in[5];
    const float* poly_w   = (const float*)d_in[6];
    const float* qnodes   = (const float*)d_in[7];
    const float* qweights = (const float*)d_in[8];
    float* out = (float*)d_out;

    float* qkv_ptr = 0;
    cudaGetSymbolAddress((void**)&qkv_ptr, g_qkv);
    __nv_bfloat16 *ah, *al, *wh, *wl;
    cudaGetSymbolAddress((void**)&ah, g_ah);
    cudaGetSymbolAddress((void**)&al, g_al);
    cudaGetSymbolAddress((void**)&wh, g_wh);
    cudaGetSymbolAddress((void**)&wl, g_wl);

    cudaFuncSetAttribute(gemm_mma_k, cudaFuncAttributeMaxDynamicSharedMemorySize, 2*S_STAGE);
    cudaFuncSetAttribute(passA_mma_k, cudaFuncAttributeMaxDynamicSharedMemorySize, 106496);
    cudaFuncSetAttribute(scores_mma_k, cudaFuncAttributeMaxDynamicSharedMemorySize, 106496);
    cudaFuncSetAttribute(hist_mma_k, cudaFuncAttributeMaxDynamicSharedMemorySize, 59392);

    // 1) split operands to bf16 hi/lo
    split_bf16_k<<<(Bc*Tc*Ec)/1024, 256>>>(x, ah, al);
    split_bf16_k<<<(3*Ec*Ec)/1024, 256>>>(qkv_w, wh, wl);
    // 2) QKV GEMM (HMMA)
    gemm_mma_k<<<dim3(3*Ec/128, (Bc*Tc)/128), 256, 2*S_STAGE>>>(
        ah, al, wh, wl, qkv_b, qkv_ptr, 3*Ec);
    // 3) head split + l2norm
    split_norm_k<<<Bc*Tc*Hc, 32>>>();
    // 4) feature maps -> bf16 hi/lo [token][feature]
    features_k<<<dim3(BHc*NCc, 2), 256>>>(omega, poly_w, qnodes, qweights);
    // 5) per-chunk kv + ks (HMMA)
    passA_mma_k<<<dim3(BHc*NCc, 4), 256, 106496>>>();
    // 6) exclusive prefix over chunks
    prefix_kv_k<<<(BHc*PMc*Dc)/256, 256>>>();
    prefix_ks_k<<<(BHc*PMc)/256, 256>>>();
    // 7) kv state -> bf16 hi/lo
    cvt_ckv_k<<<(BHc*NCc*PMc*Dc)/1024, 256>>>();
    // 8) intra-chunk scores + intra context (HMMA)
    scores_mma_k<<<BHc*NCc, 256, 106496>>>();
    // 9) history context + normalize (HMMA)
    hist_mma_k<<<BHc*NCc, 256, 59392>>>();
    // 10) output projection (HMMA)
    o2rows_k<<<(BHc*Tc*Dc)/512, 256>>>();
    split_bf16_k<<<(Ec*Ec)/1024, 256>>>(out_w, wh, wl);
    gemm_mma_k<<<dim3(Ec/128, (Bc*Tc)/128), 256, 2*S_STAGE>>>(
        ah, al, wh, wl, out_b, out, Ec);
}

// round 6
// speedup vs baseline: 2.3099x; 1.0661x over previous
#include <cuda_runtime.h>
#include <cuda_bf16.h>
#include <math.h>

#define Bc 2
#define Tc 4096
#define Ec 1024
#define Hc 16
#define Dc 64
#define Pc 64
#define PMc 512
#define CHc 128
#define NCc 32
#define BHc 32

typedef unsigned long long u64;
typedef unsigned int u32;

// ---------------- scratch (device globals; no allocations allowed) ----------
__device__ float g_qkv[(size_t)Bc*Tc*3*Ec];
__device__ float g_ckv[(size_t)BHc*NCc*PMc*Dc];      // (bhc, f, d) fp32 per-chunk
__device__ float g_ks [(size_t)BHc*NCc*PMc];
__device__ float g_o  [(size_t)BHc*Tc*Dc];
__device__ float g_nrm[(size_t)BHc*Tc];
// bf16 hi/lo features, [bhc][token 128][feature 512]
__device__ __align__(16) __nv_bfloat16 g_qfh[(size_t)BHc*NCc*CHc*PMc];
__device__ __align__(16) __nv_bfloat16 g_qfl[(size_t)BHc*NCc*CHc*PMc];
__device__ __align__(16) __nv_bfloat16 g_kfh[(size_t)BHc*NCc*CHc*PMc];
__device__ __align__(16) __nv_bfloat16 g_kfl[(size_t)BHc*NCc*CHc*PMc];
// bf16 hi/lo exclusive kv state, [bhc][f][d]
__device__ __align__(16) __nv_bfloat16 g_ckvh[(size_t)BHc*NCc*PMc*Dc];
__device__ __align__(16) __nv_bfloat16 g_ckvl[(size_t)BHc*NCc*PMc*Dc];
// bf16 split operands for dense GEMMs
__device__ __align__(16) __nv_bfloat16 g_ah[(size_t)Bc*Tc*Ec];
__device__ __align__(16) __nv_bfloat16 g_al[(size_t)Bc*Tc*Ec];
__device__ __align__(16) __nv_bfloat16 g_wh[(size_t)3*Ec*Ec];
__device__ __align__(16) __nv_bfloat16 g_wl[(size_t)3*Ec*Ec];

// ================= helpers ===================================================
__device__ __forceinline__ u32 smem_u32(const void* p) {
    u32 a; asm("{ .reg .u64 t; cvta.to.shared.u64 t, %1; cvt.u32.u64 %0, t; }"
               : "=r"(a) : "l"(p));
    return a;
}
#define CP_ASYNC16(dst, src) \
    asm volatile("cp.async.cg.shared.global [%0], [%1], 16;\n" :: "r"(dst), "l"(src))
#define CP_COMMIT() asm volatile("cp.async.commit_group;\n" ::: "memory")
#define CP_WAIT1()  asm volatile("cp.async.wait_group 1;\n" ::: "memory")
#define CP_WAIT0()  asm volatile("cp.async.wait_group 0;\n" ::: "memory")

__device__ __forceinline__ void ldsm4(u32 &r0, u32 &r1, u32 &r2, u32 &r3, u32 a) {
    asm volatile("ldmatrix.sync.aligned.m8n8.x4.shared.b16 {%0,%1,%2,%3}, [%4];\n"
                 : "=r"(r0), "=r"(r1), "=r"(r2), "=r"(r3) : "r"(a));
}
__device__ __forceinline__ void ldsm4t(u32 &r0, u32 &r1, u32 &r2, u32 &r3, u32 a) {
    asm volatile("ldmatrix.sync.aligned.m8n8.x4.trans.shared.b16 {%0,%1,%2,%3}, [%4];\n"
                 : "=r"(r0), "=r"(r1), "=r"(r2), "=r"(r3) : "r"(a));
}
__device__ __forceinline__ void mma16816(float* c, const u32* a, u32 b0, u32 b1) {
    asm volatile(
        "mma.sync.aligned.m16n8k16.row.col.f32.bf16.bf16.f32 "
        "{%0,%1,%2,%3},{%4,%5,%6,%7},{%8,%9},{%0,%1,%2,%3};\n"
        : "+f"(c[0]), "+f"(c[1]), "+f"(c[2]), "+f"(c[3])
        : "r"(a[0]), "r"(a[1]), "r"(a[2]), "r"(a[3]), "r"(b0), "r"(b1));
}

// ================= fp32 -> bf16 hi/lo split ==================================
__global__ void split_bf16_k(const float* __restrict__ s,
                             __nv_bfloat16* __restrict__ h,
                             __nv_bfloat16* __restrict__ l)
{
    size_t i = ((size_t)blockIdx.x*256 + threadIdx.x)*4;
    float4 v = *(const float4*)(s + i);
    __nv_bfloat16 h0=__float2bfloat16(v.x), h1=__float2bfloat16(v.y);
    __nv_bfloat16 h2=__float2bfloat16(v.z), h3=__float2bfloat16(v.w);
    __nv_bfloat162 ha = {h0,h1}, hb = {h2,h3};
    __nv_bfloat162 la = {__float2bfloat16(v.x-__bfloat162float(h0)),
                         __float2bfloat16(v.y-__bfloat162float(h1))};
    __nv_bfloat162 lb = {__float2bfloat16(v.z-__bfloat162float(h2)),
                         __float2bfloat16(v.w-__bfloat162float(h3))};
    *(__nv_bfloat162*)(h+i) = ha; *(__nv_bfloat162*)(h+i+2) = hb;
    *(__nv_bfloat162*)(l+i) = la; *(__nv_bfloat162*)(l+i+2) = lb;
}

// ------ reshape g_o (B,H,T,D) -> rows (b*T+t, h*64+d), bf16 hi/lo ------------
__global__ void o2rows_k()
{
    size_t gidx = ((size_t)blockIdx.x*256 + threadIdx.x)*2;
    float2 v = *(const float2*)(g_o + gidx);
    int d = (int)(gidx & 63), t = (int)((gidx >> 6) & 4095);
    int h = (int)((gidx >> 18) & 15), b = (int)(gidx >> 22);
    size_t dst = ((size_t)(b*Tc + t))*Ec + h*64 + d;
    __nv_bfloat16 h0=__float2bfloat16(v.x), h1=__float2bfloat16(v.y);
    *(__nv_bfloat162*)(g_ah+dst) = {h0,h1};
    *(__nv_bfloat162*)(g_al+dst) = {__float2bfloat16(v.x-__bfloat162float(h0)),
                                    __float2bfloat16(v.y-__bfloat162float(h1))};
}

// ================= HMMA GEMM: C[M,N] = A @ W^T + bias (bf16x3 split) ========
#define S_STRIDE 40
#define S_ARR 10240
#define S_STAGE 40960

__global__ __launch_bounds__(256, 1)
void gemm_mma_k(const __nv_bfloat16* __restrict__ Abase_h,
                const __nv_bfloat16* __restrict__ Abase_l,
                const __nv_bfloat16* __restrict__ Wbase_h,
                const __nv_bfloat16* __restrict__ Wbase_l,
                const float* __restrict__ bias, float* __restrict__ C, int N)
{
    extern __shared__ char smem[];
    u32 sb = smem_u32(smem);
    const int K = 1024;
    int tid = threadIdx.x;
    int lane = tid & 31, warp = tid >> 5;
    int wm = warp >> 1, wn = warp & 1;
    int bm = blockIdx.y * 128, bn = blockIdx.x * 128;

    const __nv_bfloat16* Ah = Abase_h + (size_t)bm * K;
    const __nv_bfloat16* Al = Abase_l + (size_t)bm * K;
    const __nv_bfloat16* Wh = Wbase_h + (size_t)bn * K;
    const __nv_bfloat16* Wl = Wbase_l + (size_t)bn * K;

    int r0 = (tid*2) >> 2, s0 = (tid*2) & 3;
    int r1 = (tid*2+1) >> 2, s1 = (tid*2+1) & 3;

    int lr = lane & 7;
    int a_row = lr + (((lane >> 3) & 1) << 3);
    int a_col = ((lane >> 4) & 1) << 3;
    int b_row = lr + (((lane >> 4) & 1) << 3);
    int b_col = ((lane >> 3) & 1) << 3;

    float acc[2][8][4];
    #pragma unroll
    for (int i = 0; i < 2; i++)
        #pragma unroll
        for (int j = 0; j < 8; j++)
            #pragma unroll
            for (int q = 0; q < 4; q++) acc[i][j][q] = 0.f;

    auto load_chunk = [&](int ch, int stage) {
        int k0 = ch * 32;
        u32 st = sb + stage * S_STAGE;
        u32 d0 = st + r0*80 + s0*16;
        u32 d1 = st + r1*80 + s1*16;
        CP_ASYNC16(d0, Ah + (size_t)r0*K + k0 + s0*8);
        CP_ASYNC16(d1, Ah + (size_t)r1*K + k0 + s1*8);
        CP_ASYNC16(d0 + S_ARR, Al + (size_t)r0*K + k0 + s0*8);
        CP_ASYNC16(d1 + S_ARR, Al + (size_t)r1*K + k0 + s1*8);
        CP_ASYNC16(d0 + 2*S_ARR, Wh + (size_t)r0*K + k0 + s0*8);
        CP_ASYNC16(d1 + 2*S_ARR, Wh + (size_t)r1*K + k0 + s1*8);
        CP_ASYNC16(d0 + 3*S_ARR, Wl + (size_t)r0*K + k0 + s0*8);
        CP_ASYNC16(d1 + 3*S_ARR, Wl + (size_t)r1*K + k0 + s1*8);
        CP_COMMIT();
    };

    load_chunk(0, 0);

    for (int ch = 0; ch < 32; ch++) {
        int stage = ch & 1;
        if (ch + 1 < 32) { load_chunk(ch + 1, stage ^ 1); CP_WAIT1(); }
        else             { CP_WAIT0(); }
        __syncthreads();

        u32 st = sb + stage * S_STAGE;
        #pragma unroll
        for (int ks = 0; ks < 2; ks++) {
            u32 afh[2][4], afl[2][4], bfh[4][4], bfl[4][4];
            #pragma unroll
            for (int mi = 0; mi < 2; mi++) {
                u32 addr = st + ((wm*32 + mi*16 + a_row)*S_STRIDE + ks*16 + a_col)*2;
                ldsm4(afh[mi][0], afh[mi][1], afh[mi][2], afh[mi][3], addr);
                ldsm4(afl[mi][0], afl[mi][1], afl[mi][2], afl[mi][3], addr + S_ARR);
            }
            #pragma unroll
            for (int nj = 0; nj < 4; nj++) {
                u32 addr = st + 2*S_ARR +
                           ((wn*64 + nj*16 + b_row)*S_STRIDE + ks*16 + b_col)*2;
                ldsm4(bfh[nj][0], bfh[nj][1], bfh[nj][2], bfh[nj][3], addr);
                ldsm4(bfl[nj][0], bfl[nj][1], bfl[nj][2], bfl[nj][3], addr + S_ARR);
            }
            #pragma unroll
            for (int mi = 0; mi < 2; mi++) {
                #pragma unroll
                for (int ni = 0; ni < 8; ni++) {
                    int nj = ni >> 1, off = (ni & 1) << 1;
                    mma16816(acc[mi][ni], afh[mi], bfh[nj][off], bfh[nj][off+1]);
                    mma16816(acc[mi][ni], afh[mi], bfl[nj][off], bfl[nj][off+1]);
                    mma16816(acc[mi][ni], afl[mi], bfh[nj][off], bfh[nj][off+1]);
                }
            }
        }
        __syncthreads();
    }

    #pragma unroll
    for (int mi = 0; mi < 2; mi++) {
        #pragma unroll
        for (int ni = 0; ni < 8; ni++) {
            int m = bm + wm*32 + mi*16 + (lane >> 2);
            int n = bn + wn*64 + ni*8 + (lane & 3)*2;
            float2 o0, o1;
            o0.x = acc[mi][ni][0] + bias[n];
            o0.y = acc[mi][ni][1] + bias[n+1];
            o1.x = acc[mi][ni][2] + bias[n];
            o1.y = acc[mi][ni][3] + bias[n+1];
            *(float2*)(C + (size_t)m*N + n)     = o0;
            *(float2*)(C + (size_t)(m+8)*N + n) = o1;
        }
    }
}

// ---------------- feature map -> bf16 hi/lo [token][feature] ----------------
// reads q/k directly from g_qkv, performs l2-normalization in-kernel
__global__ __launch_bounds__(256) void features_k(
    const float* __restrict__ omega, const float* __restrict__ poly_w,
    const float* __restrict__ qnodes, const float* __restrict__ qweights)
{
    __shared__ float xs[64*129];
    __shared__ float om[64*8];
    __shared__ float prf[128*8];
    __shared__ float rn[128];
    int bhc = blockIdx.x;
    int isK = blockIdx.y;
    int bh = bhc >> 5, c = bhc & 31;
    int h = bh & 15, b = bh >> 4;
    const float* src = g_qkv + ((size_t)(b*Tc + c*CHc))*(3*Ec) + isK*Ec + h*64;
    __nv_bfloat16* dh = (isK ? g_kfh : g_qfh) + (size_t)bhc*CHc*PMc;
    __nv_bfloat16* dl = (isK ? g_kfl : g_qfl) + (size_t)bhc*CHc*PMc;
    int tid = threadIdx.x;
    #pragma unroll
    for (int l = 0; l < 32; l++) {
        int idx = tid + l*256;
        int i = idx >> 6, d = idx & 63;
        xs[d*129 + i] = src[(size_t)i*(3*Ec) + d];
    }
    om[tid]       = omega[h*512 + tid];
    om[tid + 256] = omega[h*512 + tid + 256];
    __syncthreads();
    if (tid < 128) {
        float s = 0.f;
        #pragma unroll
        for (int d = 0; d < 64; d++) { float x = xs[d*129 + tid]; s += x*x; }
        rn[tid] = 1.f / fmaxf(sqrtf(s), 1e-12f);
    }
    __syncthreads();
    float s0 = qnodes[0];
    float sq2s = sqrtf(fmaxf(2.f*s0, 0.f));
    float wq = sqrtf(fmaxf(qweights[0], 0.f));
    float prescale = 0.3535533905932738f * wq;
    #pragma unroll
    for (int l = 0; l < 4; l++) {
        int pair = tid + l*256;
        int i = pair >> 3, m = pair & 7;
        float a = 0.f;
        #pragma unroll
        for (int d = 0; d < 64; d++) a += xs[d*129 + i] * om[d*8 + m];
        float e = fminf(fmaxf(a * rn[i] * sq2s - s0, -20.f), 20.f);
        prf[i*8 + m] = expf(e) * prescale;
    }
    __syncthreads();
    int ti = (tid >> 4) << 3, tp = (tid & 15) << 2;
    float acc[8][4] = {};
    const float* pwp = poly_w + h*4096;
    for (int d = 0; d < 64; d++) {
        float a[8];
        #pragma unroll
        for (int x = 0; x < 8; x++) a[x] = xs[d*129 + ti + x];
        float4 bb = *(const float4*)(pwp + d*64 + tp);
        #pragma unroll
        for (int i2 = 0; i2 < 8; i2++) {
            acc[i2][0] += a[i2]*bb.x; acc[i2][1] += a[i2]*bb.y;
            acc[i2][2] += a[i2]*bb.z; acc[i2][3] += a[i2]*bb.w;
        }
    }
    #pragma unroll
    for (int i2 = 0; i2 < 8; i2++) {
        float r = rn[ti + i2];
        #pragma unroll
        for (int j = 0; j < 4; j++) {
            float t = acc[i2][j] * r;
            acc[i2][j] = t*t*0.125f;
        }
    }
    #pragma unroll
    for (int i2 = 0; i2 < 8; i2++) {
        int tok = ti + i2;
        __nv_bfloat16 hb[32], lb[32];
        #pragma unroll
        for (int j = 0; j < 4; j++)
            #pragma unroll
            for (int m = 0; m < 8; m++) {
                float v = acc[i2][j] * prf[tok*8 + m];
                __nv_bfloat16 hh = __float2bfloat16(v);
                hb[j*8+m] = hh;
                lb[j*8+m] = __float2bfloat16(v - __bfloat162float(hh));
            }
        __nv_bfloat16* ph = dh + (size_t)tok*PMc + tp*8;
        __nv_bfloat16* pl = dl + (size_t)tok*PMc + tp*8;
        #pragma unroll
        for (int s = 0; s < 4; s++) {
            *(uint4*)(ph + s*8) = *(uint4*)(hb + s*8);
            *(uint4*)(pl + s*8) = *(uint4*)(lb + s*8);
        }
    }
}

// ---------------- pass A (HMMA): kv[f][d] = sum_i kf[i][f] v[i][d] ----------
__global__ __launch_bounds__(256, 1) void passA_mma_k()
{
    extern __shared__ char sm[];
    u32 sb = smem_u32(sm);
    const u32 KFH = 0, KFL = 34816, VH = 69632, VL = 88064;
    int bhc = blockIdx.x, fb = blockIdx.y;
    int bh = bhc >> 5, c = bhc & 31;
    int tid = threadIdx.x, lane = tid & 31, warp = tid >> 5;
    int wm = warp >> 1, wn = warp & 1;

    const __nv_bfloat16* kh = g_kfh + (size_t)bhc*CHc*PMc + fb*128;
    const __nv_bfloat16* kl = g_kfl + (size_t)bhc*CHc*PMc + fb*128;
    #pragma unroll
    for (int l = 0; l < 8; l++) {
        int idx = tid + l*256;
        int row = idx >> 4, seg = idx & 15;
        u32 d = sb + KFH + row*272 + seg*16;
        CP_ASYNC16(d,              kh + (size_t)row*PMc + seg*8);
        CP_ASYNC16(d + (KFL-KFH),  kl + (size_t)row*PMc + seg*8);
    }
    CP_COMMIT();
    // load + convert v (directly from g_qkv)
    const float* vb = g_qkv + ((size_t)((bh>>4)*Tc + c*CHc))*(3*Ec) + 2*Ec + (bh&15)*64;
    #pragma unroll
    for (int l = 0; l < 8; l++) {
        int idx = tid + l*256;
        int i = idx >> 4, dd = (idx & 15)*4;
        float4 v = *(const float4*)(vb + (size_t)i*(3*Ec) + dd);
        __nv_bfloat16 h0=__float2bfloat16(v.x), h1=__float2bfloat16(v.y);
        __nv_bfloat16 h2=__float2bfloat16(v.z), h3=__float2bfloat16(v.w);
        u32 off = i*144 + dd*2;
        *(__nv_bfloat162*)(sm + VH + off)     = {h0,h1};
        *(__nv_bfloat162*)(sm + VH + off + 4) = {h2,h3};
        *(__nv_bfloat162*)(sm + VL + off)     = {__float2bfloat16(v.x-__bfloat162float(h0)),
                                                 __float2bfloat16(v.y-__bfloat162float(h1))};
        *(__nv_bfloat162*)(sm + VL + off + 4) = {__float2bfloat16(v.z-__bfloat162float(h2)),
                                                 __float2bfloat16(v.w-__bfloat162float(h3))};
    }
    CP_WAIT0();
    __syncthreads();

    if (tid < 128) {
        float s = 0.f;
        for (int i = 0; i < 128; i++) {
            s += __bfloat162float(*(const __nv_bfloat16*)(sm + KFH + i*272 + tid*2));
            s += __bfloat162float(*(const __nv_bfloat16*)(sm + KFL + i*272 + tid*2));
        }
        g_ks[(size_t)bhc*PMc + fb*128 + tid] = s;
    }

    int t_row = (lane & 7) + (((lane >> 4) & 1) << 3);
    int t_colbit = ((lane >> 3) & 1) << 3;

    float acc[2][4][4];
    #pragma unroll
    for (int i = 0; i < 2; i++)
        #pragma unroll
        for (int j = 0; j < 4; j++)
            #pragma unroll
            for (int q = 0; q < 4; q++) acc[i][j][q] = 0.f;

    #pragma unroll
    for (int ks16 = 0; ks16 < 8; ks16++) {
        int krow = ks16*16 + t_row;
        u32 afh[2][4], afl[2][4], bvh[2][4], bvl[2][4];
        #pragma unroll
        for (int mi = 0; mi < 2; mi++) {
            int fc = wm*32 + mi*16 + t_colbit;
            u32 addr = sb + KFH + krow*272 + fc*2;
            ldsm4t(afh[mi][0], afh[mi][1], afh[mi][2], afh[mi][3], addr);
            ldsm4t(afl[mi][0], afl[mi][1], afl[mi][2], afl[mi][3], addr + (KFL-KFH));
        }
        #pragma unroll
        for (int nj = 0; nj < 2; nj++) {
            int dc = wn*32 + nj*16 + t_colbit;
            u32 addr = sb + VH + krow*144 + dc*2;
            ldsm4t(bvh[nj][0], bvh[nj][1], bvh[nj][2], bvh[nj][3], addr);
            ldsm4t(bvl[nj][0], bvl[nj][1], bvl[nj][2], bvl[nj][3], addr + (VL-VH));
        }
        #pragma unroll
        for (int mi = 0; mi < 2; mi++) {
            #pragma unroll
            for (int ng = 0; ng < 4; ng++) {
                int nj = ng >> 1, sel = ng & 1;
                mma16816(acc[mi][ng], afh[mi], bvh[nj][sel], bvh[nj][2+sel]);
                mma16816(acc[mi][ng], afh[mi], bvl[nj][sel], bvl[nj][2+sel]);
                mma16816(acc[mi][ng], afl[mi], bvh[nj][sel], bvh[nj][2+sel]);
            }
        }
    }
    float* outp = g_ckv + (size_t)bhc*PMc*Dc + (size_t)fb*128*Dc;
    #pragma unroll
    for (int mi = 0; mi < 2; mi++) {
        #pragma unroll
        for (int ng = 0; ng < 4; ng++) {
            int f = wm*32 + mi*16 + (lane >> 2);
            int d = wn*32 + ng*8 + (lane & 3)*2;
            *(float2*)(outp + (size_t)f*64 + d)     = make_float2(acc[mi][ng][0], acc[mi][ng][1]);
            *(float2*)(outp + (size_t)(f+8)*64 + d) = make_float2(acc[mi][ng][2], acc[mi][ng][3]);
        }
    }
}

// ------- fused exclusive prefix over chunks + bf16 hi/lo convert -------------
__global__ void prefix_kv_cvt_k()
{
    size_t e = ((size_t)blockIdx.x*256 + threadIdx.x)*4;
    size_t bh = e / (PMc*Dc);
    size_t rem = e % (PMc*Dc);
    float4 acc = make_float4(0.f,0.f,0.f,0.f);
    #pragma unroll
    for (int c = 0; c < NCc; c++) {
        size_t p = (bh*NCc + c)*(size_t)(PMc*Dc) + rem;
        float4 v = *(const float4*)(g_ckv + p);
        __nv_bfloat16 h0=__float2bfloat16(acc.x), h1=__float2bfloat16(acc.y);
        __nv_bfloat16 h2=__float2bfloat16(acc.z), h3=__float2bfloat16(acc.w);
        *(__nv_bfloat162*)(g_ckvh+p)   = {h0,h1};
        *(__nv_bfloat162*)(g_ckvh+p+2) = {h2,h3};
        *(__nv_bfloat162*)(g_ckvl+p)   = {__float2bfloat16(acc.x-__bfloat162float(h0)),
                                          __float2bfloat16(acc.y-__bfloat162float(h1))};
        *(__nv_bfloat162*)(g_ckvl+p+2) = {__float2bfloat16(acc.z-__bfloat162float(h2)),
                                          __float2bfloat16(acc.w-__bfloat162float(h3))};
        acc.x += v.x; acc.y += v.y; acc.z += v.z; acc.w += v.w;
    }
}
__global__ void prefix_ks_k()
{
    size_t e = ((size_t)blockIdx.x*256 + threadIdx.x)*4;
    size_t bh = e / PMc;
    size_t rem = e % PMc;
    float4 acc = make_float4(0.f,0.f,0.f,0.f);
    #pragma unroll
    for (int c = 0; c < NCc; c++) {
        size_t p = (bh*NCc + c)*(size_t)PMc + rem;
        float4 v = *(const float4*)(g_ks + p);
        *(float4*)(g_ks + p) = acc;
        acc.x += v.x; acc.y += v.y; acc.z += v.z; acc.w += v.w;
    }
}

// ---------------- scores (HMMA): S = qf kf^T, mask, rowsum, intra = S v -----
__global__ __launch_bounds__(256, 1) void scores_mma_k()
{
    extern __shared__ char sm[];
    __shared__ float rowsum[128];
    u32 sb = smem_u32(sm);
    int bhc = blockIdx.x;
    int bh = bhc >> 5, c = bhc & 31;
    int tid = threadIdx.x, lane = tid & 31, warp = tid >> 5;
    int wm = warp >> 1, wn = warp & 1;
    if (tid < 128) rowsum[tid] = 0.f;

    const __nv_bfloat16* qh = g_qfh + (size_t)bhc*CHc*PMc;
    const __nv_bfloat16* ql = g_qfl + (size_t)bhc*CHc*PMc;
    const __nv_bfloat16* kh = g_kfh + (size_t)bhc*CHc*PMc;
    const __nv_bfloat16* kl = g_kfl + (size_t)bhc*CHc*PMc;

    int r0 = (tid*2) >> 2, s0 = (tid*2) & 3;
    int r1 = (tid*2+1) >> 2, s1 = (tid*2+1) & 3;
    int lr = lane & 7;
    int a_row = lr + (((lane >> 3) & 1) << 3);
    int a_col = ((lane >> 4) & 1) << 3;
    int b_row = lr + (((lane >> 4) & 1) << 3);
    int b_col = ((lane >> 3) & 1) << 3;

    float acc[2][8][4];
    #pragma unroll
    for (int i = 0; i < 2; i++)
        #pragma unroll
        for (int j = 0; j < 8; j++)
            #pragma unroll
            for (int q = 0; q < 4; q++) acc[i][j][q] = 0.f;

    auto load_chunk = [&](int ch, int stage) {
        int k0 = ch * 32;
        u32 st = sb + stage * 40960;
        u32 d0 = st + r0*80 + s0*16;
        u32 d1 = st + r1*80 + s1*16;
        CP_ASYNC16(d0,         qh + (size_t)r0*PMc + k0 + s0*8);
        CP_ASYNC16(d1,         qh + (size_t)r1*PMc + k0 + s1*8);
        CP_ASYNC16(d0 + 10240, ql + (size_t)r0*PMc + k0 + s0*8);
        CP_ASYNC16(d1 + 10240, ql + (size_t)r1*PMc + k0 + s1*8);
        CP_ASYNC16(d0 + 20480, kh + (size_t)r0*PMc + k0 + s0*8);
        CP_ASYNC16(d1 + 20480, kh + (size_t)r1*PMc + k0 + s1*8);
        CP_ASYNC16(d0 + 30720, kl + (size_t)r0*PMc + k0 + s0*8);
        CP_ASYNC16(d1 + 30720, kl + (size_t)r1*PMc + k0 + s1*8);
        CP_COMMIT();
    };

    load_chunk(0, 0);
    for (int ch = 0; ch < 16; ch++) {
        int stage = ch & 1;
        if (ch + 1 < 16) { load_chunk(ch + 1, stage ^ 1); CP_WAIT1(); }
        else             { CP_WAIT0(); }
        __syncthreads();
        u32 st = sb + stage * 40960;
        #pragma unroll
        for (int ks = 0; ks < 2; ks++) {
            u32 afh[2][4], afl[2][4], bfh[4][4], bfl[4][4];
            #pragma unroll
            for (int mi = 0; mi < 2; mi++) {
                u32 addr = st + ((wm*32 + mi*16 + a_row)*40 + ks*16 + a_col)*2;
                ldsm4(afh[mi][0], afh[mi][1], afh[mi][2], afh[mi][3], addr);
                ldsm4(afl[mi][0], afl[mi][1], afl[mi][2], afl[mi][3], addr + 10240);
            }
            #pragma unroll
            for (int nj = 0; nj < 4; nj++) {
                u32 addr = st + 20480 + ((wn*64 + nj*16 + b_row)*40 + ks*16 + b_col)*2;
                ldsm4(bfh[nj][0], bfh[nj][1], bfh[nj][2], bfh[nj][3], addr);
                ldsm4(bfl[nj][0], bfl[nj][1], bfl[nj][2], bfl[nj][3], addr + 10240);
            }
            #pragma unroll
            for (int mi = 0; mi < 2; mi++) {
                #pragma unroll
                for (int ni = 0; ni < 8; ni++) {
                    int nj = ni >> 1, off = (ni & 1) << 1;
                    mma16816(acc[mi][ni], afh[mi], bfh[nj][off], bfh[nj][off+1]);
                    mma16816(acc[mi][ni], afh[mi], bfl[nj][off], bfl[nj][off+1]);
                    mma16816(acc[mi][ni], afl[mi], bfh[nj][off], bfh[nj][off+1]);
                }
            }
        }
        __syncthreads();
    }

    #pragma unroll
    for (int mi = 0; mi < 2; mi++) {
        float rs0 = 0.f, rs1 = 0.f;
        int ri0 = wm*32 + mi*16 + (lane >> 2);
        #pragma unroll
        for (int ni = 0; ni < 8; ni++) {
            int cj = wn*64 + ni*8 + (lane & 3)*2;
            float v00 = (cj   <= ri0)   ? acc[mi][ni][0] : 0.f;
            float v01 = (cj+1 <= ri0)   ? acc[mi][ni][1] : 0.f;
            float v10 = (cj   <= ri0+8) ? acc[mi][ni][2] : 0.f;
            float v11 = (cj+1 <= ri0+8) ? acc[mi][ni][3] : 0.f;
            rs0 += v00 + v01; rs1 += v10 + v11;
            __nv_bfloat16 h00=__float2bfloat16(v00), h01=__float2bfloat16(v01);
            __nv_bfloat16 h10=__float2bfloat16(v10), h11=__float2bfloat16(v11);
            u32 o0 = ri0*272 + cj*2, o1 = (ri0+8)*272 + cj*2;
            *(__nv_bfloat162*)(sm + o0)         = {h00,h01};
            *(__nv_bfloat162*)(sm + o1)         = {h10,h11};
            *(__nv_bfloat162*)(sm + 34816 + o0) = {__float2bfloat16(v00-__bfloat162float(h00)),
                                                   __float2bfloat16(v01-__bfloat162float(h01))};
            *(__nv_bfloat162*)(sm + 34816 + o1) = {__float2bfloat16(v10-__bfloat162float(h10)),
                                                   __float2bfloat16(v11-__bfloat162float(h11))};
        }
        rs0 += __shfl_xor_sync(0xffffffffu, rs0, 1);
        rs0 += __shfl_xor_sync(0xffffffffu, rs0, 2);
        rs1 += __shfl_xor_sync(0xffffffffu, rs1, 1);
        rs1 += __shfl_xor_sync(0xffffffffu, rs1, 2);
        if ((lane & 3) == 0) {
            atomicAdd(&rowsum[ri0], rs0);
            atomicAdd(&rowsum[ri0+8], rs1);
        }
    }
    // v -> bf16 hi/lo smem (directly from g_qkv)
    const float* vb = g_qkv + ((size_t)((bh>>4)*Tc + c*CHc))*(3*Ec) + 2*Ec + (bh&15)*64;
    #pragma unroll
    for (int l = 0; l < 8; l++) {
        int idx = tid + l*256;
        int i = idx >> 4, dd = (idx & 15)*4;
        float4 v = *(const float4*)(vb + (size_t)i*(3*Ec) + dd);
        __nv_bfloat16 h0=__float2bfloat16(v.x), h1=__float2bfloat16(v.y);
        __nv_bfloat16 h2=__float2bfloat16(v.z), h3=__float2bfloat16(v.w);
        u32 off = 69632 + i*144 + dd*2;
        *(__nv_bfloat162*)(sm + off)     = {h0,h1};
        *(__nv_bfloat162*)(sm + off + 4) = {h2,h3};
        *(__nv_bfloat162*)(sm + off + (88064-69632))     = {__float2bfloat16(v.x-__bfloat162float(h0)),
                                                            __float2bfloat16(v.y-__bfloat162float(h1))};
        *(__nv_bfloat162*)(sm + off + (88064-69632) + 4) = {__float2bfloat16(v.z-__bfloat162float(h2)),
                                                            __float2bfloat16(v.w-__bfloat162float(h3))};
    }
    __syncthreads();
    if (tid < 128) g_nrm[(size_t)bh*Tc + c*CHc + tid] = rowsum[tid];

    int t_row = (lane & 7) + (((lane >> 4) & 1) << 3);
    int t_colbit = ((lane >> 3) & 1) << 3;
    float acc2[2][4][4];
    #pragma unroll
    for (int i = 0; i < 2; i++)
        #pragma unroll
        for (int j = 0; j < 4; j++)
            #pragma unroll
            for (int q = 0; q < 4; q++) acc2[i][j][q] = 0.f;

    #pragma unroll
    for (int ks16 = 0; ks16 < 8; ks16++) {
        u32 ah2[2][4], al2[2][4], bvh[2][4], bvl[2][4];
        #pragma unroll
        for (int mi = 0; mi < 2; mi++) {
            u32 addr = sb + ((wm*32 + mi*16 + a_row)*136 + ks16*16 + a_col)*2;
            ldsm4(ah2[mi][0], ah2[mi][1], ah2[mi][2], ah2[mi][3], addr);
            ldsm4(al2[mi][0], al2[mi][1], al2[mi][2], al2[mi][3], addr + 34816);
        }
        int krow = ks16*16 + t_row;
        #pragma unroll
        for (int nj = 0; nj < 2; nj++) {
            int dc = wn*32 + nj*16 + t_colbit;
            u32 addr = sb + 69632 + krow*144 + dc*2;
            ldsm4t(bvh[nj][0], bvh[nj][1], bvh[nj][2], bvh[nj][3], addr);
            ldsm4t(bvl[nj][0], bvl[nj][1], bvl[nj][2], bvl[nj][3], addr + (88064-69632));
        }
        #pragma unroll
        for (int mi = 0; mi < 2; mi++) {
            #pragma unroll
            for (int ng = 0; ng < 4; ng++) {
                int nj = ng >> 1, sel = ng & 1;
                mma16816(acc2[mi][ng], ah2[mi], bvh[nj][sel], bvh[nj][2+sel]);
                mma16816(acc2[mi][ng], ah2[mi], bvl[nj][sel], bvl[nj][2+sel]);
                mma16816(acc2[mi][ng], al2[mi], bvh[nj][sel], bvh[nj][2+sel]);
            }
        }
    }
    float* ob = g_o + ((size_t)bh*Tc + c*CHc)*Dc;
    #pragma unroll
    for (int mi = 0; mi < 2; mi++) {
        #pragma unroll
        for (int ng = 0; ng < 4; ng++) {
            int tok = wm*32 + mi*16 + (lane >> 2);
            int d = wn*32 + ng*8 + (lane & 3)*2;
            *(float2*)(ob + (size_t)tok*64 + d)     = make_float2(acc2[mi][ng][0], acc2[mi][ng][1]);
            *(float2*)(ob + (size_t)(tok+8)*64 + d) = make_float2(acc2[mi][ng][2], acc2[mi][ng][3]);
        }
    }
}

// ---------------- hist (HMMA): ctx = qf @ kv_state^T, + nrm finalize --------
__global__ __launch_bounds__(256, 1) void hist_mma_k()
{
    extern __shared__ char sm[];
    __shared__ float ks_sm[512];
    __shared__ float nrm_sm[128];
    u32 sb = smem_u32(sm);
    int bhc = blockIdx.x;
    int bh = bhc >> 5, c = bhc & 31;
    int tid = threadIdx.x, lane = tid & 31, warp = tid >> 5;
    int wm = warp >> 1, wn = warp & 1;

    const __nv_bfloat16* qh = g_qfh + (size_t)bhc*CHc*PMc;
    const __nv_bfloat16* ql = g_qfl + (size_t)bhc*CHc*PMc;
    const __nv_bfloat16* kvh = g_ckvh + (size_t)bhc*PMc*Dc;
    const __nv_bfloat16* kvl = g_ckvl + (size_t)bhc*PMc*Dc;
    const float* ksb = g_ks + (size_t)bhc*PMc;
    ks_sm[tid] = ksb[tid];
    ks_sm[tid+256] = ksb[tid+256];

    int r0 = (tid*2) >> 2, s0 = (tid*2) & 3;
    int r1 = (tid*2+1) >> 2, s1 = (tid*2+1) & 3;
    int kvr = tid >> 3, kvs = tid & 7;
    int lr = lane & 7;
    int a_row = lr + (((lane >> 3) & 1) << 3);
    int a_col = ((lane >> 4) & 1) << 3;
    int t_row = lr + (((lane >> 4) & 1) << 3);
    int t_colbit = ((lane >> 3) & 1) << 3;

    float acc[2][4][4];
    #pragma unroll
    for (int i = 0; i < 2; i++)
        #pragma unroll
        for (int j = 0; j < 4; j++)
            #pragma unroll
            for (int q = 0; q < 4; q++) acc[i][j][q] = 0.f;
    float nacc = 0.f;

    auto load_chunk = [&](int ch, int stage) {
        int k0 = ch * 32;
        u32 st = sb + stage * 29696;
        u32 d0 = st + r0*80 + s0*16;
        u32 d1 = st + r1*80 + s1*16;
        CP_ASYNC16(d0,         qh + (size_t)r0*PMc + k0 + s0*8);
        CP_ASYNC16(d1,         qh + (size_t)r1*PMc + k0 + s1*8);
        CP_ASYNC16(d0 + 10240, ql + (size_t)r0*PMc + k0 + s0*8);
        CP_ASYNC16(d1 + 10240, ql + (size_t)r1*PMc + k0 + s1*8);
        u32 dk = st + 20480 + kvr*144 + kvs*16;
        CP_ASYNC16(dk,        kvh + (size_t)(k0+kvr)*64 + kvs*8);
        CP_ASYNC16(dk + 4608, kvl + (size_t)(k0+kvr)*64 + kvs*8);
        CP_COMMIT();
    };

    load_chunk(0, 0);
    for (int ch = 0; ch < 16; ch++) {
        int stage = ch & 1;
        if (ch + 1 < 16) { load_chunk(ch + 1, stage ^ 1); CP_WAIT1(); }
        else             { CP_WAIT0(); }
        __syncthreads();
        u32 st = sb + stage * 29696;
        #pragma unroll
        for (int ks16 = 0; ks16 < 2; ks16++) {
            u32 afh[2][4], afl[2][4], bvh[2][4], bvl[2][4];
            #pragma unroll
            for (int mi = 0; mi < 2; mi++) {
                u32 addr = st + ((wm*32 + mi*16 + a_row)*40 + ks16*16 + a_col)*2;
                ldsm4(afh[mi][0], afh[mi][1], afh[mi][2], afh[mi][3], addr);
                ldsm4(afl[mi][0], afl[mi][1], afl[mi][2], afl[mi][3], addr + 10240);
            }
            int krow = ks16*16 + t_row;
            #pragma unroll
            for (int nj = 0; nj < 2; nj++) {
                int dc = wn*32 + nj*16 + t_colbit;
                u32 addr = st + 20480 + krow*144 + dc*2;
                ldsm4t(bvh[nj][0], bvh[nj][1], bvh[nj][2], bvh[nj][3], addr);
                ldsm4t(bvl[nj][0], bvl[nj][1], bvl[nj][2], bvl[nj][3], addr + 4608);
            }
            #pragma unroll
            for (int mi = 0; mi < 2; mi++) {
                #pragma unroll
                for (int ng = 0; ng < 4; ng++) {
                    int nj = ng >> 1, sel = ng & 1;
                    mma16816(acc[mi][ng], afh[mi], bvh[nj][sel], bvh[nj][2+sel]);
                    mma16816(acc[mi][ng], afh[mi], bvl[nj][sel], bvl[nj][2+sel]);
                    mma16816(acc[mi][ng], afl[mi], bvh[nj][sel], bvh[nj][2+sel]);
                }
            }
        }
        {
            int tt = tid >> 1, fh = (tid & 1)*16;
            const __nv_bfloat16* qhs = (const __nv_bfloat16*)(sm + stage*29696 + tt*80);
            const __nv_bfloat16* qls = (const __nv_bfloat16*)(sm + stage*29696 + 10240 + tt*80);
            #pragma unroll
            for (int f = 0; f < 16; f++) {
                int fl = fh + f;
                float qv = __bfloat162float(qhs[fl]) + __bfloat162float(qls[fl]);
                nacc += qv * ks_sm[ch*32 + fl];
            }
        }
        __syncthreads();
    }
    nacc += __shfl_xor_sync(0xffffffffu, nacc, 1);
    if ((tid & 1) == 0) nrm_sm[tid >> 1] = nacc;
    __syncthreads();
    if (tid < 128) {
        float tot = nrm_sm[tid] + g_nrm[(size_t)bh*Tc + c*CHc + tid] + 1e-6f;
        nrm_sm[tid] = 1.f / tot;
    }
    __syncthreads();

    float* ob = g_o + ((size_t)bh*Tc + c*CHc)*Dc;
    #pragma unroll
    for (int mi = 0; mi < 2; mi++) {
        #pragma unroll
        for (int ng = 0; ng < 4; ng++) {
            int tok = wm*32 + mi*16 + (lane >> 2);
            int d = wn*32 + ng*8 + (lane & 3)*2;
            float inv0 = nrm_sm[tok], inv1 = nrm_sm[tok+8];
            float2* p0 = (float2*)(ob + (size_t)tok*64 + d);
            float2* p1 = (float2*)(ob + (size_t)(tok+8)*64 + d);
            float2 c0 = *p0, c1 = *p1;
            c0.x = (c0.x + acc[mi][ng][0]) * inv0;
            c0.y = (c0.y + acc[mi][ng][1]) * inv0;
            c1.x = (c1.x + acc[mi][ng][2]) * inv1;
            c1.y = (c1.y + acc[mi][ng][3]) * inv1;
            *p0 = c0; *p1 = c1;
        }
    }
}

// ---------------- host launcher ---------------------------------------------
extern "C" void kernel_launch(void* const* d_in, const int* in_sizes, int n_in,
                              void* d_out, int out_size)
{
    const float* x        = (const float*)d_in[0];
    const float* qkv_w    = (const float*)d_in[1];
    const float* qkv_b    = (const float*)d_in[2];
    const float* out_w    = (const float*)d_in[3];
    const float* out_b    = (const float*)d_in[4];
    const float* omega    = (const float*)d_in[5];
    const float* poly_w   = (const float*)d_in[6];
    const float* qnodes   = (const float*)d_in[7];
    const float* qweights = (const float*)d_in[8];
    float* out = (float*)d_out;

    float* qkv_ptr = 0;
    cudaGetSymbolAddress((void**)&qkv_ptr, g_qkv);
    __nv_bfloat16 *ah, *al, *wh, *wl;
    cudaGetSymbolAddress((void**)&ah, g_ah);
    cudaGetSymbolAddress((void**)&al, g_al);
    cudaGetSymbolAddress((void**)&wh, g_wh);
    cudaGetSymbolAddress((void**)&wl, g_wl);

    cudaFuncSetAttribute(gemm_mma_k, cudaFuncAttributeMaxDynamicSharedMemorySize, 2*S_STAGE);
    cudaFuncSetAttribute(passA_mma_k, cudaFuncAttributeMaxDynamicSharedMemorySize, 106496);
    cudaFuncSetAttribute(scores_mma_k, cudaFuncAttributeMaxDynamicSharedMemorySize, 106496);
    cudaFuncSetAttribute(hist_mma_k, cudaFuncAttributeMaxDynamicSharedMemorySize, 59392);

    // 1) split operands to bf16 hi/lo
    split_bf16_k<<<(Bc*Tc*Ec)/1024, 256>>>(x, ah, al);
    split_bf16_k<<<(3*Ec*Ec)/1024, 256>>>(qkv_w, wh, wl);
    // 2) QKV GEMM (HMMA)
    gemm_mma_k<<<dim3(3*Ec/128, (Bc*Tc)/128), 256, 2*S_STAGE>>>(
        ah, al, wh, wl, qkv_b, qkv_ptr, 3*Ec);
    // 3) feature maps (reads g_qkv directly, l2norm fused)
    features_k<<<dim3(BHc*NCc, 2), 256>>>(omega, poly_w, qnodes, qweights);
    // 4) per-chunk kv + ks (HMMA, v from g_qkv)
    passA_mma_k<<<dim3(BHc*NCc, 4), 256, 106496>>>();
    // 5) fused exclusive prefix + bf16 convert
    prefix_kv_cvt_k<<<(BHc*PMc*Dc)/1024, 256>>>();
    prefix_ks_k<<<(BHc*PMc)/1024, 256>>>();
    // 6) intra-chunk scores + intra context (HMMA)
    scores_mma_k<<<BHc*NCc, 256, 106496>>>();
    // 7) history context + normalize (HMMA)
    hist_mma_k<<<BHc*NCc, 256, 59392>>>();
    // 8) output projection (HMMA)
    o2rows_k<<<(BHc*Tc*Dc)/512, 256>>>();
    split_bf16_k<<<(Ec*Ec)/1024, 256>>>(out_w, wh, wl);
    gemm_mma_k<<<dim3(Ec/128, (Bc*Tc)/128), 256, 2*S_STAGE>>>(
        ah, al, wh, wl, out_b, out, Ec);
}

// round 7
// speedup vs baseline: 2.3465x; 1.0158x over previous
#include <cuda_runtime.h>
#include <cuda_bf16.h>
#include <math.h>

#define Bc 2
#define Tc 4096
#define Ec 1024
#define Hc 16
#define Dc 64
#define Pc 64
#define PMc 512
#define CHc 128
#define NCc 32
#define BHc 32

typedef unsigned long long u64;
typedef unsigned int u32;

// ---------------- scratch (device globals; no allocations allowed) ----------
__device__ float g_qkv[(size_t)Bc*Tc*3*Ec];
__device__ float g_ckv[(size_t)BHc*NCc*PMc*Dc];      // (bhc, f, d) fp32 per-chunk
__device__ float g_ks [(size_t)BHc*NCc*PMc];
__device__ float g_o  [(size_t)BHc*Tc*Dc];
__device__ float g_nrm[(size_t)BHc*Tc];
// bf16 hi/lo features, [bhc][token 128][feature 512]
__device__ __align__(16) __nv_bfloat16 g_qfh[(size_t)BHc*NCc*CHc*PMc];
__device__ __align__(16) __nv_bfloat16 g_qfl[(size_t)BHc*NCc*CHc*PMc];
__device__ __align__(16) __nv_bfloat16 g_kfh[(size_t)BHc*NCc*CHc*PMc];
__device__ __align__(16) __nv_bfloat16 g_kfl[(size_t)BHc*NCc*CHc*PMc];
// bf16 hi/lo exclusive kv state, [bhc][f][d]
__device__ __align__(16) __nv_bfloat16 g_ckvh[(size_t)BHc*NCc*PMc*Dc];
__device__ __align__(16) __nv_bfloat16 g_ckvl[(size_t)BHc*NCc*PMc*Dc];
// bf16 split operands for dense GEMMs
__device__ __align__(16) __nv_bfloat16 g_ah[(size_t)Bc*Tc*Ec];
__device__ __align__(16) __nv_bfloat16 g_al[(size_t)Bc*Tc*Ec];
__device__ __align__(16) __nv_bfloat16 g_wh[(size_t)3*Ec*Ec];
__device__ __align__(16) __nv_bfloat16 g_wl[(size_t)3*Ec*Ec];

// ================= helpers ===================================================
__device__ __forceinline__ u32 smem_u32(const void* p) {
    u32 a; asm("{ .reg .u64 t; cvta.to.shared.u64 t, %1; cvt.u32.u64 %0, t; }"
               : "=r"(a) : "l"(p));
    return a;
}
#define CP_ASYNC16(dst, src) \
    asm volatile("cp.async.cg.shared.global [%0], [%1], 16;\n" :: "r"(dst), "l"(src))
#define CP_COMMIT() asm volatile("cp.async.commit_group;\n" ::: "memory")
#define CP_WAIT1()  asm volatile("cp.async.wait_group 1;\n" ::: "memory")
#define CP_WAIT0()  asm volatile("cp.async.wait_group 0;\n" ::: "memory")

__device__ __forceinline__ void ldsm4(u32 &r0, u32 &r1, u32 &r2, u32 &r3, u32 a) {
    asm volatile("ldmatrix.sync.aligned.m8n8.x4.shared.b16 {%0,%1,%2,%3}, [%4];\n"
                 : "=r"(r0), "=r"(r1), "=r"(r2), "=r"(r3) : "r"(a));
}
__device__ __forceinline__ void ldsm4t(u32 &r0, u32 &r1, u32 &r2, u32 &r3, u32 a) {
    asm volatile("ldmatrix.sync.aligned.m8n8.x4.trans.shared.b16 {%0,%1,%2,%3}, [%4];\n"
                 : "=r"(r0), "=r"(r1), "=r"(r2), "=r"(r3) : "r"(a));
}
__device__ __forceinline__ void mma16816(float* c, const u32* a, u32 b0, u32 b1) {
    asm volatile(
        "mma.sync.aligned.m16n8k16.row.col.f32.bf16.bf16.f32 "
        "{%0,%1,%2,%3},{%4,%5,%6,%7},{%8,%9},{%0,%1,%2,%3};\n"
        : "+f"(c[0]), "+f"(c[1]), "+f"(c[2]), "+f"(c[3])
        : "r"(a[0]), "r"(a[1]), "r"(a[2]), "r"(a[3]), "r"(b0), "r"(b1));
}

// ================= fp32 -> bf16 hi/lo split ==================================
__global__ void split_bf16_k(const float* __restrict__ s,
                             __nv_bfloat16* __restrict__ h,
                             __nv_bfloat16* __restrict__ l)
{
    size_t i = ((size_t)blockIdx.x*256 + threadIdx.x)*4;
    float4 v = *(const float4*)(s + i);
    __nv_bfloat16 h0=__float2bfloat16(v.x), h1=__float2bfloat16(v.y);
    __nv_bfloat16 h2=__float2bfloat16(v.z), h3=__float2bfloat16(v.w);
    __nv_bfloat162 ha = {h0,h1}, hb = {h2,h3};
    __nv_bfloat162 la = {__float2bfloat16(v.x-__bfloat162float(h0)),
                         __float2bfloat16(v.y-__bfloat162float(h1))};
    __nv_bfloat162 lb = {__float2bfloat16(v.z-__bfloat162float(h2)),
                         __float2bfloat16(v.w-__bfloat162float(h3))};
    *(__nv_bfloat162*)(h+i) = ha; *(__nv_bfloat162*)(h+i+2) = hb;
    *(__nv_bfloat162*)(l+i) = la; *(__nv_bfloat162*)(l+i+2) = lb;
}

// ------ reshape g_o (B,H,T,D) -> rows (b*T+t, h*64+d), bf16 hi/lo ------------
__global__ void o2rows_k()
{
    size_t gidx = ((size_t)blockIdx.x*256 + threadIdx.x)*2;
    float2 v = *(const float2*)(g_o + gidx);
    int d = (int)(gidx & 63), t = (int)((gidx >> 6) & 4095);
    int h = (int)((gidx >> 18) & 15), b = (int)(gidx >> 22);
    size_t dst = ((size_t)(b*Tc + t))*Ec + h*64 + d;
    __nv_bfloat16 h0=__float2bfloat16(v.x), h1=__float2bfloat16(v.y);
    *(__nv_bfloat162*)(g_ah+dst) = {h0,h1};
    *(__nv_bfloat162*)(g_al+dst) = {__float2bfloat16(v.x-__bfloat162float(h0)),
                                    __float2bfloat16(v.y-__bfloat162float(h1))};
}

// ================= HMMA GEMM: C[M,N] = A @ W^T + bias (bf16x3 split) ========
#define S_STRIDE 40
#define S_ARR 10240
#define S_STAGE 40960

__global__ __launch_bounds__(256, 1)
void gemm_mma_k(const __nv_bfloat16* __restrict__ Abase_h,
                const __nv_bfloat16* __restrict__ Abase_l,
                const __nv_bfloat16* __restrict__ Wbase_h,
                const __nv_bfloat16* __restrict__ Wbase_l,
                const float* __restrict__ bias, float* __restrict__ C, int N)
{
    extern __shared__ char smem[];
    u32 sb = smem_u32(smem);
    const int K = 1024;
    int tid = threadIdx.x;
    int lane = tid & 31, warp = tid >> 5;
    int wm = warp >> 1, wn = warp & 1;
    int bm = blockIdx.y * 128, bn = blockIdx.x * 128;

    const __nv_bfloat16* Ah = Abase_h + (size_t)bm * K;
    const __nv_bfloat16* Al = Abase_l + (size_t)bm * K;
    const __nv_bfloat16* Wh = Wbase_h + (size_t)bn * K;
    const __nv_bfloat16* Wl = Wbase_l + (size_t)bn * K;

    int r0 = (tid*2) >> 2, s0 = (tid*2) & 3;
    int r1 = (tid*2+1) >> 2, s1 = (tid*2+1) & 3;

    int lr = lane & 7;
    int a_row = lr + (((lane >> 3) & 1) << 3);
    int a_col = ((lane >> 4) & 1) << 3;
    int b_row = lr + (((lane >> 4) & 1) << 3);
    int b_col = ((lane >> 3) & 1) << 3;

    float acc[2][8][4];
    #pragma unroll
    for (int i = 0; i < 2; i++)
        #pragma unroll
        for (int j = 0; j < 8; j++)
            #pragma unroll
            for (int q = 0; q < 4; q++) acc[i][j][q] = 0.f;

    auto load_chunk = [&](int ch, int stage) {
        int k0 = ch * 32;
        u32 st = sb + stage * S_STAGE;
        u32 d0 = st + r0*80 + s0*16;
        u32 d1 = st + r1*80 + s1*16;
        CP_ASYNC16(d0, Ah + (size_t)r0*K + k0 + s0*8);
        CP_ASYNC16(d1, Ah + (size_t)r1*K + k0 + s1*8);
        CP_ASYNC16(d0 + S_ARR, Al + (size_t)r0*K + k0 + s0*8);
        CP_ASYNC16(d1 + S_ARR, Al + (size_t)r1*K + k0 + s1*8);
        CP_ASYNC16(d0 + 2*S_ARR, Wh + (size_t)r0*K + k0 + s0*8);
        CP_ASYNC16(d1 + 2*S_ARR, Wh + (size_t)r1*K + k0 + s1*8);
        CP_ASYNC16(d0 + 3*S_ARR, Wl + (size_t)r0*K + k0 + s0*8);
        CP_ASYNC16(d1 + 3*S_ARR, Wl + (size_t)r1*K + k0 + s1*8);
        CP_COMMIT();
    };

    load_chunk(0, 0);

    for (int ch = 0; ch < 32; ch++) {
        int stage = ch & 1;
        if (ch + 1 < 32) { load_chunk(ch + 1, stage ^ 1); CP_WAIT1(); }
        else             { CP_WAIT0(); }
        __syncthreads();

        u32 st = sb + stage * S_STAGE;
        #pragma unroll
        for (int ks = 0; ks < 2; ks++) {
            u32 afh[2][4], afl[2][4], bfh[4][4], bfl[4][4];
            #pragma unroll
            for (int mi = 0; mi < 2; mi++) {
                u32 addr = st + ((wm*32 + mi*16 + a_row)*S_STRIDE + ks*16 + a_col)*2;
                ldsm4(afh[mi][0], afh[mi][1], afh[mi][2], afh[mi][3], addr);
                ldsm4(afl[mi][0], afl[mi][1], afl[mi][2], afl[mi][3], addr + S_ARR);
            }
            #pragma unroll
            for (int nj = 0; nj < 4; nj++) {
                u32 addr = st + 2*S_ARR +
                           ((wn*64 + nj*16 + b_row)*S_STRIDE + ks*16 + b_col)*2;
                ldsm4(bfh[nj][0], bfh[nj][1], bfh[nj][2], bfh[nj][3], addr);
                ldsm4(bfl[nj][0], bfl[nj][1], bfl[nj][2], bfl[nj][3], addr + S_ARR);
            }
            #pragma unroll
            for (int mi = 0; mi < 2; mi++) {
                #pragma unroll
                for (int ni = 0; ni < 8; ni++) {
                    int nj = ni >> 1, off = (ni & 1) << 1;
                    mma16816(acc[mi][ni], afh[mi], bfh[nj][off], bfh[nj][off+1]);
                    mma16816(acc[mi][ni], afh[mi], bfl[nj][off], bfl[nj][off+1]);
                    mma16816(acc[mi][ni], afl[mi], bfh[nj][off], bfh[nj][off+1]);
                }
            }
        }
        __syncthreads();
    }

    #pragma unroll
    for (int mi = 0; mi < 2; mi++) {
        #pragma unroll
        for (int ni = 0; ni < 8; ni++) {
            int m = bm + wm*32 + mi*16 + (lane >> 2);
            int n = bn + wn*64 + ni*8 + (lane & 3)*2;
            float2 o0, o1;
            o0.x = acc[mi][ni][0] + bias[n];
            o0.y = acc[mi][ni][1] + bias[n+1];
            o1.x = acc[mi][ni][2] + bias[n];
            o1.y = acc[mi][ni][3] + bias[n+1];
            *(float2*)(C + (size_t)m*N + n)     = o0;
            *(float2*)(C + (size_t)(m+8)*N + n) = o1;
        }
    }
}

// ---------------- feature map -> bf16 hi/lo [token][feature] ----------------
// v2: float4 loads, [token][68] smem layout, lean epilogue, 3 CTAs/SM
__global__ __launch_bounds__(256, 3) void features_k(
    const float* __restrict__ omega, const float* __restrict__ poly_w,
    const float* __restrict__ qnodes, const float* __restrict__ qweights)
{
    __shared__ float xs[128*68];       // [token][d], stride 68 (16B-aligned rows)
    __shared__ float om[512];
    __shared__ float prf[128*8];
    __shared__ float rn[128];
    int bhc = blockIdx.x;
    int isK = blockIdx.y;
    int bh = bhc >> 5, c = bhc & 31;
    int h = bh & 15, b = bh >> 4;
    const float* src = g_qkv + ((size_t)(b*Tc + c*CHc))*(3*Ec) + isK*Ec + h*64;
    __nv_bfloat16* dh = (isK ? g_kfh : g_qfh) + (size_t)bhc*CHc*PMc;
    __nv_bfloat16* dl = (isK ? g_kfl : g_qfl) + (size_t)bhc*CHc*PMc;
    int tid = threadIdx.x;
    #pragma unroll
    for (int l = 0; l < 8; l++) {
        int idx = tid + l*256;         // < 2048
        int i = idx >> 4, dd = (idx & 15) << 2;
        float4 v = *(const float4*)(src + (size_t)i*(3*Ec) + dd);
        *(float4*)&xs[i*68 + dd] = v;
    }
    om[tid]       = omega[h*512 + tid];
    om[tid + 256] = omega[h*512 + tid + 256];
    __syncthreads();
    if (tid < 128) {
        const float* xr = &xs[tid*68];
        float s = 0.f;
        #pragma unroll
        for (int d = 0; d < 64; d++) { float x = xr[d]; s += x*x; }
        rn[tid] = 1.f / fmaxf(sqrtf(s), 1e-12f);
    }
    __syncthreads();
    float s0 = qnodes[0];
    float sq2s = sqrtf(fmaxf(2.f*s0, 0.f));
    float wq = sqrtf(fmaxf(qweights[0], 0.f));
    float prescale = 0.3535533905932738f * wq;
    #pragma unroll
    for (int l = 0; l < 4; l++) {
        int pair = tid + l*256;
        int i = pair >> 3, m = pair & 7;
        const float* xr = &xs[i*68];
        float a = 0.f;
        #pragma unroll
        for (int d = 0; d < 64; d++) a += xr[d] * om[d*8 + m];
        float e = fminf(fmaxf(a * rn[i] * sq2s - s0, -20.f), 20.f);
        prf[i*8 + m] = expf(e) * prescale;
    }
    __syncthreads();
    int ti = (tid >> 4) << 3, tp = (tid & 15) << 2;
    float acc[8][4] = {};
    const float* pwp = poly_w + h*4096;
    for (int d = 0; d < 64; d++) {
        float a[8];
        #pragma unroll
        for (int x = 0; x < 8; x++) a[x] = xs[(ti+x)*68 + d];
        float4 bb = *(const float4*)(pwp + d*64 + tp);
        #pragma unroll
        for (int i2 = 0; i2 < 8; i2++) {
            acc[i2][0] += a[i2]*bb.x; acc[i2][1] += a[i2]*bb.y;
            acc[i2][2] += a[i2]*bb.z; acc[i2][3] += a[i2]*bb.w;
        }
    }
    #pragma unroll
    for (int i2 = 0; i2 < 8; i2++) {
        float r = rn[ti + i2];
        #pragma unroll
        for (int j = 0; j < 4; j++) {
            float t = acc[i2][j] * r;
            acc[i2][j] = t*t*0.125f;
        }
    }
    // epilogue: per (token, p) emit 8 consecutive features, store immediately
    #pragma unroll
    for (int i2 = 0; i2 < 8; i2++) {
        int tok = ti + i2;
        const float* pr = &prf[tok*8];
        #pragma unroll
        for (int j = 0; j < 4; j++) {
            float base = acc[i2][j];
            __nv_bfloat16 hb[8], lb[8];
            #pragma unroll
            for (int m = 0; m < 8; m++) {
                float v = base * pr[m];
                __nv_bfloat16 hh = __float2bfloat16(v);
                hb[m] = hh;
                lb[m] = __float2bfloat16(v - __bfloat162float(hh));
            }
            size_t off = (size_t)tok*PMc + (tp+j)*8;
            *(uint4*)(dh + off) = *(uint4*)hb;
            *(uint4*)(dl + off) = *(uint4*)lb;
        }
    }
}

// ---------------- pass A (HMMA): kv[f][d] = sum_i kf[i][f] v[i][d] ----------
__global__ __launch_bounds__(256, 1) void passA_mma_k()
{
    extern __shared__ char sm[];
    u32 sb = smem_u32(sm);
    const u32 KFH = 0, KFL = 34816, VH = 69632, VL = 88064;
    int bhc = blockIdx.x, fb = blockIdx.y;
    int bh = bhc >> 5, c = bhc & 31;
    int tid = threadIdx.x, lane = tid & 31, warp = tid >> 5;
    int wm = warp >> 1, wn = warp & 1;

    const __nv_bfloat16* kh = g_kfh + (size_t)bhc*CHc*PMc + fb*128;
    const __nv_bfloat16* kl = g_kfl + (size_t)bhc*CHc*PMc + fb*128;
    #pragma unroll
    for (int l = 0; l < 8; l++) {
        int idx = tid + l*256;
        int row = idx >> 4, seg = idx & 15;
        u32 d = sb + KFH + row*272 + seg*16;
        CP_ASYNC16(d,              kh + (size_t)row*PMc + seg*8);
        CP_ASYNC16(d + (KFL-KFH),  kl + (size_t)row*PMc + seg*8);
    }
    CP_COMMIT();
    const float* vb = g_qkv + ((size_t)((bh>>4)*Tc + c*CHc))*(3*Ec) + 2*Ec + (bh&15)*64;
    #pragma unroll
    for (int l = 0; l < 8; l++) {
        int idx = tid + l*256;
        int i = idx >> 4, dd = (idx & 15)*4;
        float4 v = *(const float4*)(vb + (size_t)i*(3*Ec) + dd);
        __nv_bfloat16 h0=__float2bfloat16(v.x), h1=__float2bfloat16(v.y);
        __nv_bfloat16 h2=__float2bfloat16(v.z), h3=__float2bfloat16(v.w);
        u32 off = i*144 + dd*2;
        *(__nv_bfloat162*)(sm + VH + off)     = {h0,h1};
        *(__nv_bfloat162*)(sm + VH + off + 4) = {h2,h3};
        *(__nv_bfloat162*)(sm + VL + off)     = {__float2bfloat16(v.x-__bfloat162float(h0)),
                                                 __float2bfloat16(v.y-__bfloat162float(h1))};
        *(__nv_bfloat162*)(sm + VL + off + 4) = {__float2bfloat16(v.z-__bfloat162float(h2)),
                                                 __float2bfloat16(v.w-__bfloat162float(h3))};
    }
    CP_WAIT0();
    __syncthreads();

    if (tid < 128) {
        float s = 0.f;
        for (int i = 0; i < 128; i++) {
            s += __bfloat162float(*(const __nv_bfloat16*)(sm + KFH + i*272 + tid*2));
            s += __bfloat162float(*(const __nv_bfloat16*)(sm + KFL + i*272 + tid*2));
        }
        g_ks[(size_t)bhc*PMc + fb*128 + tid] = s;
    }

    int t_row = (lane & 7) + (((lane >> 4) & 1) << 3);
    int t_colbit = ((lane >> 3) & 1) << 3;

    float acc[2][4][4];
    #pragma unroll
    for (int i = 0; i < 2; i++)
        #pragma unroll
        for (int j = 0; j < 4; j++)
            #pragma unroll
            for (int q = 0; q < 4; q++) acc[i][j][q] = 0.f;

    #pragma unroll
    for (int ks16 = 0; ks16 < 8; ks16++) {
        int krow = ks16*16 + t_row;
        u32 afh[2][4], afl[2][4], bvh[2][4], bvl[2][4];
        #pragma unroll
        for (int mi = 0; mi < 2; mi++) {
            int fc = wm*32 + mi*16 + t_colbit;
            u32 addr = sb + KFH + krow*272 + fc*2;
            ldsm4t(afh[mi][0], afh[mi][1], afh[mi][2], afh[mi][3], addr);
            ldsm4t(afl[mi][0], afl[mi][1], afl[mi][2], afl[mi][3], addr + (KFL-KFH));
        }
        #pragma unroll
        for (int nj = 0; nj < 2; nj++) {
            int dc = wn*32 + nj*16 + t_colbit;
            u32 addr = sb + VH + krow*144 + dc*2;
            ldsm4t(bvh[nj][0], bvh[nj][1], bvh[nj][2], bvh[nj][3], addr);
            ldsm4t(bvl[nj][0], bvl[nj][1], bvl[nj][2], bvl[nj][3], addr + (VL-VH));
        }
        #pragma unroll
        for (int mi = 0; mi < 2; mi++) {
            #pragma unroll
            for (int ng = 0; ng < 4; ng++) {
                int nj = ng >> 1, sel = ng & 1;
                mma16816(acc[mi][ng], afh[mi], bvh[nj][sel], bvh[nj][2+sel]);
                mma16816(acc[mi][ng], afh[mi], bvl[nj][sel], bvl[nj][2+sel]);
                mma16816(acc[mi][ng], afl[mi], bvh[nj][sel], bvh[nj][2+sel]);
            }
        }
    }
    float* outp = g_ckv + (size_t)bhc*PMc*Dc + (size_t)fb*128*Dc;
    #pragma unroll
    for (int mi = 0; mi < 2; mi++) {
        #pragma unroll
        for (int ng = 0; ng < 4; ng++) {
            int f = wm*32 + mi*16 + (lane >> 2);
            int d = wn*32 + ng*8 + (lane & 3)*2;
            *(float2*)(outp + (size_t)f*64 + d)     = make_float2(acc[mi][ng][0], acc[mi][ng][1]);
            *(float2*)(outp + (size_t)(f+8)*64 + d) = make_float2(acc[mi][ng][2], acc[mi][ng][3]);
        }
    }
}

// ------- fused exclusive prefix over chunks + bf16 hi/lo convert -------------
__global__ void prefix_kv_cvt_k()
{
    size_t e = ((size_t)blockIdx.x*256 + threadIdx.x)*4;
    size_t bh = e / (PMc*Dc);
    size_t rem = e % (PMc*Dc);
    float4 acc = make_float4(0.f,0.f,0.f,0.f);
    #pragma unroll
    for (int c = 0; c < NCc; c++) {
        size_t p = (bh*NCc + c)*(size_t)(PMc*Dc) + rem;
        float4 v = *(const float4*)(g_ckv + p);
        __nv_bfloat16 h0=__float2bfloat16(acc.x), h1=__float2bfloat16(acc.y);
        __nv_bfloat16 h2=__float2bfloat16(acc.z), h3=__float2bfloat16(acc.w);
        *(__nv_bfloat162*)(g_ckvh+p)   = {h0,h1};
        *(__nv_bfloat162*)(g_ckvh+p+2) = {h2,h3};
        *(__nv_bfloat162*)(g_ckvl+p)   = {__float2bfloat16(acc.x-__bfloat162float(h0)),
                                          __float2bfloat16(acc.y-__bfloat162float(h1))};
        *(__nv_bfloat162*)(g_ckvl+p+2) = {__float2bfloat16(acc.z-__bfloat162float(h2)),
                                          __float2bfloat16(acc.w-__bfloat162float(h3))};
        acc.x += v.x; acc.y += v.y; acc.z += v.z; acc.w += v.w;
    }
}
__global__ void prefix_ks_k()
{
    size_t e = ((size_t)blockIdx.x*256 + threadIdx.x)*4;
    size_t bh = e / PMc;
    size_t rem = e % PMc;
    float4 acc = make_float4(0.f,0.f,0.f,0.f);
    #pragma unroll
    for (int c = 0; c < NCc; c++) {
        size_t p = (bh*NCc + c)*(size_t)PMc + rem;
        float4 v = *(const float4*)(g_ks + p);
        *(float4*)(g_ks + p) = acc;
        acc.x += v.x; acc.y += v.y; acc.z += v.z; acc.w += v.w;
    }
}

// ---------------- scores (HMMA): S = qf kf^T, mask, rowsum, intra = S v -----
__global__ __launch_bounds__(256, 1) void scores_mma_k()
{
    extern __shared__ char sm[];
    __shared__ float rowsum[128];
    u32 sb = smem_u32(sm);
    int bhc = blockIdx.x;
    int bh = bhc >> 5, c = bhc & 31;
    int tid = threadIdx.x, lane = tid & 31, warp = tid >> 5;
    int wm = warp >> 1, wn = warp & 1;
    if (tid < 128) rowsum[tid] = 0.f;

    const __nv_bfloat16* qh = g_qfh + (size_t)bhc*CHc*PMc;
    const __nv_bfloat16* ql = g_qfl + (size_t)bhc*CHc*PMc;
    const __nv_bfloat16* kh = g_kfh + (size_t)bhc*CHc*PMc;
    const __nv_bfloat16* kl = g_kfl + (size_t)bhc*CHc*PMc;

    int r0 = (tid*2) >> 2, s0 = (tid*2) & 3;
    int r1 = (tid*2+1) >> 2, s1 = (tid*2+1) & 3;
    int lr = lane & 7;
    int a_row = lr + (((lane >> 3) & 1) << 3);
    int a_col = ((lane >> 4) & 1) << 3;
    int b_row = lr + (((lane >> 4) & 1) << 3);
    int b_col = ((lane >> 3) & 1) << 3;

    float acc[2][8][4];
    #pragma unroll
    for (int i = 0; i < 2; i++)
        #pragma unroll
        for (int j = 0; j < 8; j++)
            #pragma unroll
            for (int q = 0; q < 4; q++) acc[i][j][q] = 0.f;

    auto load_chunk = [&](int ch, int stage) {
        int k0 = ch * 32;
        u32 st = sb + stage * 40960;
        u32 d0 = st + r0*80 + s0*16;
        u32 d1 = st + r1*80 + s1*16;
        CP_ASYNC16(d0,         qh + (size_t)r0*PMc + k0 + s0*8);
        CP_ASYNC16(d1,         qh + (size_t)r1*PMc + k0 + s1*8);
        CP_ASYNC16(d0 + 10240, ql + (size_t)r0*PMc + k0 + s0*8);
        CP_ASYNC16(d1 + 10240, ql + (size_t)r1*PMc + k0 + s1*8);
        CP_ASYNC16(d0 + 20480, kh + (size_t)r0*PMc + k0 + s0*8);
        CP_ASYNC16(d1 + 20480, kh + (size_t)r1*PMc + k0 + s1*8);
        CP_ASYNC16(d0 + 30720, kl + (size_t)r0*PMc + k0 + s0*8);
        CP_ASYNC16(d1 + 30720, kl + (size_t)r1*PMc + k0 + s1*8);
        CP_COMMIT();
    };

    load_chunk(0, 0);
    for (int ch = 0; ch < 16; ch++) {
        int stage = ch & 1;
        if (ch + 1 < 16) { load_chunk(ch + 1, stage ^ 1); CP_WAIT1(); }
        else             { CP_WAIT0(); }
        __syncthreads();
        u32 st = sb + stage * 40960;
        #pragma unroll
        for (int ks = 0; ks < 2; ks++) {
            u32 afh[2][4], afl[2][4], bfh[4][4], bfl[4][4];
            #pragma unroll
            for (int mi = 0; mi < 2; mi++) {
                u32 addr = st + ((wm*32 + mi*16 + a_row)*40 + ks*16 + a_col)*2;
                ldsm4(afh[mi][0], afh[mi][1], afh[mi][2], afh[mi][3], addr);
                ldsm4(afl[mi][0], afl[mi][1], afl[mi][2], afl[mi][3], addr + 10240);
            }
            #pragma unroll
            for (int nj = 0; nj < 4; nj++) {
                u32 addr = st + 20480 + ((wn*64 + nj*16 + b_row)*40 + ks*16 + b_col)*2;
                ldsm4(bfh[nj][0], bfh[nj][1], bfh[nj][2], bfh[nj][3], addr);
                ldsm4(bfl[nj][0], bfl[nj][1], bfl[nj][2], bfl[nj][3], addr + 10240);
            }
            #pragma unroll
            for (int mi = 0; mi < 2; mi++) {
                #pragma unroll
                for (int ni = 0; ni < 8; ni++) {
                    int nj = ni >> 1, off = (ni & 1) << 1;
                    mma16816(acc[mi][ni], afh[mi], bfh[nj][off], bfh[nj][off+1]);
                    mma16816(acc[mi][ni], afh[mi], bfl[nj][off], bfl[nj][off+1]);
                    mma16816(acc[mi][ni], afl[mi], bfh[nj][off], bfh[nj][off+1]);
                }
            }
        }
        __syncthreads();
    }

    #pragma unroll
    for (int mi = 0; mi < 2; mi++) {
        float rs0 = 0.f, rs1 = 0.f;
        int ri0 = wm*32 + mi*16 + (lane >> 2);
        #pragma unroll
        for (int ni = 0; ni < 8; ni++) {
            int cj = wn*64 + ni*8 + (lane & 3)*2;
            float v00 = (cj   <= ri0)   ? acc[mi][ni][0] : 0.f;
            float v01 = (cj+1 <= ri0)   ? acc[mi][ni][1] : 0.f;
            float v10 = (cj   <= ri0+8) ? acc[mi][ni][2] : 0.f;
            float v11 = (cj+1 <= ri0+8) ? acc[mi][ni][3] : 0.f;
            rs0 += v00 + v01; rs1 += v10 + v11;
            __nv_bfloat16 h00=__float2bfloat16(v00), h01=__float2bfloat16(v01);
            __nv_bfloat16 h10=__float2bfloat16(v10), h11=__float2bfloat16(v11);
            u32 o0 = ri0*272 + cj*2, o1 = (ri0+8)*272 + cj*2;
            *(__nv_bfloat162*)(sm + o0)         = {h00,h01};
            *(__nv_bfloat162*)(sm + o1)         = {h10,h11};
            *(__nv_bfloat162*)(sm + 34816 + o0) = {__float2bfloat16(v00-__bfloat162float(h00)),
                                                   __float2bfloat16(v01-__bfloat162float(h01))};
            *(__nv_bfloat162*)(sm + 34816 + o1) = {__float2bfloat16(v10-__bfloat162float(h10)),
                                                   __float2bfloat16(v11-__bfloat162float(h11))};
        }
        rs0 += __shfl_xor_sync(0xffffffffu, rs0, 1);
        rs0 += __shfl_xor_sync(0xffffffffu, rs0, 2);
        rs1 += __shfl_xor_sync(0xffffffffu, rs1, 1);
        rs1 += __shfl_xor_sync(0xffffffffu, rs1, 2);
        if ((lane & 3) == 0) {
            atomicAdd(&rowsum[ri0], rs0);
            atomicAdd(&rowsum[ri0+8], rs1);
        }
    }
    const float* vb = g_qkv + ((size_t)((bh>>4)*Tc + c*CHc))*(3*Ec) + 2*Ec + (bh&15)*64;
    #pragma unroll
    for (int l = 0; l < 8; l++) {
        int idx = tid + l*256;
        int i = idx >> 4, dd = (idx & 15)*4;
        float4 v = *(const float4*)(vb + (size_t)i*(3*Ec) + dd);
        __nv_bfloat16 h0=__float2bfloat16(v.x), h1=__float2bfloat16(v.y);
        __nv_bfloat16 h2=__float2bfloat16(v.z), h3=__float2bfloat16(v.w);
        u32 off = 69632 + i*144 + dd*2;
        *(__nv_bfloat162*)(sm + off)     = {h0,h1};
        *(__nv_bfloat162*)(sm + off + 4) = {h2,h3};
        *(__nv_bfloat162*)(sm + off + (88064-69632))     = {__float2bfloat16(v.x-__bfloat162float(h0)),
                                                            __float2bfloat16(v.y-__bfloat162float(h1))};
        *(__nv_bfloat162*)(sm + off + (88064-69632) + 4) = {__float2bfloat16(v.z-__bfloat162float(h2)),
                                                            __float2bfloat16(v.w-__bfloat162float(h3))};
    }
    __syncthreads();
    if (tid < 128) g_nrm[(size_t)bh*Tc + c*CHc + tid] = rowsum[tid];

    int t_row = (lane & 7) + (((lane >> 4) & 1) << 3);
    int t_colbit = ((lane >> 3) & 1) << 3;
    float acc2[2][4][4];
    #pragma unroll
    for (int i = 0; i < 2; i++)
        #pragma unroll
        for (int j = 0; j < 4; j++)
            #pragma unroll
            for (int q = 0; q < 4; q++) acc2[i][j][q] = 0.f;

    #pragma unroll
    for (int ks16 = 0; ks16 < 8; ks16++) {
        u32 ah2[2][4], al2[2][4], bvh[2][4], bvl[2][4];
        #pragma unroll
        for (int mi = 0; mi < 2; mi++) {
            u32 addr = sb + ((wm*32 + mi*16 + a_row)*136 + ks16*16 + a_col)*2;
            ldsm4(ah2[mi][0], ah2[mi][1], ah2[mi][2], ah2[mi][3], addr);
            ldsm4(al2[mi][0], al2[mi][1], al2[mi][2], al2[mi][3], addr + 34816);
        }
        int krow = ks16*16 + t_row;
        #pragma unroll
        for (int nj = 0; nj < 2; nj++) {
            int dc = wn*32 + nj*16 + t_colbit;
            u32 addr = sb + 69632 + krow*144 + dc*2;
            ldsm4t(bvh[nj][0], bvh[nj][1], bvh[nj][2], bvh[nj][3], addr);
            ldsm4t(bvl[nj][0], bvl[nj][1], bvl[nj][2], bvl[nj][3], addr + (88064-69632));
        }
        #pragma unroll
        for (int mi = 0; mi < 2; mi++) {
            #pragma unroll
            for (int ng = 0; ng < 4; ng++) {
                int nj = ng >> 1, sel = ng & 1;
                mma16816(acc2[mi][ng], ah2[mi], bvh[nj][sel], bvh[nj][2+sel]);
                mma16816(acc2[mi][ng], ah2[mi], bvl[nj][sel], bvl[nj][2+sel]);
                mma16816(acc2[mi][ng], al2[mi], bvh[nj][sel], bvh[nj][2+sel]);
            }
        }
    }
    float* ob = g_o + ((size_t)bh*Tc + c*CHc)*Dc;
    #pragma unroll
    for (int mi = 0; mi < 2; mi++) {
        #pragma unroll
        for (int ng = 0; ng < 4; ng++) {
            int tok = wm*32 + mi*16 + (lane >> 2);
            int d = wn*32 + ng*8 + (lane & 3)*2;
            *(float2*)(ob + (size_t)tok*64 + d)     = make_float2(acc2[mi][ng][0], acc2[mi][ng][1]);
            *(float2*)(ob + (size_t)(tok+8)*64 + d) = make_float2(acc2[mi][ng][2], acc2[mi][ng][3]);
        }
    }
}

// ---------------- hist (HMMA): ctx = qf @ kv_state^T, + nrm finalize --------
__global__ __launch_bounds__(256, 1) void hist_mma_k()
{
    extern __shared__ char sm[];
    __shared__ float ks_sm[512];
    __shared__ float nrm_sm[128];
    u32 sb = smem_u32(sm);
    int bhc = blockIdx.x;
    int bh = bhc >> 5, c = bhc & 31;
    int tid = threadIdx.x, lane = tid & 31, warp = tid >> 5;
    int wm = warp >> 1, wn = warp & 1;

    const __nv_bfloat16* qh = g_qfh + (size_t)bhc*CHc*PMc;
    const __nv_bfloat16* ql = g_qfl + (size_t)bhc*CHc*PMc;
    const __nv_bfloat16* kvh = g_ckvh + (size_t)bhc*PMc*Dc;
    const __nv_bfloat16* kvl = g_ckvl + (size_t)bhc*PMc*Dc;
    const float* ksb = g_ks + (size_t)bhc*PMc;
    ks_sm[tid] = ksb[tid];
    ks_sm[tid+256] = ksb[tid+256];

    int r0 = (tid*2) >> 2, s0 = (tid*2) & 3;
    int r1 = (tid*2+1) >> 2, s1 = (tid*2+1) & 3;
    int kvr = tid >> 3, kvs = tid & 7;
    int lr = lane & 7;
    int a_row = lr + (((lane >> 3) & 1) << 3);
    int a_col = ((lane >> 4) & 1) << 3;
    int t_row = lr + (((lane >> 4) & 1) << 3);
    int t_colbit = ((lane >> 3) & 1) << 3;

    float acc[2][4][4];
    #pragma unroll
    for (int i = 0; i < 2; i++)
        #pragma unroll
        for (int j = 0; j < 4; j++)
            #pragma unroll
            for (int q = 0; q < 4; q++) acc[i][j][q] = 0.f;
    float nacc = 0.f;

    auto load_chunk = [&](int ch, int stage) {
        int k0 = ch * 32;
        u32 st = sb + stage * 29696;
        u32 d0 = st + r0*80 + s0*16;
        u32 d1 = st + r1*80 + s1*16;
        CP_ASYNC16(d0,         qh + (size_t)r0*PMc + k0 + s0*8);
        CP_ASYNC16(d1,         qh + (size_t)r1*PMc + k0 + s1*8);
        CP_ASYNC16(d0 + 10240, ql + (size_t)r0*PMc + k0 + s0*8);
        CP_ASYNC16(d1 + 10240, ql + (size_t)r1*PMc + k0 + s1*8);
        u32 dk = st + 20480 + kvr*144 + kvs*16;
        CP_ASYNC16(dk,        kvh + (size_t)(k0+kvr)*64 + kvs*8);
        CP_ASYNC16(dk + 4608, kvl + (size_t)(k0+kvr)*64 + kvs*8);
        CP_COMMIT();
    };

    load_chunk(0, 0);
    for (int ch = 0; ch < 16; ch++) {
        int stage = ch & 1;
        if (ch + 1 < 16) { load_chunk(ch + 1, stage ^ 1); CP_WAIT1(); }
        else             { CP_WAIT0(); }
        __syncthreads();
        u32 st = sb + stage * 29696;
        #pragma unroll
        for (int ks16 = 0; ks16 < 2; ks16++) {
            u32 afh[2][4], afl[2][4], bvh[2][4], bvl[2][4];
            #pragma unroll
            for (int mi = 0; mi < 2; mi++) {
                u32 addr = st + ((wm*32 + mi*16 + a_row)*40 + ks16*16 + a_col)*2;
                ldsm4(afh[mi][0], afh[mi][1], afh[mi][2], afh[mi][3], addr);
                ldsm4(afl[mi][0], afl[mi][1], afl[mi][2], afl[mi][3], addr + 10240);
            }
            int krow = ks16*16 + t_row;
            #pragma unroll
            for (int nj = 0; nj < 2; nj++) {
                int dc = wn*32 + nj*16 + t_colbit;
                u32 addr = st + 20480 + krow*144 + dc*2;
                ldsm4t(bvh[nj][0], bvh[nj][1], bvh[nj][2], bvh[nj][3], addr);
                ldsm4t(bvl[nj][0], bvl[nj][1], bvl[nj][2], bvl[nj][3], addr + 4608);
            }
            #pragma unroll
            for (int mi = 0; mi < 2; mi++) {
                #pragma unroll
                for (int ng = 0; ng < 4; ng++) {
                    int nj = ng >> 1, sel = ng & 1;
                    mma16816(acc[mi][ng], afh[mi], bvh[nj][sel], bvh[nj][2+sel]);
                    mma16816(acc[mi][ng], afh[mi], bvl[nj][sel], bvl[nj][2+sel]);
                    mma16816(acc[mi][ng], afl[mi], bvh[nj][sel], bvh[nj][2+sel]);
                }
            }
        }
        {
            int tt = tid >> 1, fh = (tid & 1)*16;
            const __nv_bfloat16* qhs = (const __nv_bfloat16*)(sm + stage*29696 + tt*80);
            const __nv_bfloat16* qls = (const __nv_bfloat16*)(sm + stage*29696 + 10240 + tt*80);
            #pragma unroll
            for (int f = 0; f < 16; f++) {
                int fl = fh + f;
                float qv = __bfloat162float(qhs[fl]) + __bfloat162float(qls[fl]);
                nacc += qv * ks_sm[ch*32 + fl];
            }
        }
        __syncthreads();
    }
    nacc += __shfl_xor_sync(0xffffffffu, nacc, 1);
    if ((tid & 1) == 0) nrm_sm[tid >> 1] = nacc;
    __syncthreads();
    if (tid < 128) {
        float tot = nrm_sm[tid] + g_nrm[(size_t)bh*Tc + c*CHc + tid] + 1e-6f;
        nrm_sm[tid] = 1.f / tot;
    }
    __syncthreads();

    float* ob = g_o + ((size_t)bh*Tc + c*CHc)*Dc;
    #pragma unroll
    for (int mi = 0; mi < 2; mi++) {
        #pragma unroll
        for (int ng = 0; ng < 4; ng++) {
            int tok = wm*32 + mi*16 + (lane >> 2);
            int d = wn*32 + ng*8 + (lane & 3)*2;
            float inv0 = nrm_sm[tok], inv1 = nrm_sm[tok+8];
            float2* p0 = (float2*)(ob + (size_t)tok*64 + d);
            float2* p1 = (float2*)(ob + (size_t)(tok+8)*64 + d);
            float2 c0 = *p0, c1 = *p1;
            c0.x = (c0.x + acc[mi][ng][0]) * inv0;
            c0.y = (c0.y + acc[mi][ng][1]) * inv0;
            c1.x = (c1.x + acc[mi][ng][2]) * inv1;
            c1.y = (c1.y + acc[mi][ng][3]) * inv1;
            *p0 = c0; *p1 = c1;
        }
    }
}

// ---------------- host launcher ---------------------------------------------
extern "C" void kernel_launch(void* const* d_in, const int* in_sizes, int n_in,
                              void* d_out, int out_size)
{
    const float* x        = (const float*)d_in[0];
    const float* qkv_w    = (const float*)d_in[1];
    const float* qkv_b    = (const float*)d_in[2];
    const float* out_w    = (const float*)d_in[3];
    const float* out_b    = (const float*)d_in[4];
    const float* omega    = (const float*)d_in[5];
    const float* poly_w   = (const float*)d_in[6];
    const float* qnodes   = (const float*)d_in[7];
    const float* qweights = (const float*)d_in[8];
    float* out = (float*)d_out;

    float* qkv_ptr = 0;
    cudaGetSymbolAddress((void**)&qkv_ptr, g_qkv);
    __nv_bfloat16 *ah, *al, *wh, *wl;
    cudaGetSymbolAddress((void**)&ah, g_ah);
    cudaGetSymbolAddress((void**)&al, g_al);
    cudaGetSymbolAddress((void**)&wh, g_wh);
    cudaGetSymbolAddress((void**)&wl, g_wl);

    cudaFuncSetAttribute(gemm_mma_k, cudaFuncAttributeMaxDynamicSharedMemorySize, 2*S_STAGE);
    cudaFuncSetAttribute(passA_mma_k, cudaFuncAttributeMaxDynamicSharedMemorySize, 106496);
    cudaFuncSetAttribute(scores_mma_k, cudaFuncAttributeMaxDynamicSharedMemorySize, 106496);
    cudaFuncSetAttribute(hist_mma_k, cudaFuncAttributeMaxDynamicSharedMemorySize, 59392);

    // 1) split operands to bf16 hi/lo
    split_bf16_k<<<(Bc*Tc*Ec)/1024, 256>>>(x, ah, al);
    split_bf16_k<<<(3*Ec*Ec)/1024, 256>>>(qkv_w, wh, wl);
    // 2) QKV GEMM (HMMA)
    gemm_mma_k<<<dim3(3*Ec/128, (Bc*Tc)/128), 256, 2*S_STAGE>>>(
        ah, al, wh, wl, qkv_b, qkv_ptr, 3*Ec);
    // 3) feature maps (reads g_qkv directly, l2norm fused)
    features_k<<<dim3(BHc*NCc, 2), 256>>>(omega, poly_w, qnodes, qweights);
    // 4) per-chunk kv + ks (HMMA, v from g_qkv)
    passA_mma_k<<<dim3(BHc*NCc, 4), 256, 106496>>>();
    // 5) fused exclusive prefix + bf16 convert
    prefix_kv_cvt_k<<<(BHc*PMc*Dc)/1024, 256>>>();
    prefix_ks_k<<<(BHc*PMc)/1024, 256>>>();
    // 6) intra-chunk scores + intra context (HMMA)
    scores_mma_k<<<BHc*NCc, 256, 106496>>>();
    // 7) history context + normalize (HMMA)
    hist_mma_k<<<BHc*NCc, 256, 59392>>>();
    // 8) output projection (HMMA)
    o2rows_k<<<(BHc*Tc*Dc)/512, 256>>>();
    split_bf16_k<<<(Ec*Ec)/1024, 256>>>(out_w, wh, wl);
    gemm_mma_k<<<dim3(Ec/128, (Bc*Tc)/128), 256, 2*S_STAGE>>>(
        ah, al, wh, wl, out_b, out, Ec);
}

// round 8
// speedup vs baseline: 2.5207x; 1.0742x over previous
#include <cuda_runtime.h>
#include <cuda_bf16.h>
#include <math.h>

#define Bc 2
#define Tc 4096
#define Ec 1024
#define Hc 16
#define Dc 64
#define Pc 64
#define PMc 512
#define CHc 128
#define NCc 32
#define BHc 32

typedef unsigned long long u64;
typedef unsigned int u32;

// ---------------- scratch (device globals; no allocations allowed) ----------
__device__ float g_qkv[(size_t)Bc*Tc*3*Ec];
__device__ float g_ckv[(size_t)BHc*NCc*PMc*Dc];      // (bhc, f, d) fp32 per-chunk
__device__ float g_ks [(size_t)BHc*NCc*PMc];
__device__ float g_o  [(size_t)BHc*Tc*Dc];
__device__ float g_nrm[(size_t)BHc*Tc];
// bf16 hi/lo features, [bhc][token 128][feature 512]
__device__ __align__(16) __nv_bfloat16 g_qfh[(size_t)BHc*NCc*CHc*PMc];
__device__ __align__(16) __nv_bfloat16 g_qfl[(size_t)BHc*NCc*CHc*PMc];
__device__ __align__(16) __nv_bfloat16 g_kfh[(size_t)BHc*NCc*CHc*PMc];
__device__ __align__(16) __nv_bfloat16 g_kfl[(size_t)BHc*NCc*CHc*PMc];
// bf16 hi/lo exclusive kv state, [bhc][f][d]
__device__ __align__(16) __nv_bfloat16 g_ckvh[(size_t)BHc*NCc*PMc*Dc];
__device__ __align__(16) __nv_bfloat16 g_ckvl[(size_t)BHc*NCc*PMc*Dc];
// bf16 split operands for dense GEMMs
__device__ __align__(16) __nv_bfloat16 g_ah[(size_t)Bc*Tc*Ec];
__device__ __align__(16) __nv_bfloat16 g_al[(size_t)Bc*Tc*Ec];
__device__ __align__(16) __nv_bfloat16 g_wh[(size_t)3*Ec*Ec];
__device__ __align__(16) __nv_bfloat16 g_wl[(size_t)3*Ec*Ec];

// ================= helpers ===================================================
__device__ __forceinline__ u32 smem_u32(const void* p) {
    u32 a; asm("{ .reg .u64 t; cvta.to.shared.u64 t, %1; cvt.u32.u64 %0, t; }"
               : "=r"(a) : "l"(p));
    return a;
}
#define CP_ASYNC16(dst, src) \
    asm volatile("cp.async.cg.shared.global [%0], [%1], 16;\n" :: "r"(dst), "l"(src))
#define CP_COMMIT() asm volatile("cp.async.commit_group;\n" ::: "memory")
#define CP_WAIT1()  asm volatile("cp.async.wait_group 1;\n" ::: "memory")
#define CP_WAIT0()  asm volatile("cp.async.wait_group 0;\n" ::: "memory")

__device__ __forceinline__ void ldsm4(u32 &r0, u32 &r1, u32 &r2, u32 &r3, u32 a) {
    asm volatile("ldmatrix.sync.aligned.m8n8.x4.shared.b16 {%0,%1,%2,%3}, [%4];\n"
                 : "=r"(r0), "=r"(r1), "=r"(r2), "=r"(r3) : "r"(a));
}
__device__ __forceinline__ void ldsm4t(u32 &r0, u32 &r1, u32 &r2, u32 &r3, u32 a) {
    asm volatile("ldmatrix.sync.aligned.m8n8.x4.trans.shared.b16 {%0,%1,%2,%3}, [%4];\n"
                 : "=r"(r0), "=r"(r1), "=r"(r2), "=r"(r3) : "r"(a));
}
__device__ __forceinline__ void mma16816(float* c, const u32* a, u32 b0, u32 b1) {
    asm volatile(
        "mma.sync.aligned.m16n8k16.row.col.f32.bf16.bf16.f32 "
        "{%0,%1,%2,%3},{%4,%5,%6,%7},{%8,%9},{%0,%1,%2,%3};\n"
        : "+f"(c[0]), "+f"(c[1]), "+f"(c[2]), "+f"(c[3])
        : "r"(a[0]), "r"(a[1]), "r"(a[2]), "r"(a[3]), "r"(b0), "r"(b1));
}

// ================= fp32 -> bf16 hi/lo split ==================================
__global__ void split_bf16_k(const float* __restrict__ s,
                             __nv_bfloat16* __restrict__ h,
                             __nv_bfloat16* __restrict__ l)
{
    size_t i = ((size_t)blockIdx.x*256 + threadIdx.x)*4;
    float4 v = *(const float4*)(s + i);
    __nv_bfloat16 h0=__float2bfloat16(v.x), h1=__float2bfloat16(v.y);
    __nv_bfloat16 h2=__float2bfloat16(v.z), h3=__float2bfloat16(v.w);
    __nv_bfloat162 ha = {h0,h1}, hb = {h2,h3};
    __nv_bfloat162 la = {__float2bfloat16(v.x-__bfloat162float(h0)),
                         __float2bfloat16(v.y-__bfloat162float(h1))};
    __nv_bfloat162 lb = {__float2bfloat16(v.z-__bfloat162float(h2)),
                         __float2bfloat16(v.w-__bfloat162float(h3))};
    *(__nv_bfloat162*)(h+i) = ha; *(__nv_bfloat162*)(h+i+2) = hb;
    *(__nv_bfloat162*)(l+i) = la; *(__nv_bfloat162*)(l+i+2) = lb;
}

// ------ reshape g_o (B,H,T,D) -> rows (b*T+t, h*64+d), bf16 hi/lo ------------
__global__ void o2rows_k()
{
    size_t gidx = ((size_t)blockIdx.x*256 + threadIdx.x)*2;
    float2 v = *(const float2*)(g_o + gidx);
    int d = (int)(gidx & 63), t = (int)((gidx >> 6) & 4095);
    int h = (int)((gidx >> 18) & 15), b = (int)(gidx >> 22);
    size_t dst = ((size_t)(b*Tc + t))*Ec + h*64 + d;
    __nv_bfloat16 h0=__float2bfloat16(v.x), h1=__float2bfloat16(v.y);
    *(__nv_bfloat162*)(g_ah+dst) = {h0,h1};
    *(__nv_bfloat162*)(g_al+dst) = {__float2bfloat16(v.x-__bfloat162float(h0)),
                                    __float2bfloat16(v.y-__bfloat162float(h1))};
}

// ================= HMMA GEMM: C[M,N] = A @ W^T + bias (bf16x3 split) ========
#define S_STRIDE 40
#define S_ARR 10240
#define S_STAGE 40960

__global__ __launch_bounds__(256, 1)
void gemm_mma_k(const __nv_bfloat16* __restrict__ Abase_h,
                const __nv_bfloat16* __restrict__ Abase_l,
                const __nv_bfloat16* __restrict__ Wbase_h,
                const __nv_bfloat16* __restrict__ Wbase_l,
                const float* __restrict__ bias, float* __restrict__ C, int N)
{
    extern __shared__ char smem[];
    u32 sb = smem_u32(smem);
    const int K = 1024;
    int tid = threadIdx.x;
    int lane = tid & 31, warp = tid >> 5;
    int wm = warp >> 1, wn = warp & 1;
    int bm = blockIdx.y * 128, bn = blockIdx.x * 128;

    const __nv_bfloat16* Ah = Abase_h + (size_t)bm * K;
    const __nv_bfloat16* Al = Abase_l + (size_t)bm * K;
    const __nv_bfloat16* Wh = Wbase_h + (size_t)bn * K;
    const __nv_bfloat16* Wl = Wbase_l + (size_t)bn * K;

    int r0 = (tid*2) >> 2, s0 = (tid*2) & 3;
    int r1 = (tid*2+1) >> 2, s1 = (tid*2+1) & 3;

    int lr = lane & 7;
    int a_row = lr + (((lane >> 3) & 1) << 3);
    int a_col = ((lane >> 4) & 1) << 3;
    int b_row = lr + (((lane >> 4) & 1) << 3);
    int b_col = ((lane >> 3) & 1) << 3;

    float acc[2][8][4];
    #pragma unroll
    for (int i = 0; i < 2; i++)
        #pragma unroll
        for (int j = 0; j < 8; j++)
            #pragma unroll
            for (int q = 0; q < 4; q++) acc[i][j][q] = 0.f;

    auto load_chunk = [&](int ch, int stage) {
        int k0 = ch * 32;
        u32 st = sb + stage * S_STAGE;
        u32 d0 = st + r0*80 + s0*16;
        u32 d1 = st + r1*80 + s1*16;
        CP_ASYNC16(d0, Ah + (size_t)r0*K + k0 + s0*8);
        CP_ASYNC16(d1, Ah + (size_t)r1*K + k0 + s1*8);
        CP_ASYNC16(d0 + S_ARR, Al + (size_t)r0*K + k0 + s0*8);
        CP_ASYNC16(d1 + S_ARR, Al + (size_t)r1*K + k0 + s1*8);
        CP_ASYNC16(d0 + 2*S_ARR, Wh + (size_t)r0*K + k0 + s0*8);
        CP_ASYNC16(d1 + 2*S_ARR, Wh + (size_t)r1*K + k0 + s1*8);
        CP_ASYNC16(d0 + 3*S_ARR, Wl + (size_t)r0*K + k0 + s0*8);
        CP_ASYNC16(d1 + 3*S_ARR, Wl + (size_t)r1*K + k0 + s1*8);
        CP_COMMIT();
    };

    load_chunk(0, 0);

    for (int ch = 0; ch < 32; ch++) {
        int stage = ch & 1;
        if (ch + 1 < 32) { load_chunk(ch + 1, stage ^ 1); CP_WAIT1(); }
        else             { CP_WAIT0(); }
        __syncthreads();

        u32 st = sb + stage * S_STAGE;
        #pragma unroll
        for (int ks = 0; ks < 2; ks++) {
            u32 afh[2][4], afl[2][4], bfh[4][4], bfl[4][4];
            #pragma unroll
            for (int mi = 0; mi < 2; mi++) {
                u32 addr = st + ((wm*32 + mi*16 + a_row)*S_STRIDE + ks*16 + a_col)*2;
                ldsm4(afh[mi][0], afh[mi][1], afh[mi][2], afh[mi][3], addr);
                ldsm4(afl[mi][0], afl[mi][1], afl[mi][2], afl[mi][3], addr + S_ARR);
            }
            #pragma unroll
            for (int nj = 0; nj < 4; nj++) {
                u32 addr = st + 2*S_ARR +
                           ((wn*64 + nj*16 + b_row)*S_STRIDE + ks*16 + b_col)*2;
                ldsm4(bfh[nj][0], bfh[nj][1], bfh[nj][2], bfh[nj][3], addr);
                ldsm4(bfl[nj][0], bfl[nj][1], bfl[nj][2], bfl[nj][3], addr + S_ARR);
            }
            #pragma unroll
            for (int mi = 0; mi < 2; mi++) {
                #pragma unroll
                for (int ni = 0; ni < 8; ni++) {
                    int nj = ni >> 1, off = (ni & 1) << 1;
                    mma16816(acc[mi][ni], afh[mi], bfh[nj][off], bfh[nj][off+1]);
                    mma16816(acc[mi][ni], afh[mi], bfl[nj][off], bfl[nj][off+1]);
                    mma16816(acc[mi][ni], afl[mi], bfh[nj][off], bfh[nj][off+1]);
                }
            }
        }
        __syncthreads();
    }

    #pragma unroll
    for (int mi = 0; mi < 2; mi++) {
        #pragma unroll
        for (int ni = 0; ni < 8; ni++) {
            int m = bm + wm*32 + mi*16 + (lane >> 2);
            int n = bn + wn*64 + ni*8 + (lane & 3)*2;
            float2 o0, o1;
            o0.x = acc[mi][ni][0] + bias[n];
            o0.y = acc[mi][ni][1] + bias[n+1];
            o1.x = acc[mi][ni][2] + bias[n];
            o1.y = acc[mi][ni][3] + bias[n+1];
            *(float2*)(C + (size_t)m*N + n)     = o0;
            *(float2*)(C + (size_t)(m+8)*N + n) = o1;
        }
    }
}

// ---------------- feature map -> bf16 hi/lo [token][feature] ----------------
// v3: strided p-column ownership -> perfectly coalesced stores; poly_w in smem
// dynamic smem layout: xs[128*68] | ps[64*68] | om[512] | prf[1024] | rn[128]
#define F_XS   0
#define F_PS   (128*68)
#define F_OM   (F_PS + 64*68)
#define F_PRF  (F_OM + 512)
#define F_RN   (F_PRF + 1024)
#define F_SMEM ((F_RN + 128)*4)

__global__ __launch_bounds__(256, 3) void features_k(
    const float* __restrict__ omega, const float* __restrict__ poly_w,
    const float* __restrict__ qnodes, const float* __restrict__ qweights)
{
    extern __shared__ float fsm[];
    float* xs  = fsm + F_XS;           // [token][68]
    float* ps  = fsm + F_PS;           // [d][68]
    float* om  = fsm + F_OM;
    float* prf = fsm + F_PRF;
    float* rn  = fsm + F_RN;
    int bhc = blockIdx.x;
    int isK = blockIdx.y;
    int bh = bhc >> 5, c = bhc & 31;
    int h = bh & 15, b = bh >> 4;
    const float* src = g_qkv + ((size_t)(b*Tc + c*CHc))*(3*Ec) + isK*Ec + h*64;
    __nv_bfloat16* dh = (isK ? g_kfh : g_qfh) + (size_t)bhc*CHc*PMc;
    __nv_bfloat16* dl = (isK ? g_kfl : g_qfl) + (size_t)bhc*CHc*PMc;
    int tid = threadIdx.x;
    #pragma unroll
    for (int l = 0; l < 8; l++) {
        int idx = tid + l*256;         // < 2048
        int i = idx >> 4, dd = (idx & 15) << 2;
        float4 v = *(const float4*)(src + (size_t)i*(3*Ec) + dd);
        *(float4*)&xs[i*68 + dd] = v;
    }
    {
        const float* pwp = poly_w + h*4096;
        #pragma unroll
        for (int l = 0; l < 4; l++) {
            int idx = tid + l*256;     // < 1024 float4s
            int d = idx >> 4, pc = (idx & 15) << 2;
            *(float4*)&ps[d*68 + pc] = *(const float4*)(pwp + d*64 + pc);
        }
    }
    om[tid]       = omega[h*512 + tid];
    om[tid + 256] = omega[h*512 + tid + 256];
    __syncthreads();
    if (tid < 128) {
        const float* xr = &xs[tid*68];
        float s = 0.f;
        #pragma unroll
        for (int d = 0; d < 64; d++) { float x = xr[d]; s += x*x; }
        rn[tid] = 1.f / fmaxf(sqrtf(s), 1e-12f);
    }
    __syncthreads();
    float s0 = qnodes[0];
    float sq2s = sqrtf(fmaxf(2.f*s0, 0.f));
    float wq = sqrtf(fmaxf(qweights[0], 0.f));
    float prescale = 0.3535533905932738f * wq;
    #pragma unroll
    for (int l = 0; l < 4; l++) {
        int pair = tid + l*256;
        int i = pair >> 3, m = pair & 7;
        const float* xr = &xs[i*68];
        float a = 0.f;
        #pragma unroll
        for (int d = 0; d < 64; d++) a += xr[d] * om[d*8 + m];
        float e = fminf(fmaxf(a * rn[i] * sq2s - s0, -20.f), 20.f);
        prf[i*8 + m] = expf(e) * prescale;
    }
    __syncthreads();
    // thread owns tokens [ti, ti+8) and p-columns {tp, tp+16, tp+32, tp+48}
    int ti = (tid >> 4) << 3, tp = tid & 15;
    float acc[8][4] = {};
    for (int d = 0; d < 64; d++) {
        float a[8];
        #pragma unroll
        for (int x = 0; x < 8; x++) a[x] = xs[(ti+x)*68 + d];
        float b0 = ps[d*68 + tp];
        float b1 = ps[d*68 + tp + 16];
        float b2 = ps[d*68 + tp + 32];
        float b3 = ps[d*68 + tp + 48];
        #pragma unroll
        for (int i2 = 0; i2 < 8; i2++) {
            acc[i2][0] += a[i2]*b0; acc[i2][1] += a[i2]*b1;
            acc[i2][2] += a[i2]*b2; acc[i2][3] += a[i2]*b3;
        }
    }
    #pragma unroll
    for (int i2 = 0; i2 < 8; i2++) {
        float r = rn[ti + i2];
        #pragma unroll
        for (int j = 0; j < 4; j++) {
            float t = acc[i2][j] * r;
            acc[i2][j] = t*t*0.125f;
        }
    }
    // epilogue: for fixed (i2,j) lanes 0..15 write contiguous 256B segments
    #pragma unroll
    for (int i2 = 0; i2 < 8; i2++) {
        int tok = ti + i2;
        const float* pr = &prf[tok*8];
        #pragma unroll
        for (int j = 0; j < 4; j++) {
            float base = acc[i2][j];
            __nv_bfloat16 hb[8], lb[8];
            #pragma unroll
            for (int m = 0; m < 8; m++) {
                float v = base * pr[m];
                __nv_bfloat16 hh = __float2bfloat16(v);
                hb[m] = hh;
                lb[m] = __float2bfloat16(v - __bfloat162float(hh));
            }
            size_t off = (size_t)tok*PMc + (tp + j*16)*8;
            *(uint4*)(dh + off) = *(uint4*)hb;
            *(uint4*)(dl + off) = *(uint4*)lb;
        }
    }
}

// ---------------- pass A (HMMA): kv[f][d] = sum_i kf[i][f] v[i][d] ----------
__global__ __launch_bounds__(256, 2) void passA_mma_k()
{
    extern __shared__ char sm[];
    u32 sb = smem_u32(sm);
    const u32 KFH = 0, KFL = 34816, VH = 69632, VL = 88064;
    int bhc = blockIdx.x, fb = blockIdx.y;
    int bh = bhc >> 5, c = bhc & 31;
    int tid = threadIdx.x, lane = tid & 31, warp = tid >> 5;
    int wm = warp >> 1, wn = warp & 1;

    const __nv_bfloat16* kh = g_kfh + (size_t)bhc*CHc*PMc + fb*128;
    const __nv_bfloat16* kl = g_kfl + (size_t)bhc*CHc*PMc + fb*128;
    #pragma unroll
    for (int l = 0; l < 8; l++) {
        int idx = tid + l*256;
        int row = idx >> 4, seg = idx & 15;
        u32 d = sb + KFH + row*272 + seg*16;
        CP_ASYNC16(d,              kh + (size_t)row*PMc + seg*8);
        CP_ASYNC16(d + (KFL-KFH),  kl + (size_t)row*PMc + seg*8);
    }
    CP_COMMIT();
    const float* vb = g_qkv + ((size_t)((bh>>4)*Tc + c*CHc))*(3*Ec) + 2*Ec + (bh&15)*64;
    #pragma unroll
    for (int l = 0; l < 8; l++) {
        int idx = tid + l*256;
        int i = idx >> 4, dd = (idx & 15)*4;
        float4 v = *(const float4*)(vb + (size_t)i*(3*Ec) + dd);
        __nv_bfloat16 h0=__float2bfloat16(v.x), h1=__float2bfloat16(v.y);
        __nv_bfloat16 h2=__float2bfloat16(v.z), h3=__float2bfloat16(v.w);
        u32 off = i*144 + dd*2;
        *(__nv_bfloat162*)(sm + VH + off)     = {h0,h1};
        *(__nv_bfloat162*)(sm + VH + off + 4) = {h2,h3};
        *(__nv_bfloat162*)(sm + VL + off)     = {__float2bfloat16(v.x-__bfloat162float(h0)),
                                                 __float2bfloat16(v.y-__bfloat162float(h1))};
        *(__nv_bfloat162*)(sm + VL + off + 4) = {__float2bfloat16(v.z-__bfloat162float(h2)),
                                                 __float2bfloat16(v.w-__bfloat162float(h3))};
    }
    CP_WAIT0();
    __syncthreads();

    if (tid < 128) {
        float s = 0.f;
        for (int i = 0; i < 128; i++) {
            s += __bfloat162float(*(const __nv_bfloat16*)(sm + KFH + i*272 + tid*2));
            s += __bfloat162float(*(const __nv_bfloat16*)(sm + KFL + i*272 + tid*2));
        }
        g_ks[(size_t)bhc*PMc + fb*128 + tid] = s;
    }

    int t_row = (lane & 7) + (((lane >> 4) & 1) << 3);
    int t_colbit = ((lane >> 3) & 1) << 3;

    float acc[2][4][4];
    #pragma unroll
    for (int i = 0; i < 2; i++)
        #pragma unroll
        for (int j = 0; j < 4; j++)
            #pragma unroll
            for (int q = 0; q < 4; q++) acc[i][j][q] = 0.f;

    #pragma unroll
    for (int ks16 = 0; ks16 < 8; ks16++) {
        int krow = ks16*16 + t_row;
        u32 afh[2][4], afl[2][4], bvh[2][4], bvl[2][4];
        #pragma unroll
        for (int mi = 0; mi < 2; mi++) {
            int fc = wm*32 + mi*16 + t_colbit;
            u32 addr = sb + KFH + krow*272 + fc*2;
            ldsm4t(afh[mi][0], afh[mi][1], afh[mi][2], afh[mi][3], addr);
            ldsm4t(afl[mi][0], afl[mi][1], afl[mi][2], afl[mi][3], addr + (KFL-KFH));
        }
        #pragma unroll
        for (int nj = 0; nj < 2; nj++) {
            int dc = wn*32 + nj*16 + t_colbit;
            u32 addr = sb + VH + krow*144 + dc*2;
            ldsm4t(bvh[nj][0], bvh[nj][1], bvh[nj][2], bvh[nj][3], addr);
            ldsm4t(bvl[nj][0], bvl[nj][1], bvl[nj][2], bvl[nj][3], addr + (VL-VH));
        }
        #pragma unroll
        for (int mi = 0; mi < 2; mi++) {
            #pragma unroll
            for (int ng = 0; ng < 4; ng++) {
                int nj = ng >> 1, sel = ng & 1;
                mma16816(acc[mi][ng], afh[mi], bvh[nj][sel], bvh[nj][2+sel]);
                mma16816(acc[mi][ng], afh[mi], bvl[nj][sel], bvl[nj][2+sel]);
                mma16816(acc[mi][ng], afl[mi], bvh[nj][sel], bvh[nj][2+sel]);
            }
        }
    }
    float* outp = g_ckv + (size_t)bhc*PMc*Dc + (size_t)fb*128*Dc;
    #pragma unroll
    for (int mi = 0; mi < 2; mi++) {
        #pragma unroll
        for (int ng = 0; ng < 4; ng++) {
            int f = wm*32 + mi*16 + (lane >> 2);
            int d = wn*32 + ng*8 + (lane & 3)*2;
            *(float2*)(outp + (size_t)f*64 + d)     = make_float2(acc[mi][ng][0], acc[mi][ng][1]);
            *(float2*)(outp + (size_t)(f+8)*64 + d) = make_float2(acc[mi][ng][2], acc[mi][ng][3]);
        }
    }
}

// ------- fused exclusive prefix over chunks + bf16 hi/lo convert -------------
__global__ void prefix_kv_cvt_k()
{
    size_t e = ((size_t)blockIdx.x*256 + threadIdx.x)*4;
    size_t bh = e / (PMc*Dc);
    size_t rem = e % (PMc*Dc);
    float4 acc = make_float4(0.f,0.f,0.f,0.f);
    #pragma unroll
    for (int c = 0; c < NCc; c++) {
        size_t p = (bh*NCc + c)*(size_t)(PMc*Dc) + rem;
        float4 v = *(const float4*)(g_ckv + p);
        __nv_bfloat16 h0=__float2bfloat16(acc.x), h1=__float2bfloat16(acc.y);
        __nv_bfloat16 h2=__float2bfloat16(acc.z), h3=__float2bfloat16(acc.w);
        *(__nv_bfloat162*)(g_ckvh+p)   = {h0,h1};
        *(__nv_bfloat162*)(g_ckvh+p+2) = {h2,h3};
        *(__nv_bfloat162*)(g_ckvl+p)   = {__float2bfloat16(acc.x-__bfloat162float(h0)),
                                          __float2bfloat16(acc.y-__bfloat162float(h1))};
        *(__nv_bfloat162*)(g_ckvl+p+2) = {__float2bfloat16(acc.z-__bfloat162float(h2)),
                                          __float2bfloat16(acc.w-__bfloat162float(h3))};
        acc.x += v.x; acc.y += v.y; acc.z += v.z; acc.w += v.w;
    }
}
__global__ void prefix_ks_k()
{
    size_t e = ((size_t)blockIdx.x*256 + threadIdx.x)*4;
    size_t bh = e / PMc;
    size_t rem = e % PMc;
    float4 acc = make_float4(0.f,0.f,0.f,0.f);
    #pragma unroll
    for (int c = 0; c < NCc; c++) {
        size_t p = (bh*NCc + c)*(size_t)PMc + rem;
        float4 v = *(const float4*)(g_ks + p);
        *(float4*)(g_ks + p) = acc;
        acc.x += v.x; acc.y += v.y; acc.z += v.z; acc.w += v.w;
    }
}

// ---------------- scores (HMMA): S = qf kf^T, mask, rowsum, intra = S v -----
__global__ __launch_bounds__(256, 1) void scores_mma_k()
{
    extern __shared__ char sm[];
    __shared__ float rowsum[128];
    u32 sb = smem_u32(sm);
    int bhc = blockIdx.x;
    int bh = bhc >> 5, c = bhc & 31;
    int tid = threadIdx.x, lane = tid & 31, warp = tid >> 5;
    int wm = warp >> 1, wn = warp & 1;
    if (tid < 128) rowsum[tid] = 0.f;

    const __nv_bfloat16* qh = g_qfh + (size_t)bhc*CHc*PMc;
    const __nv_bfloat16* ql = g_qfl + (size_t)bhc*CHc*PMc;
    const __nv_bfloat16* kh = g_kfh + (size_t)bhc*CHc*PMc;
    const __nv_bfloat16* kl = g_kfl + (size_t)bhc*CHc*PMc;

    int r0 = (tid*2) >> 2, s0 = (tid*2) & 3;
    int r1 = (tid*2+1) >> 2, s1 = (tid*2+1) & 3;
    int lr = lane & 7;
    int a_row = lr + (((lane >> 3) & 1) << 3);
    int a_col = ((lane >> 4) & 1) << 3;
    int b_row = lr + (((lane >> 4) & 1) << 3);
    int b_col = ((lane >> 3) & 1) << 3;

    float acc[2][8][4];
    #pragma unroll
    for (int i = 0; i < 2; i++)
        #pragma unroll
        for (int j = 0; j < 8; j++)
            #pragma unroll
            for (int q = 0; q < 4; q++) acc[i][j][q] = 0.f;

    auto load_chunk = [&](int ch, int stage) {
        int k0 = ch * 32;
        u32 st = sb + stage * 40960;
        u32 d0 = st + r0*80 + s0*16;
        u32 d1 = st + r1*80 + s1*16;
        CP_ASYNC16(d0,         qh + (size_t)r0*PMc + k0 + s0*8);
        CP_ASYNC16(d1,         qh + (size_t)r1*PMc + k0 + s1*8);
        CP_ASYNC16(d0 + 10240, ql + (size_t)r0*PMc + k0 + s0*8);
        CP_ASYNC16(d1 + 10240, ql + (size_t)r1*PMc + k0 + s1*8);
        CP_ASYNC16(d0 + 20480, kh + (size_t)r0*PMc + k0 + s0*8);
        CP_ASYNC16(d1 + 20480, kh + (size_t)r1*PMc + k0 + s1*8);
        CP_ASYNC16(d0 + 30720, kl + (size_t)r0*PMc + k0 + s0*8);
        CP_ASYNC16(d1 + 30720, kl + (size_t)r1*PMc + k0 + s1*8);
        CP_COMMIT();
    };

    load_chunk(0, 0);
    for (int ch = 0; ch < 16; ch++) {
        int stage = ch & 1;
        if (ch + 1 < 16) { load_chunk(ch + 1, stage ^ 1); CP_WAIT1(); }
        else             { CP_WAIT0(); }
        __syncthreads();
        u32 st = sb + stage * 40960;
        #pragma unroll
        for (int ks = 0; ks < 2; ks++) {
            u32 afh[2][4], afl[2][4], bfh[4][4], bfl[4][4];
            #pragma unroll
            for (int mi = 0; mi < 2; mi++) {
                u32 addr = st + ((wm*32 + mi*16 + a_row)*40 + ks*16 + a_col)*2;
                ldsm4(afh[mi][0], afh[mi][1], afh[mi][2], afh[mi][3], addr);
                ldsm4(afl[mi][0], afl[mi][1], afl[mi][2], afl[mi][3], addr + 10240);
            }
            #pragma unroll
            for (int nj = 0; nj < 4; nj++) {
                u32 addr = st + 20480 + ((wn*64 + nj*16 + b_row)*40 + ks*16 + b_col)*2;
                ldsm4(bfh[nj][0], bfh[nj][1], bfh[nj][2], bfh[nj][3], addr);
                ldsm4(bfl[nj][0], bfl[nj][1], bfl[nj][2], bfl[nj][3], addr + 10240);
            }
            #pragma unroll
            for (int mi = 0; mi < 2; mi++) {
                #pragma unroll
                for (int ni = 0; ni < 8; ni++) {
                    int nj = ni >> 1, off = (ni & 1) << 1;
                    mma16816(acc[mi][ni], afh[mi], bfh[nj][off], bfh[nj][off+1]);
                    mma16816(acc[mi][ni], afh[mi], bfl[nj][off], bfl[nj][off+1]);
                    mma16816(acc[mi][ni], afl[mi], bfh[nj][off], bfh[nj][off+1]);
                }
            }
        }
        __syncthreads();
    }

    #pragma unroll
    for (int mi = 0; mi < 2; mi++) {
        float rs0 = 0.f, rs1 = 0.f;
        int ri0 = wm*32 + mi*16 + (lane >> 2);
        #pragma unroll
        for (int ni = 0; ni < 8; ni++) {
            int cj = wn*64 + ni*8 + (lane & 3)*2;
            float v00 = (cj   <= ri0)   ? acc[mi][ni][0] : 0.f;
            float v01 = (cj+1 <= ri0)   ? acc[mi][ni][1] : 0.f;
            float v10 = (cj   <= ri0+8) ? acc[mi][ni][2] : 0.f;
            float v11 = (cj+1 <= ri0+8) ? acc[mi][ni][3] : 0.f;
            rs0 += v00 + v01; rs1 += v10 + v11;
            __nv_bfloat16 h00=__float2bfloat16(v00), h01=__float2bfloat16(v01);
            __nv_bfloat16 h10=__float2bfloat16(v10), h11=__float2bfloat16(v11);
            u32 o0 = ri0*272 + cj*2, o1 = (ri0+8)*272 + cj*2;
            *(__nv_bfloat162*)(sm + o0)         = {h00,h01};
            *(__nv_bfloat162*)(sm + o1)         = {h10,h11};
            *(__nv_bfloat162*)(sm + 34816 + o0) = {__float2bfloat16(v00-__bfloat162float(h00)),
                                                   __float2bfloat16(v01-__bfloat162float(h01))};
            *(__nv_bfloat162*)(sm + 34816 + o1) = {__float2bfloat16(v10-__bfloat162float(h10)),
                                                   __float2bfloat16(v11-__bfloat162float(h11))};
        }
        rs0 += __shfl_xor_sync(0xffffffffu, rs0, 1);
        rs0 += __shfl_xor_sync(0xffffffffu, rs0, 2);
        rs1 += __shfl_xor_sync(0xffffffffu, rs1, 1);
        rs1 += __shfl_xor_sync(0xffffffffu, rs1, 2);
        if ((lane & 3) == 0) {
            atomicAdd(&rowsum[ri0], rs0);
            atomicAdd(&rowsum[ri0+8], rs1);
        }
    }
    const float* vb = g_qkv + ((size_t)((bh>>4)*Tc + c*CHc))*(3*Ec) + 2*Ec + (bh&15)*64;
    #pragma unroll
    for (int l = 0; l < 8; l++) {
        int idx = tid + l*256;
        int i = idx >> 4, dd = (idx & 15)*4;
        float4 v = *(const float4*)(vb + (size_t)i*(3*Ec) + dd);
        __nv_bfloat16 h0=__float2bfloat16(v.x), h1=__float2bfloat16(v.y);
        __nv_bfloat16 h2=__float2bfloat16(v.z), h3=__float2bfloat16(v.w);
        u32 off = 69632 + i*144 + dd*2;
        *(__nv_bfloat162*)(sm + off)     = {h0,h1};
        *(__nv_bfloat162*)(sm + off + 4) = {h2,h3};
        *(__nv_bfloat162*)(sm + off + (88064-69632))     = {__float2bfloat16(v.x-__bfloat162float(h0)),
                                                            __float2bfloat16(v.y-__bfloat162float(h1))};
        *(__nv_bfloat162*)(sm + off + (88064-69632) + 4) = {__float2bfloat16(v.z-__bfloat162float(h2)),
                                                            __float2bfloat16(v.w-__bfloat162float(h3))};
    }
    __syncthreads();
    if (tid < 128) g_nrm[(size_t)bh*Tc + c*CHc + tid] = rowsum[tid];

    int t_row = (lane & 7) + (((lane >> 4) & 1) << 3);
    int t_colbit = ((lane >> 3) & 1) << 3;
    float acc2[2][4][4];
    #pragma unroll
    for (int i = 0; i < 2; i++)
        #pragma unroll
        for (int j = 0; j < 4; j++)
            #pragma unroll
            for (int q = 0; q < 4; q++) acc2[i][j][q] = 0.f;

    #pragma unroll
    for (int ks16 = 0; ks16 < 8; ks16++) {
        u32 ah2[2][4], al2[2][4], bvh[2][4], bvl[2][4];
        #pragma unroll
        for (int mi = 0; mi < 2; mi++) {
            u32 addr = sb + ((wm*32 + mi*16 + a_row)*136 + ks16*16 + a_col)*2;
            ldsm4(ah2[mi][0], ah2[mi][1], ah2[mi][2], ah2[mi][3], addr);
            ldsm4(al2[mi][0], al2[mi][1], al2[mi][2], al2[mi][3], addr + 34816);
        }
        int krow = ks16*16 + t_row;
        #pragma unroll
        for (int nj = 0; nj < 2; nj++) {
            int dc = wn*32 + nj*16 + t_colbit;
            u32 addr = sb + 69632 + krow*144 + dc*2;
            ldsm4t(bvh[nj][0], bvh[nj][1], bvh[nj][2], bvh[nj][3], addr);
            ldsm4t(bvl[nj][0], bvl[nj][1], bvl[nj][2], bvl[nj][3], addr + (88064-69632));
        }
        #pragma unroll
        for (int mi = 0; mi < 2; mi++) {
            #pragma unroll
            for (int ng = 0; ng < 4; ng++) {
                int nj = ng >> 1, sel = ng & 1;
                mma16816(acc2[mi][ng], ah2[mi], bvh[nj][sel], bvh[nj][2+sel]);
                mma16816(acc2[mi][ng], ah2[mi], bvl[nj][sel], bvl[nj][2+sel]);
                mma16816(acc2[mi][ng], al2[mi], bvh[nj][sel], bvh[nj][2+sel]);
            }
        }
    }
    float* ob = g_o + ((size_t)bh*Tc + c*CHc)*Dc;
    #pragma unroll
    for (int mi = 0; mi < 2; mi++) {
        #pragma unroll
        for (int ng = 0; ng < 4; ng++) {
            int tok = wm*32 + mi*16 + (lane >> 2);
            int d = wn*32 + ng*8 + (lane & 3)*2;
            *(float2*)(ob + (size_t)tok*64 + d)     = make_float2(acc2[mi][ng][0], acc2[mi][ng][1]);
            *(float2*)(ob + (size_t)(tok+8)*64 + d) = make_float2(acc2[mi][ng][2], acc2[mi][ng][3]);
        }
    }
}

// ---------------- hist (HMMA): ctx = qf @ kv_state^T, + nrm finalize --------
__global__ __launch_bounds__(256, 2) void hist_mma_k()
{
    extern __shared__ char sm[];
    __shared__ float ks_sm[512];
    __shared__ float nrm_sm[128];
    u32 sb = smem_u32(sm);
    int bhc = blockIdx.x;
    int bh = bhc >> 5, c = bhc & 31;
    int tid = threadIdx.x, lane = tid & 31, warp = tid >> 5;
    int wm = warp >> 1, wn = warp & 1;

    const __nv_bfloat16* qh = g_qfh + (size_t)bhc*CHc*PMc;
    const __nv_bfloat16* ql = g_qfl + (size_t)bhc*CHc*PMc;
    const __nv_bfloat16* kvh = g_ckvh + (size_t)bhc*PMc*Dc;
    const __nv_bfloat16* kvl = g_ckvl + (size_t)bhc*PMc*Dc;
    const float* ksb = g_ks + (size_t)bhc*PMc;
    ks_sm[tid] = ksb[tid];
    ks_sm[tid+256] = ksb[tid+256];

    int r0 = (tid*2) >> 2, s0 = (tid*2) & 3;
    int r1 = (tid*2+1) >> 2, s1 = (tid*2+1) & 3;
    int kvr = tid >> 3, kvs = tid & 7;
    int lr = lane & 7;
    int a_row = lr + (((lane >> 3) & 1) << 3);
    int a_col = ((lane >> 4) & 1) << 3;
    int t_row = lr + (((lane >> 4) & 1) << 3);
    int t_colbit = ((lane >> 3) & 1) << 3;

    float acc[2][4][4];
    #pragma unroll
    for (int i = 0; i < 2; i++)
        #pragma unroll
        for (int j = 0; j < 4; j++)
            #pragma unroll
            for (int q = 0; q < 4; q++) acc[i][j][q] = 0.f;
    float nacc = 0.f;

    auto load_chunk = [&](int ch, int stage) {
        int k0 = ch * 32;
        u32 st = sb + stage * 29696;
        u32 d0 = st + r0*80 + s0*16;
        u32 d1 = st + r1*80 + s1*16;
        CP_ASYNC16(d0,         qh + (size_t)r0*PMc + k0 + s0*8);
        CP_ASYNC16(d1,         qh + (size_t)r1*PMc + k0 + s1*8);
        CP_ASYNC16(d0 + 10240, ql + (size_t)r0*PMc + k0 + s0*8);
        CP_ASYNC16(d1 + 10240, ql + (size_t)r1*PMc + k0 + s1*8);
        u32 dk = st + 20480 + kvr*144 + kvs*16;
        CP_ASYNC16(dk,        kvh + (size_t)(k0+kvr)*64 + kvs*8);
        CP_ASYNC16(dk + 4608, kvl + (size_t)(k0+kvr)*64 + kvs*8);
        CP_COMMIT();
    };

    load_chunk(0, 0);
    for (int ch = 0; ch < 16; ch++) {
        int stage = ch & 1;
        if (ch + 1 < 16) { load_chunk(ch + 1, stage ^ 1); CP_WAIT1(); }
        else             { CP_WAIT0(); }
        __syncthreads();
        u32 st = sb + stage * 29696;
        #pragma unroll
        for (int ks16 = 0; ks16 < 2; ks16++) {
            u32 afh[2][4], afl[2][4], bvh[2][4], bvl[2][4];
            #pragma unroll
            for (int mi = 0; mi < 2; mi++) {
                u32 addr = st + ((wm*32 + mi*16 + a_row)*40 + ks16*16 + a_col)*2;
                ldsm4(afh[mi][0], afh[mi][1], afh[mi][2], afh[mi][3], addr);
                ldsm4(afl[mi][0], afl[mi][1], afl[mi][2], afl[mi][3], addr + 10240);
            }
            int krow = ks16*16 + t_row;
            #pragma unroll
            for (int nj = 0; nj < 2; nj++) {
                int dc = wn*32 + nj*16 + t_colbit;
                u32 addr = st + 20480 + krow*144 + dc*2;
                ldsm4t(bvh[nj][0], bvh[nj][1], bvh[nj][2], bvh[nj][3], addr);
                ldsm4t(bvl[nj][0], bvl[nj][1], bvl[nj][2], bvl[nj][3], addr + 4608);
            }
            #pragma unroll
            for (int mi = 0; mi < 2; mi++) {
                #pragma unroll
                for (int ng = 0; ng < 4; ng++) {
                    int nj = ng >> 1, sel = ng & 1;
                    mma16816(acc[mi][ng], afh[mi], bvh[nj][sel], bvh[nj][2+sel]);
                    mma16816(acc[mi][ng], afh[mi], bvl[nj][sel], bvl[nj][2+sel]);
                    mma16816(acc[mi][ng], afl[mi], bvh[nj][sel], bvh[nj][2+sel]);
                }
            }
        }
        {
            int tt = tid >> 1, fh = (tid & 1)*16;
            const __nv_bfloat16* qhs = (const __nv_bfloat16*)(sm + stage*29696 + tt*80);
            const __nv_bfloat16* qls = (const __nv_bfloat16*)(sm + stage*29696 + 10240 + tt*80);
            #pragma unroll
            for (int f = 0; f < 16; f++) {
                int fl = fh + f;
                float qv = __bfloat162float(qhs[fl]) + __bfloat162float(qls[fl]);
                nacc += qv * ks_sm[ch*32 + fl];
            }
        }
        __syncthreads();
    }
    nacc += __shfl_xor_sync(0xffffffffu, nacc, 1);
    if ((tid & 1) == 0) nrm_sm[tid >> 1] = nacc;
    __syncthreads();
    if (tid < 128) {
        float tot = nrm_sm[tid] + g_nrm[(size_t)bh*Tc + c*CHc + tid] + 1e-6f;
        nrm_sm[tid] = 1.f / tot;
    }
    __syncthreads();

    float* ob = g_o + ((size_t)bh*Tc + c*CHc)*Dc;
    #pragma unroll
    for (int mi = 0; mi < 2; mi++) {
        #pragma unroll
        for (int ng = 0; ng < 4; ng++) {
            int tok = wm*32 + mi*16 + (lane >> 2);
            int d = wn*32 + ng*8 + (lane & 3)*2;
            float inv0 = nrm_sm[tok], inv1 = nrm_sm[tok+8];
            float2* p0 = (float2*)(ob + (size_t)tok*64 + d);
            float2* p1 = (float2*)(ob + (size_t)(tok+8)*64 + d);
            float2 c0 = *p0, c1 = *p1;
            c0.x = (c0.x + acc[mi][ng][0]) * inv0;
            c0.y = (c0.y + acc[mi][ng][1]) * inv0;
            c1.x = (c1.x + acc[mi][ng][2]) * inv1;
            c1.y = (c1.y + acc[mi][ng][3]) * inv1;
            *p0 = c0; *p1 = c1;
        }
    }
}

// ---------------- host launcher ---------------------------------------------
extern "C" void kernel_launch(void* const* d_in, const int* in_sizes, int n_in,
                              void* d_out, int out_size)
{
    const float* x        = (const float*)d_in[0];
    const float* qkv_w    = (const float*)d_in[1];
    const float* qkv_b    = (const float*)d_in[2];
    const float* out_w    = (const float*)d_in[3];
    const float* out_b    = (const float*)d_in[4];
    const float* omega    = (const float*)d_in[5];
    const float* poly_w   = (const float*)d_in[6];
    const float* qnodes   = (const float*)d_in[7];
    const float* qweights = (const float*)d_in[8];
    float* out = (float*)d_out;

    float* qkv_ptr = 0;
    cudaGetSymbolAddress((void**)&qkv_ptr, g_qkv);
    __nv_bfloat16 *ah, *al, *wh, *wl;
    cudaGetSymbolAddress((void**)&ah, g_ah);
    cudaGetSymbolAddress((void**)&al, g_al);
    cudaGetSymbolAddress((void**)&wh, g_wh);
    cudaGetSymbolAddress((void**)&wl, g_wl);

    cudaFuncSetAttribute(gemm_mma_k, cudaFuncAttributeMaxDynamicSharedMemorySize, 2*S_STAGE);
    cudaFuncSetAttribute(features_k, cudaFuncAttributeMaxDynamicSharedMemorySize, F_SMEM);
    cudaFuncSetAttribute(passA_mma_k, cudaFuncAttributeMaxDynamicSharedMemorySize, 106496);
    cudaFuncSetAttribute(scores_mma_k, cudaFuncAttributeMaxDynamicSharedMemorySize, 106496);
    cudaFuncSetAttribute(hist_mma_k, cudaFuncAttributeMaxDynamicSharedMemorySize, 59392);

    // 1) split operands to bf16 hi/lo
    split_bf16_k<<<(Bc*Tc*Ec)/1024, 256>>>(x, ah, al);
    split_bf16_k<<<(3*Ec*Ec)/1024, 256>>>(qkv_w, wh, wl);
    // 2) QKV GEMM (HMMA)
    gemm_mma_k<<<dim3(3*Ec/128, (Bc*Tc)/128), 256, 2*S_STAGE>>>(
        ah, al, wh, wl, qkv_b, qkv_ptr, 3*Ec);
    // 3) feature maps (coalesced stores, poly_w in smem)
    features_k<<<dim3(BHc*NCc, 2), 256, F_SMEM>>>(omega, poly_w, qnodes, qweights);
    // 4) per-chunk kv + ks (HMMA, v from g_qkv)
    passA_mma_k<<<dim3(BHc*NCc, 4), 256, 106496>>>();
    // 5) fused exclusive prefix + bf16 convert
    prefix_kv_cvt_k<<<(BHc*PMc*Dc)/1024, 256>>>();
    prefix_ks_k<<<(BHc*PMc)/1024, 256>>>();
    // 6) intra-chunk scores + intra context (HMMA)
    scores_mma_k<<<BHc*NCc, 256, 106496>>>();
    // 7) history context + normalize (HMMA)
    hist_mma_k<<<BHc*NCc, 256, 59392>>>();
    // 8) output projection (HMMA)
    o2rows_k<<<(BHc*Tc*Dc)/512, 256>>>();
    split_bf16_k<<<(Ec*Ec)/1024, 256>>>(out_w, wh, wl);
    gemm_mma_k<<<dim3(Ec/128, (Bc*Tc)/128), 256, 2*S_STAGE>>>(
        ah, al, wh, wl, out_b, out, Ec);
}

// round 9
// speedup vs baseline: 2.8899x; 1.1465x over previous
#include <cuda_runtime.h>
#include <cuda_bf16.h>
#include <math.h>

#define Bc 2
#define Tc 4096
#define Ec 1024
#define Hc 16
#define Dc 64
#define Pc 64
#define PMc 512
#define CHc 128
#define NCc 32
#define BHc 32

typedef unsigned long long u64;
typedef unsigned int u32;

// ---------------- scratch (device globals; no allocations allowed) ----------
__device__ float g_qkv[(size_t)Bc*Tc*3*Ec];
__device__ float g_ckv[(size_t)BHc*NCc*PMc*Dc];      // (bhc, f, d) fp32 per-chunk
__device__ float g_ks [(size_t)BHc*NCc*PMc];
__device__ float g_o  [(size_t)BHc*Tc*Dc];
__device__ float g_nrm[(size_t)BHc*Tc];
// bf16 hi/lo features, [bhc][token 128][feature 512]
__device__ __align__(16) __nv_bfloat16 g_qfh[(size_t)BHc*NCc*CHc*PMc];
__device__ __align__(16) __nv_bfloat16 g_qfl[(size_t)BHc*NCc*CHc*PMc];
__device__ __align__(16) __nv_bfloat16 g_kfh[(size_t)BHc*NCc*CHc*PMc];
__device__ __align__(16) __nv_bfloat16 g_kfl[(size_t)BHc*NCc*CHc*PMc];
// bf16 hi/lo exclusive kv state, [bhc][f][d]
__device__ __align__(16) __nv_bfloat16 g_ckvh[(size_t)BHc*NCc*PMc*Dc];
__device__ __align__(16) __nv_bfloat16 g_ckvl[(size_t)BHc*NCc*PMc*Dc];
// bf16 split operands for dense GEMMs
__device__ __align__(16) __nv_bfloat16 g_ah[(size_t)Bc*Tc*Ec];
__device__ __align__(16) __nv_bfloat16 g_al[(size_t)Bc*Tc*Ec];
__device__ __align__(16) __nv_bfloat16 g_wh[(size_t)3*Ec*Ec];
__device__ __align__(16) __nv_bfloat16 g_wl[(size_t)3*Ec*Ec];

// ================= helpers ===================================================
__device__ __forceinline__ u32 smem_u32(const void* p) {
    u32 a; asm("{ .reg .u64 t; cvta.to.shared.u64 t, %1; cvt.u32.u64 %0, t; }"
               : "=r"(a) : "l"(p));
    return a;
}
#define CP_ASYNC16(dst, src) \
    asm volatile("cp.async.cg.shared.global [%0], [%1], 16;\n" :: "r"(dst), "l"(src))
#define CP_COMMIT() asm volatile("cp.async.commit_group;\n" ::: "memory")
#define CP_WAIT1()  asm volatile("cp.async.wait_group 1;\n" ::: "memory")
#define CP_WAIT0()  asm volatile("cp.async.wait_group 0;\n" ::: "memory")

__device__ __forceinline__ void ldsm4(u32 &r0, u32 &r1, u32 &r2, u32 &r3, u32 a) {
    asm volatile("ldmatrix.sync.aligned.m8n8.x4.shared.b16 {%0,%1,%2,%3}, [%4];\n"
                 : "=r"(r0), "=r"(r1), "=r"(r2), "=r"(r3) : "r"(a));
}
__device__ __forceinline__ void ldsm4t(u32 &r0, u32 &r1, u32 &r2, u32 &r3, u32 a) {
    asm volatile("ldmatrix.sync.aligned.m8n8.x4.trans.shared.b16 {%0,%1,%2,%3}, [%4];\n"
                 : "=r"(r0), "=r"(r1), "=r"(r2), "=r"(r3) : "r"(a));
}
__device__ __forceinline__ void mma16816(float* c, const u32* a, u32 b0, u32 b1) {
    asm volatile(
        "mma.sync.aligned.m16n8k16.row.col.f32.bf16.bf16.f32 "
        "{%0,%1,%2,%3},{%4,%5,%6,%7},{%8,%9},{%0,%1,%2,%3};\n"
        : "+f"(c[0]), "+f"(c[1]), "+f"(c[2]), "+f"(c[3])
        : "r"(a[0]), "r"(a[1]), "r"(a[2]), "r"(a[3]), "r"(b0), "r"(b1));
}

// ================= fp32 -> bf16 hi/lo split ==================================
__global__ void split_bf16_k(const float* __restrict__ s,
                             __nv_bfloat16* __restrict__ h,
                             __nv_bfloat16* __restrict__ l)
{
    size_t i = ((size_t)blockIdx.x*256 + threadIdx.x)*4;
    float4 v = *(const float4*)(s + i);
    __nv_bfloat16 h0=__float2bfloat16(v.x), h1=__float2bfloat16(v.y);
    __nv_bfloat16 h2=__float2bfloat16(v.z), h3=__float2bfloat16(v.w);
    __nv_bfloat162 ha = {h0,h1}, hb = {h2,h3};
    __nv_bfloat162 la = {__float2bfloat16(v.x-__bfloat162float(h0)),
                         __float2bfloat16(v.y-__bfloat162float(h1))};
    __nv_bfloat162 lb = {__float2bfloat16(v.z-__bfloat162float(h2)),
                         __float2bfloat16(v.w-__bfloat162float(h3))};
    *(__nv_bfloat162*)(h+i) = ha; *(__nv_bfloat162*)(h+i+2) = hb;
    *(__nv_bfloat162*)(l+i) = la; *(__nv_bfloat162*)(l+i+2) = lb;
}

// ------ reshape g_o (B,H,T,D) -> rows (b*T+t, h*64+d), bf16 hi/lo ------------
__global__ void o2rows_k()
{
    size_t gidx = ((size_t)blockIdx.x*256 + threadIdx.x)*2;
    float2 v = *(const float2*)(g_o + gidx);
    int d = (int)(gidx & 63), t = (int)((gidx >> 6) & 4095);
    int h = (int)((gidx >> 18) & 15), b = (int)(gidx >> 22);
    size_t dst = ((size_t)(b*Tc + t))*Ec + h*64 + d;
    __nv_bfloat16 h0=__float2bfloat16(v.x), h1=__float2bfloat16(v.y);
    *(__nv_bfloat162*)(g_ah+dst) = {h0,h1};
    *(__nv_bfloat162*)(g_al+dst) = {__float2bfloat16(v.x-__bfloat162float(h0)),
                                    __float2bfloat16(v.y-__bfloat162float(h1))};
}

// ================= HMMA GEMM: C[M,N] = A @ W^T + bias (bf16x3 split) ========
#define S_STRIDE 40
#define S_ARR 10240
#define S_STAGE 40960

__global__ __launch_bounds__(256, 2)
void gemm_mma_k(const __nv_bfloat16* __restrict__ Abase_h,
                const __nv_bfloat16* __restrict__ Abase_l,
                const __nv_bfloat16* __restrict__ Wbase_h,
                const __nv_bfloat16* __restrict__ Wbase_l,
                const float* __restrict__ bias, float* __restrict__ C, int N)
{
    extern __shared__ char smem[];
    u32 sb = smem_u32(smem);
    const int K = 1024;
    int tid = threadIdx.x;
    int lane = tid & 31, warp = tid >> 5;
    int wm = warp >> 1, wn = warp & 1;
    int bm = blockIdx.y * 128, bn = blockIdx.x * 128;

    const __nv_bfloat16* Ah = Abase_h + (size_t)bm * K;
    const __nv_bfloat16* Al = Abase_l + (size_t)bm * K;
    const __nv_bfloat16* Wh = Wbase_h + (size_t)bn * K;
    const __nv_bfloat16* Wl = Wbase_l + (size_t)bn * K;

    int r0 = (tid*2) >> 2, s0 = (tid*2) & 3;
    int r1 = (tid*2+1) >> 2, s1 = (tid*2+1) & 3;

    int lr = lane & 7;
    int a_row = lr + (((lane >> 3) & 1) << 3);
    int a_col = ((lane >> 4) & 1) << 3;
    int b_row = lr + (((lane >> 4) & 1) << 3);
    int b_col = ((lane >> 3) & 1) << 3;

    float acc[2][8][4];
    #pragma unroll
    for (int i = 0; i < 2; i++)
        #pragma unroll
        for (int j = 0; j < 8; j++)
            #pragma unroll
            for (int q = 0; q < 4; q++) acc[i][j][q] = 0.f;

    auto load_chunk = [&](int ch, int stage) {
        int k0 = ch * 32;
        u32 st = sb + stage * S_STAGE;
        u32 d0 = st + r0*80 + s0*16;
        u32 d1 = st + r1*80 + s1*16;
        CP_ASYNC16(d0, Ah + (size_t)r0*K + k0 + s0*8);
        CP_ASYNC16(d1, Ah + (size_t)r1*K + k0 + s1*8);
        CP_ASYNC16(d0 + S_ARR, Al + (size_t)r0*K + k0 + s0*8);
        CP_ASYNC16(d1 + S_ARR, Al + (size_t)r1*K + k0 + s1*8);
        CP_ASYNC16(d0 + 2*S_ARR, Wh + (size_t)r0*K + k0 + s0*8);
        CP_ASYNC16(d1 + 2*S_ARR, Wh + (size_t)r1*K + k0 + s1*8);
        CP_ASYNC16(d0 + 3*S_ARR, Wl + (size_t)r0*K + k0 + s0*8);
        CP_ASYNC16(d1 + 3*S_ARR, Wl + (size_t)r1*K + k0 + s1*8);
        CP_COMMIT();
    };

    load_chunk(0, 0);

    for (int ch = 0; ch < 32; ch++) {
        int stage = ch & 1;
        if (ch + 1 < 32) { load_chunk(ch + 1, stage ^ 1); CP_WAIT1(); }
        else             { CP_WAIT0(); }
        __syncthreads();

        u32 st = sb + stage * S_STAGE;
        #pragma unroll
        for (int ks = 0; ks < 2; ks++) {
            u32 afh[2][4], afl[2][4], bfh[4][4], bfl[4][4];
            #pragma unroll
            for (int mi = 0; mi < 2; mi++) {
                u32 addr = st + ((wm*32 + mi*16 + a_row)*S_STRIDE + ks*16 + a_col)*2;
                ldsm4(afh[mi][0], afh[mi][1], afh[mi][2], afh[mi][3], addr);
                ldsm4(afl[mi][0], afl[mi][1], afl[mi][2], afl[mi][3], addr + S_ARR);
            }
            #pragma unroll
            for (int nj = 0; nj < 4; nj++) {
                u32 addr = st + 2*S_ARR +
                           ((wn*64 + nj*16 + b_row)*S_STRIDE + ks*16 + b_col)*2;
                ldsm4(bfh[nj][0], bfh[nj][1], bfh[nj][2], bfh[nj][3], addr);
                ldsm4(bfl[nj][0], bfl[nj][1], bfl[nj][2], bfl[nj][3], addr + S_ARR);
            }
            #pragma unroll
            for (int mi = 0; mi < 2; mi++) {
                #pragma unroll
                for (int ni = 0; ni < 8; ni++) {
                    int nj = ni >> 1, off = (ni & 1) << 1;
                    mma16816(acc[mi][ni], afh[mi], bfh[nj][off], bfh[nj][off+1]);
                    mma16816(acc[mi][ni], afh[mi], bfl[nj][off], bfl[nj][off+1]);
                    mma16816(acc[mi][ni], afl[mi], bfh[nj][off], bfh[nj][off+1]);
                }
            }
        }
        __syncthreads();
    }

    #pragma unroll
    for (int mi = 0; mi < 2; mi++) {
        #pragma unroll
        for (int ni = 0; ni < 8; ni++) {
            int m = bm + wm*32 + mi*16 + (lane >> 2);
            int n = bn + wn*64 + ni*8 + (lane & 3)*2;
            float2 o0, o1;
            o0.x = acc[mi][ni][0] + bias[n];
            o0.y = acc[mi][ni][1] + bias[n+1];
            o1.x = acc[mi][ni][2] + bias[n];
            o1.y = acc[mi][ni][3] + bias[n+1];
            *(float2*)(C + (size_t)m*N + n)     = o0;
            *(float2*)(C + (size_t)(m+8)*N + n) = o1;
        }
    }
}

// ---------------- feature map -> bf16 hi/lo [token][feature] ----------------
// v3: strided p-column ownership -> perfectly coalesced stores; poly_w in smem
// dynamic smem layout: xs[128*68] | ps[64*68] | om[512] | prf[1024] | rn[128]
#define F_XS   0
#define F_PS   (128*68)
#define F_OM   (F_PS + 64*68)
#define F_PRF  (F_OM + 512)
#define F_RN   (F_PRF + 1024)
#define F_SMEM ((F_RN + 128)*4)

__global__ __launch_bounds__(256, 3) void features_k(
    const float* __restrict__ omega, const float* __restrict__ poly_w,
    const float* __restrict__ qnodes, const float* __restrict__ qweights)
{
    extern __shared__ float fsm[];
    float* xs  = fsm + F_XS;           // [token][68]
    float* ps  = fsm + F_PS;           // [d][68]
    float* om  = fsm + F_OM;
    float* prf = fsm + F_PRF;
    float* rn  = fsm + F_RN;
    int bhc = blockIdx.x;
    int isK = blockIdx.y;
    int bh = bhc >> 5, c = bhc & 31;
    int h = bh & 15, b = bh >> 4;
    const float* src = g_qkv + ((size_t)(b*Tc + c*CHc))*(3*Ec) + isK*Ec + h*64;
    __nv_bfloat16* dh = (isK ? g_kfh : g_qfh) + (size_t)bhc*CHc*PMc;
    __nv_bfloat16* dl = (isK ? g_kfl : g_qfl) + (size_t)bhc*CHc*PMc;
    int tid = threadIdx.x;
    #pragma unroll
    for (int l = 0; l < 8; l++) {
        int idx = tid + l*256;         // < 2048
        int i = idx >> 4, dd = (idx & 15) << 2;
        float4 v = *(const float4*)(src + (size_t)i*(3*Ec) + dd);
        *(float4*)&xs[i*68 + dd] = v;
    }
    {
        const float* pwp = poly_w + h*4096;
        #pragma unroll
        for (int l = 0; l < 4; l++) {
            int idx = tid + l*256;     // < 1024 float4s
            int d = idx >> 4, pc = (idx & 15) << 2;
            *(float4*)&ps[d*68 + pc] = *(const float4*)(pwp + d*64 + pc);
        }
    }
    om[tid]       = omega[h*512 + tid];
    om[tid + 256] = omega[h*512 + tid + 256];
    __syncthreads();
    if (tid < 128) {
        const float* xr = &xs[tid*68];
        float s = 0.f;
        #pragma unroll
        for (int d = 0; d < 64; d++) { float x = xr[d]; s += x*x; }
        rn[tid] = 1.f / fmaxf(sqrtf(s), 1e-12f);
    }
    __syncthreads();
    float s0 = qnodes[0];
    float sq2s = sqrtf(fmaxf(2.f*s0, 0.f));
    float wq = sqrtf(fmaxf(qweights[0], 0.f));
    float prescale = 0.3535533905932738f * wq;
    #pragma unroll
    for (int l = 0; l < 4; l++) {
        int pair = tid + l*256;
        int i = pair >> 3, m = pair & 7;
        const float* xr = &xs[i*68];
        float a = 0.f;
        #pragma unroll
        for (int d = 0; d < 64; d++) a += xr[d] * om[d*8 + m];
        float e = fminf(fmaxf(a * rn[i] * sq2s - s0, -20.f), 20.f);
        prf[i*8 + m] = expf(e) * prescale;
    }
    __syncthreads();
    // thread owns tokens [ti, ti+8) and p-columns {tp, tp+16, tp+32, tp+48}
    int ti = (tid >> 4) << 3, tp = tid & 15;
    float acc[8][4] = {};
    for (int d = 0; d < 64; d++) {
        float a[8];
        #pragma unroll
        for (int x = 0; x < 8; x++) a[x] = xs[(ti+x)*68 + d];
        float b0 = ps[d*68 + tp];
        float b1 = ps[d*68 + tp + 16];
        float b2 = ps[d*68 + tp + 32];
        float b3 = ps[d*68 + tp + 48];
        #pragma unroll
        for (int i2 = 0; i2 < 8; i2++) {
            acc[i2][0] += a[i2]*b0; acc[i2][1] += a[i2]*b1;
            acc[i2][2] += a[i2]*b2; acc[i2][3] += a[i2]*b3;
        }
    }
    #pragma unroll
    for (int i2 = 0; i2 < 8; i2++) {
        float r = rn[ti + i2];
        #pragma unroll
        for (int j = 0; j < 4; j++) {
            float t = acc[i2][j] * r;
            acc[i2][j] = t*t*0.125f;
        }
    }
    // epilogue: for fixed (i2,j) lanes 0..15 write contiguous 256B segments
    #pragma unroll
    for (int i2 = 0; i2 < 8; i2++) {
        int tok = ti + i2;
        const float* pr = &prf[tok*8];
        #pragma unroll
        for (int j = 0; j < 4; j++) {
            float base = acc[i2][j];
            __nv_bfloat16 hb[8], lb[8];
            #pragma unroll
            for (int m = 0; m < 8; m++) {
                float v = base * pr[m];
                __nv_bfloat16 hh = __float2bfloat16(v);
                hb[m] = hh;
                lb[m] = __float2bfloat16(v - __bfloat162float(hh));
            }
            size_t off = (size_t)tok*PMc + (tp + j*16)*8;
            *(uint4*)(dh + off) = *(uint4*)hb;
            *(uint4*)(dl + off) = *(uint4*)lb;
        }
    }
}

// ---------------- pass A (HMMA): kv[f][d] = sum_i kf[i][f] v[i][d] ----------
__global__ __launch_bounds__(256, 2) void passA_mma_k()
{
    extern __shared__ char sm[];
    u32 sb = smem_u32(sm);
    const u32 KFH = 0, KFL = 34816, VH = 69632, VL = 88064;
    int bhc = blockIdx.x, fb = blockIdx.y;
    int bh = bhc >> 5, c = bhc & 31;
    int tid = threadIdx.x, lane = tid & 31, warp = tid >> 5;
    int wm = warp >> 1, wn = warp & 1;

    const __nv_bfloat16* kh = g_kfh + (size_t)bhc*CHc*PMc + fb*128;
    const __nv_bfloat16* kl = g_kfl + (size_t)bhc*CHc*PMc + fb*128;
    #pragma unroll
    for (int l = 0; l < 8; l++) {
        int idx = tid + l*256;
        int row = idx >> 4, seg = idx & 15;
        u32 d = sb + KFH + row*272 + seg*16;
        CP_ASYNC16(d,              kh + (size_t)row*PMc + seg*8);
        CP_ASYNC16(d + (KFL-KFH),  kl + (size_t)row*PMc + seg*8);
    }
    CP_COMMIT();
    const float* vb = g_qkv + ((size_t)((bh>>4)*Tc + c*CHc))*(3*Ec) + 2*Ec + (bh&15)*64;
    #pragma unroll
    for (int l = 0; l < 8; l++) {
        int idx = tid + l*256;
        int i = idx >> 4, dd = (idx & 15)*4;
        float4 v = *(const float4*)(vb + (size_t)i*(3*Ec) + dd);
        __nv_bfloat16 h0=__float2bfloat16(v.x), h1=__float2bfloat16(v.y);
        __nv_bfloat16 h2=__float2bfloat16(v.z), h3=__float2bfloat16(v.w);
        u32 off = i*144 + dd*2;
        *(__nv_bfloat162*)(sm + VH + off)     = {h0,h1};
        *(__nv_bfloat162*)(sm + VH + off + 4) = {h2,h3};
        *(__nv_bfloat162*)(sm + VL + off)     = {__float2bfloat16(v.x-__bfloat162float(h0)),
                                                 __float2bfloat16(v.y-__bfloat162float(h1))};
        *(__nv_bfloat162*)(sm + VL + off + 4) = {__float2bfloat16(v.z-__bfloat162float(h2)),
                                                 __float2bfloat16(v.w-__bfloat162float(h3))};
    }
    CP_WAIT0();
    __syncthreads();

    if (tid < 128) {
        float s = 0.f;
        for (int i = 0; i < 128; i++) {
            s += __bfloat162float(*(const __nv_bfloat16*)(sm + KFH + i*272 + tid*2));
            s += __bfloat162float(*(const __nv_bfloat16*)(sm + KFL + i*272 + tid*2));
        }
        g_ks[(size_t)bhc*PMc + fb*128 + tid] = s;
    }

    int t_row = (lane & 7) + (((lane >> 4) & 1) << 3);
    int t_colbit = ((lane >> 3) & 1) << 3;

    float acc[2][4][4];
    #pragma unroll
    for (int i = 0; i < 2; i++)
        #pragma unroll
        for (int j = 0; j < 4; j++)
            #pragma unroll
            for (int q = 0; q < 4; q++) acc[i][j][q] = 0.f;

    #pragma unroll
    for (int ks16 = 0; ks16 < 8; ks16++) {
        int krow = ks16*16 + t_row;
        u32 afh[2][4], afl[2][4], bvh[2][4], bvl[2][4];
        #pragma unroll
        for (int mi = 0; mi < 2; mi++) {
            int fc = wm*32 + mi*16 + t_colbit;
            u32 addr = sb + KFH + krow*272 + fc*2;
            ldsm4t(afh[mi][0], afh[mi][1], afh[mi][2], afh[mi][3], addr);
            ldsm4t(afl[mi][0], afl[mi][1], afl[mi][2], afl[mi][3], addr + (KFL-KFH));
        }
        #pragma unroll
        for (int nj = 0; nj < 2; nj++) {
            int dc = wn*32 + nj*16 + t_colbit;
            u32 addr = sb + VH + krow*144 + dc*2;
            ldsm4t(bvh[nj][0], bvh[nj][1], bvh[nj][2], bvh[nj][3], addr);
            ldsm4t(bvl[nj][0], bvl[nj][1], bvl[nj][2], bvl[nj][3], addr + (VL-VH));
        }
        #pragma unroll
        for (int mi = 0; mi < 2; mi++) {
            #pragma unroll
            for (int ng = 0; ng < 4; ng++) {
                int nj = ng >> 1, sel = ng & 1;
                mma16816(acc[mi][ng], afh[mi], bvh[nj][sel], bvh[nj][2+sel]);
                mma16816(acc[mi][ng], afh[mi], bvl[nj][sel], bvl[nj][2+sel]);
                mma16816(acc[mi][ng], afl[mi], bvh[nj][sel], bvh[nj][2+sel]);
            }
        }
    }
    float* outp = g_ckv + (size_t)bhc*PMc*Dc + (size_t)fb*128*Dc;
    #pragma unroll
    for (int mi = 0; mi < 2; mi++) {
        #pragma unroll
        for (int ng = 0; ng < 4; ng++) {
            int f = wm*32 + mi*16 + (lane >> 2);
            int d = wn*32 + ng*8 + (lane & 3)*2;
            *(float2*)(outp + (size_t)f*64 + d)     = make_float2(acc[mi][ng][0], acc[mi][ng][1]);
            *(float2*)(outp + (size_t)(f+8)*64 + d) = make_float2(acc[mi][ng][2], acc[mi][ng][3]);
        }
    }
}

// ------- fused exclusive prefix over chunks + bf16 hi/lo convert -------------
__global__ void prefix_kv_cvt_k()
{
    size_t e = ((size_t)blockIdx.x*256 + threadIdx.x)*4;
    size_t bh = e / (PMc*Dc);
    size_t rem = e % (PMc*Dc);
    float4 acc = make_float4(0.f,0.f,0.f,0.f);
    #pragma unroll
    for (int c = 0; c < NCc; c++) {
        size_t p = (bh*NCc + c)*(size_t)(PMc*Dc) + rem;
        float4 v = *(const float4*)(g_ckv + p);
        __nv_bfloat16 h0=__float2bfloat16(acc.x), h1=__float2bfloat16(acc.y);
        __nv_bfloat16 h2=__float2bfloat16(acc.z), h3=__float2bfloat16(acc.w);
        *(__nv_bfloat162*)(g_ckvh+p)   = {h0,h1};
        *(__nv_bfloat162*)(g_ckvh+p+2) = {h2,h3};
        *(__nv_bfloat162*)(g_ckvl+p)   = {__float2bfloat16(acc.x-__bfloat162float(h0)),
                                          __float2bfloat16(acc.y-__bfloat162float(h1))};
        *(__nv_bfloat162*)(g_ckvl+p+2) = {__float2bfloat16(acc.z-__bfloat162float(h2)),
                                          __float2bfloat16(acc.w-__bfloat162float(h3))};
        acc.x += v.x; acc.y += v.y; acc.z += v.z; acc.w += v.w;
    }
}
__global__ void prefix_ks_k()
{
    size_t e = ((size_t)blockIdx.x*256 + threadIdx.x)*4;
    size_t bh = e / PMc;
    size_t rem = e % PMc;
    float4 acc = make_float4(0.f,0.f,0.f,0.f);
    #pragma unroll
    for (int c = 0; c < NCc; c++) {
        size_t p = (bh*NCc + c)*(size_t)PMc + rem;
        float4 v = *(const float4*)(g_ks + p);
        *(float4*)(g_ks + p) = acc;
        acc.x += v.x; acc.y += v.y; acc.z += v.z; acc.w += v.w;
    }
}

// ---------------- scores (HMMA): S = qf kf^T, mask, rowsum, intra = S v -----
__global__ __launch_bounds__(256, 2) void scores_mma_k()
{
    extern __shared__ char sm[];
    __shared__ float rowsum[128];
    u32 sb = smem_u32(sm);
    int bhc = blockIdx.x;
    int bh = bhc >> 5, c = bhc & 31;
    int tid = threadIdx.x, lane = tid & 31, warp = tid >> 5;
    int wm = warp >> 1, wn = warp & 1;
    if (tid < 128) rowsum[tid] = 0.f;

    const __nv_bfloat16* qh = g_qfh + (size_t)bhc*CHc*PMc;
    const __nv_bfloat16* ql = g_qfl + (size_t)bhc*CHc*PMc;
    const __nv_bfloat16* kh = g_kfh + (size_t)bhc*CHc*PMc;
    const __nv_bfloat16* kl = g_kfl + (size_t)bhc*CHc*PMc;

    int r0 = (tid*2) >> 2, s0 = (tid*2) & 3;
    int r1 = (tid*2+1) >> 2, s1 = (tid*2+1) & 3;
    int lr = lane & 7;
    int a_row = lr + (((lane >> 3) & 1) << 3);
    int a_col = ((lane >> 4) & 1) << 3;
    int b_row = lr + (((lane >> 4) & 1) << 3);
    int b_col = ((lane >> 3) & 1) << 3;

    float acc[2][8][4];
    #pragma unroll
    for (int i = 0; i < 2; i++)
        #pragma unroll
        for (int j = 0; j < 8; j++)
            #pragma unroll
            for (int q = 0; q < 4; q++) acc[i][j][q] = 0.f;

    auto load_chunk = [&](int ch, int stage) {
        int k0 = ch * 32;
        u32 st = sb + stage * 40960;
        u32 d0 = st + r0*80 + s0*16;
        u32 d1 = st + r1*80 + s1*16;
        CP_ASYNC16(d0,         qh + (size_t)r0*PMc + k0 + s0*8);
        CP_ASYNC16(d1,         qh + (size_t)r1*PMc + k0 + s1*8);
        CP_ASYNC16(d0 + 10240, ql + (size_t)r0*PMc + k0 + s0*8);
        CP_ASYNC16(d1 + 10240, ql + (size_t)r1*PMc + k0 + s1*8);
        CP_ASYNC16(d0 + 20480, kh + (size_t)r0*PMc + k0 + s0*8);
        CP_ASYNC16(d1 + 20480, kh + (size_t)r1*PMc + k0 + s1*8);
        CP_ASYNC16(d0 + 30720, kl + (size_t)r0*PMc + k0 + s0*8);
        CP_ASYNC16(d1 + 30720, kl + (size_t)r1*PMc + k0 + s1*8);
        CP_COMMIT();
    };

    load_chunk(0, 0);
    for (int ch = 0; ch < 16; ch++) {
        int stage = ch & 1;
        if (ch + 1 < 16) { load_chunk(ch + 1, stage ^ 1); CP_WAIT1(); }
        else             { CP_WAIT0(); }
        __syncthreads();
        u32 st = sb + stage * 40960;
        #pragma unroll
        for (int ks = 0; ks < 2; ks++) {
            u32 afh[2][4], afl[2][4], bfh[4][4], bfl[4][4];
            #pragma unroll
            for (int mi = 0; mi < 2; mi++) {
                u32 addr = st + ((wm*32 + mi*16 + a_row)*40 + ks*16 + a_col)*2;
                ldsm4(afh[mi][0], afh[mi][1], afh[mi][2], afh[mi][3], addr);
                ldsm4(afl[mi][0], afl[mi][1], afl[mi][2], afl[mi][3], addr + 10240);
            }
            #pragma unroll
            for (int nj = 0; nj < 4; nj++) {
                u32 addr = st + 20480 + ((wn*64 + nj*16 + b_row)*40 + ks*16 + b_col)*2;
                ldsm4(bfh[nj][0], bfh[nj][1], bfh[nj][2], bfh[nj][3], addr);
                ldsm4(bfl[nj][0], bfl[nj][1], bfl[nj][2], bfl[nj][3], addr + 10240);
            }
            #pragma unroll
            for (int mi = 0; mi < 2; mi++) {
                #pragma unroll
                for (int ni = 0; ni < 8; ni++) {
                    int nj = ni >> 1, off = (ni & 1) << 1;
                    mma16816(acc[mi][ni], afh[mi], bfh[nj][off], bfh[nj][off+1]);
                    mma16816(acc[mi][ni], afh[mi], bfl[nj][off], bfl[nj][off+1]);
                    mma16816(acc[mi][ni], afl[mi], bfh[nj][off], bfh[nj][off+1]);
                }
            }
        }
        __syncthreads();
    }

    #pragma unroll
    for (int mi = 0; mi < 2; mi++) {
        float rs0 = 0.f, rs1 = 0.f;
        int ri0 = wm*32 + mi*16 + (lane >> 2);
        #pragma unroll
        for (int ni = 0; ni < 8; ni++) {
            int cj = wn*64 + ni*8 + (lane & 3)*2;
            float v00 = (cj   <= ri0)   ? acc[mi][ni][0] : 0.f;
            float v01 = (cj+1 <= ri0)   ? acc[mi][ni][1] : 0.f;
            float v10 = (cj   <= ri0+8) ? acc[mi][ni][2] : 0.f;
            float v11 = (cj+1 <= ri0+8) ? acc[mi][ni][3] : 0.f;
            rs0 += v00 + v01; rs1 += v10 + v11;
            __nv_bfloat16 h00=__float2bfloat16(v00), h01=__float2bfloat16(v01);
            __nv_bfloat16 h10=__float2bfloat16(v10), h11=__float2bfloat16(v11);
            u32 o0 = ri0*272 + cj*2, o1 = (ri0+8)*272 + cj*2;
            *(__nv_bfloat162*)(sm + o0)         = {h00,h01};
            *(__nv_bfloat162*)(sm + o1)         = {h10,h11};
            *(__nv_bfloat162*)(sm + 34816 + o0) = {__float2bfloat16(v00-__bfloat162float(h00)),
                                                   __float2bfloat16(v01-__bfloat162float(h01))};
            *(__nv_bfloat162*)(sm + 34816 + o1) = {__float2bfloat16(v10-__bfloat162float(h10)),
                                                   __float2bfloat16(v11-__bfloat162float(h11))};
        }
        rs0 += __shfl_xor_sync(0xffffffffu, rs0, 1);
        rs0 += __shfl_xor_sync(0xffffffffu, rs0, 2);
        rs1 += __shfl_xor_sync(0xffffffffu, rs1, 1);
        rs1 += __shfl_xor_sync(0xffffffffu, rs1, 2);
        if ((lane & 3) == 0) {
            atomicAdd(&rowsum[ri0], rs0);
            atomicAdd(&rowsum[ri0+8], rs1);
        }
    }
    const float* vb = g_qkv + ((size_t)((bh>>4)*Tc + c*CHc))*(3*Ec) + 2*Ec + (bh&15)*64;
    #pragma unroll
    for (int l = 0; l < 8; l++) {
        int idx = tid + l*256;
        int i = idx >> 4, dd = (idx & 15)*4;
        float4 v = *(const float4*)(vb + (size_t)i*(3*Ec) + dd);
        __nv_bfloat16 h0=__float2bfloat16(v.x), h1=__float2bfloat16(v.y);
        __nv_bfloat16 h2=__float2bfloat16(v.z), h3=__float2bfloat16(v.w);
        u32 off = 69632 + i*144 + dd*2;
        *(__nv_bfloat162*)(sm + off)     = {h0,h1};
        *(__nv_bfloat162*)(sm + off + 4) = {h2,h3};
        *(__nv_bfloat162*)(sm + off + (88064-69632))     = {__float2bfloat16(v.x-__bfloat162float(h0)),
                                                            __float2bfloat16(v.y-__bfloat162float(h1))};
        *(__nv_bfloat162*)(sm + off + (88064-69632) + 4) = {__float2bfloat16(v.z-__bfloat162float(h2)),
                                                            __float2bfloat16(v.w-__bfloat162float(h3))};
    }
    __syncthreads();
    if (tid < 128) g_nrm[(size_t)bh*Tc + c*CHc + tid] = rowsum[tid];

    int t_row = (lane & 7) + (((lane >> 4) & 1) << 3);
    int t_colbit = ((lane >> 3) & 1) << 3;
    float acc2[2][4][4];
    #pragma unroll
    for (int i = 0; i < 2; i++)
        #pragma unroll
        for (int j = 0; j < 4; j++)
            #pragma unroll
            for (int q = 0; q < 4; q++) acc2[i][j][q] = 0.f;

    #pragma unroll
    for (int ks16 = 0; ks16 < 8; ks16++) {
        u32 ah2[2][4], al2[2][4], bvh[2][4], bvl[2][4];
        #pragma unroll
        for (int mi = 0; mi < 2; mi++) {
            u32 addr = sb + ((wm*32 + mi*16 + a_row)*136 + ks16*16 + a_col)*2;
            ldsm4(ah2[mi][0], ah2[mi][1], ah2[mi][2], ah2[mi][3], addr);
            ldsm4(al2[mi][0], al2[mi][1], al2[mi][2], al2[mi][3], addr + 34816);
        }
        int krow = ks16*16 + t_row;
        #pragma unroll
        for (int nj = 0; nj < 2; nj++) {
            int dc = wn*32 + nj*16 + t_colbit;
            u32 addr = sb + 69632 + krow*144 + dc*2;
            ldsm4t(bvh[nj][0], bvh[nj][1], bvh[nj][2], bvh[nj][3], addr);
            ldsm4t(bvl[nj][0], bvl[nj][1], bvl[nj][2], bvl[nj][3], addr + (88064-69632));
        }
        #pragma unroll
        for (int mi = 0; mi < 2; mi++) {
            #pragma unroll
            for (int ng = 0; ng < 4; ng++) {
                int nj = ng >> 1, sel = ng & 1;
                mma16816(acc2[mi][ng], ah2[mi], bvh[nj][sel], bvh[nj][2+sel]);
                mma16816(acc2[mi][ng], ah2[mi], bvl[nj][sel], bvl[nj][2+sel]);
                mma16816(acc2[mi][ng], al2[mi], bvh[nj][sel], bvh[nj][2+sel]);
            }
        }
    }
    float* ob = g_o + ((size_t)bh*Tc + c*CHc)*Dc;
    #pragma unroll
    for (int mi = 0; mi < 2; mi++) {
        #pragma unroll
        for (int ng = 0; ng < 4; ng++) {
            int tok = wm*32 + mi*16 + (lane >> 2);
            int d = wn*32 + ng*8 + (lane & 3)*2;
            *(float2*)(ob + (size_t)tok*64 + d)     = make_float2(acc2[mi][ng][0], acc2[mi][ng][1]);
            *(float2*)(ob + (size_t)(tok+8)*64 + d) = make_float2(acc2[mi][ng][2], acc2[mi][ng][3]);
        }
    }
}

// ---------------- hist (HMMA): ctx = qf @ kv_state^T, + nrm finalize --------
__global__ __launch_bounds__(256, 2) void hist_mma_k()
{
    extern __shared__ char sm[];
    __shared__ float ks_sm[512];
    __shared__ float nrm_sm[128];
    u32 sb = smem_u32(sm);
    int bhc = blockIdx.x;
    int bh = bhc >> 5, c = bhc & 31;
    int tid = threadIdx.x, lane = tid & 31, warp = tid >> 5;
    int wm = warp >> 1, wn = warp & 1;

    const __nv_bfloat16* qh = g_qfh + (size_t)bhc*CHc*PMc;
    const __nv_bfloat16* ql = g_qfl + (size_t)bhc*CHc*PMc;
    const __nv_bfloat16* kvh = g_ckvh + (size_t)bhc*PMc*Dc;
    const __nv_bfloat16* kvl = g_ckvl + (size_t)bhc*PMc*Dc;
    const float* ksb = g_ks + (size_t)bhc*PMc;
    ks_sm[tid] = ksb[tid];
    ks_sm[tid+256] = ksb[tid+256];

    int r0 = (tid*2) >> 2, s0 = (tid*2) & 3;
    int r1 = (tid*2+1) >> 2, s1 = (tid*2+1) & 3;
    int kvr = tid >> 3, kvs = tid & 7;
    int lr = lane & 7;
    int a_row = lr + (((lane >> 3) & 1) << 3);
    int a_col = ((lane >> 4) & 1) << 3;
    int t_row = lr + (((lane >> 4) & 1) << 3);
    int t_colbit = ((lane >> 3) & 1) << 3;

    float acc[2][4][4];
    #pragma unroll
    for (int i = 0; i < 2; i++)
        #pragma unroll
        for (int j = 0; j < 4; j++)
            #pragma unroll
            for (int q = 0; q < 4; q++) acc[i][j][q] = 0.f;
    float nacc = 0.f;

    auto load_chunk = [&](int ch, int stage) {
        int k0 = ch * 32;
        u32 st = sb + stage * 29696;
        u32 d0 = st + r0*80 + s0*16;
        u32 d1 = st + r1*80 + s1*16;
        CP_ASYNC16(d0,         qh + (size_t)r0*PMc + k0 + s0*8);
        CP_ASYNC16(d1,         qh + (size_t)r1*PMc + k0 + s1*8);
        CP_ASYNC16(d0 + 10240, ql + (size_t)r0*PMc + k0 + s0*8);
        CP_ASYNC16(d1 + 10240, ql + (size_t)r1*PMc + k0 + s1*8);
        u32 dk = st + 20480 + kvr*144 + kvs*16;
        CP_ASYNC16(dk,        kvh + (size_t)(k0+kvr)*64 + kvs*8);
        CP_ASYNC16(dk + 4608, kvl + (size_t)(k0+kvr)*64 + kvs*8);
        CP_COMMIT();
    };

    load_chunk(0, 0);
    for (int ch = 0; ch < 16; ch++) {
        int stage = ch & 1;
        if (ch + 1 < 16) { load_chunk(ch + 1, stage ^ 1); CP_WAIT1(); }
        else             { CP_WAIT0(); }
        __syncthreads();
        u32 st = sb + stage * 29696;
        #pragma unroll
        for (int ks16 = 0; ks16 < 2; ks16++) {
            u32 afh[2][4], afl[2][4], bvh[2][4], bvl[2][4];
            #pragma unroll
            for (int mi = 0; mi < 2; mi++) {
                u32 addr = st + ((wm*32 + mi*16 + a_row)*40 + ks16*16 + a_col)*2;
                ldsm4(afh[mi][0], afh[mi][1], afh[mi][2], afh[mi][3], addr);
                ldsm4(afl[mi][0], afl[mi][1], afl[mi][2], afl[mi][3], addr + 10240);
            }
            int krow = ks16*16 + t_row;
            #pragma unroll
            for (int nj = 0; nj < 2; nj++) {
                int dc = wn*32 + nj*16 + t_colbit;
                u32 addr = st + 20480 + krow*144 + dc*2;
                ldsm4t(bvh[nj][0], bvh[nj][1], bvh[nj][2], bvh[nj][3], addr);
                ldsm4t(bvl[nj][0], bvl[nj][1], bvl[nj][2], bvl[nj][3], addr + 4608);
            }
            #pragma unroll
            for (int mi = 0; mi < 2; mi++) {
                #pragma unroll
                for (int ng = 0; ng < 4; ng++) {
                    int nj = ng >> 1, sel = ng & 1;
                    mma16816(acc[mi][ng], afh[mi], bvh[nj][sel], bvh[nj][2+sel]);
                    mma16816(acc[mi][ng], afh[mi], bvl[nj][sel], bvl[nj][2+sel]);
                    mma16816(acc[mi][ng], afl[mi], bvh[nj][sel], bvh[nj][2+sel]);
                }
            }
        }
        {
            int tt = tid >> 1, fh = (tid & 1)*16;
            const __nv_bfloat16* qhs = (const __nv_bfloat16*)(sm + stage*29696 + tt*80);
            const __nv_bfloat16* qls = (const __nv_bfloat16*)(sm + stage*29696 + 10240 + tt*80);
            #pragma unroll
            for (int f = 0; f < 16; f++) {
                int fl = fh + f;
                float qv = __bfloat162float(qhs[fl]) + __bfloat162float(qls[fl]);
                nacc += qv * ks_sm[ch*32 + fl];
            }
        }
        __syncthreads();
    }
    nacc += __shfl_xor_sync(0xffffffffu, nacc, 1);
    if ((tid & 1) == 0) nrm_sm[tid >> 1] = nacc;
    __syncthreads();
    if (tid < 128) {
        float tot = nrm_sm[tid] + g_nrm[(size_t)bh*Tc + c*CHc + tid] + 1e-6f;
        nrm_sm[tid] = 1.f / tot;
    }
    __syncthreads();

    float* ob = g_o + ((size_t)bh*Tc + c*CHc)*Dc;
    #pragma unroll
    for (int mi = 0; mi < 2; mi++) {
        #pragma unroll
        for (int ng = 0; ng < 4; ng++) {
            int tok = wm*32 + mi*16 + (lane >> 2);
            int d = wn*32 + ng*8 + (lane & 3)*2;
            float inv0 = nrm_sm[tok], inv1 = nrm_sm[tok+8];
            float2* p0 = (float2*)(ob + (size_t)tok*64 + d);
            float2* p1 = (float2*)(ob + (size_t)(tok+8)*64 + d);
            float2 c0 = *p0, c1 = *p1;
            c0.x = (c0.x + acc[mi][ng][0]) * inv0;
            c0.y = (c0.y + acc[mi][ng][1]) * inv0;
            c1.x = (c1.x + acc[mi][ng][2]) * inv1;
            c1.y = (c1.y + acc[mi][ng][3]) * inv1;
            *p0 = c0; *p1 = c1;
        }
    }
}

// ---------------- host launcher ---------------------------------------------
extern "C" void kernel_launch(void* const* d_in, const int* in_sizes, int n_in,
                              void* d_out, int out_size)
{
    const float* x        = (const float*)d_in[0];
    const float* qkv_w    = (const float*)d_in[1];
    const float* qkv_b    = (const float*)d_in[2];
    const float* out_w    = (const float*)d_in[3];
    const float* out_b    = (const float*)d_in[4];
    const float* omega    = (const float*)d_in[5];
    const float* poly_w   = (const float*)d_in[6];
    const float* qnodes   = (const float*)d_in[7];
    const float* qweights = (const float*)d_in[8];
    float* out = (float*)d_out;

    float* qkv_ptr = 0;
    cudaGetSymbolAddress((void**)&qkv_ptr, g_qkv);
    __nv_bfloat16 *ah, *al, *wh, *wl;
    cudaGetSymbolAddress((void**)&ah, g_ah);
    cudaGetSymbolAddress((void**)&al, g_al);
    cudaGetSymbolAddress((void**)&wh, g_wh);
    cudaGetSymbolAddress((void**)&wl, g_wl);

    cudaFuncSetAttribute(gemm_mma_k, cudaFuncAttributeMaxDynamicSharedMemorySize, 2*S_STAGE);
    cudaFuncSetAttribute(features_k, cudaFuncAttributeMaxDynamicSharedMemorySize, F_SMEM);
    cudaFuncSetAttribute(passA_mma_k, cudaFuncAttributeMaxDynamicSharedMemorySize, 106496);
    cudaFuncSetAttribute(scores_mma_k, cudaFuncAttributeMaxDynamicSharedMemorySize, 106496);
    cudaFuncSetAttribute(hist_mma_k, cudaFuncAttributeMaxDynamicSharedMemorySize, 59392);

    // 1) split operands to bf16 hi/lo
    split_bf16_k<<<(Bc*Tc*Ec)/1024, 256>>>(x, ah, al);
    split_bf16_k<<<(3*Ec*Ec)/1024, 256>>>(qkv_w, wh, wl);
    // 2) QKV GEMM (HMMA)
    gemm_mma_k<<<dim3(3*Ec/128, (Bc*Tc)/128), 256, 2*S_STAGE>>>(
        ah, al, wh, wl, qkv_b, qkv_ptr, 3*Ec);
    // 3) feature maps (coalesced stores, poly_w in smem)
    features_k<<<dim3(BHc*NCc, 2), 256, F_SMEM>>>(omega, poly_w, qnodes, qweights);
    // 4) per-chunk kv + ks (HMMA, v from g_qkv)
    passA_mma_k<<<dim3(BHc*NCc, 4), 256, 106496>>>();
    // 5) fused exclusive prefix + bf16 convert
    prefix_kv_cvt_k<<<(BHc*PMc*Dc)/1024, 256>>>();
    prefix_ks_k<<<(BHc*PMc)/1024, 256>>>();
    // 6) intra-chunk scores + intra context (HMMA)
    scores_mma_k<<<BHc*NCc, 256, 106496>>>();
    // 7) history context + normalize (HMMA)
    hist_mma_k<<<BHc*NCc, 256, 59392>>>();
    // 8) output projection (HMMA)
    o2rows_k<<<(BHc*Tc*Dc)/512, 256>>>();
    split_bf16_k<<<(Ec*Ec)/1024, 256>>>(out_w, wh, wl);
    gemm_mma_k<<<dim3(Ec/128, (Bc*Tc)/128), 256, 2*S_STAGE>>>(
        ah, al, wh, wl, out_b, out, Ec);
}

// round 10
// speedup vs baseline: 3.4286x; 1.1864x over previous
#include <cuda_runtime.h>
#include <cuda_bf16.h>
#include <math.h>

#define Bc 2
#define Tc 4096
#define Ec 1024
#define Hc 16
#define Dc 64
#define Pc 64
#define PMc 512
#define CHc 128
#define NCc 32
#define BHc 32

typedef unsigned long long u64;
typedef unsigned int u32;

// ---------------- scratch (device globals; no allocations allowed) ----------
__device__ float g_qkv[(size_t)Bc*Tc*3*Ec];
__device__ float g_ckv[(size_t)BHc*NCc*PMc*Dc];      // (bhc, f, d) fp32 per-chunk
__device__ float g_ks [(size_t)BHc*NCc*PMc];
__device__ float g_o  [(size_t)BHc*Tc*Dc];
__device__ float g_nrm[(size_t)BHc*Tc];
// bf16 features (hi only), [bhc][token 128][feature 512]
__device__ __align__(16) __nv_bfloat16 g_qf[(size_t)BHc*NCc*CHc*PMc];
__device__ __align__(16) __nv_bfloat16 g_kf[(size_t)BHc*NCc*CHc*PMc];
// bf16 hi/lo exclusive kv state, [bhc][f][d]
__device__ __align__(16) __nv_bfloat16 g_ckvh[(size_t)BHc*NCc*PMc*Dc];
__device__ __align__(16) __nv_bfloat16 g_ckvl[(size_t)BHc*NCc*PMc*Dc];
// bf16 split operands for dense GEMMs
__device__ __align__(16) __nv_bfloat16 g_ah[(size_t)Bc*Tc*Ec];
__device__ __align__(16) __nv_bfloat16 g_al[(size_t)Bc*Tc*Ec];
__device__ __align__(16) __nv_bfloat16 g_wh[(size_t)3*Ec*Ec];
__device__ __align__(16) __nv_bfloat16 g_wl[(size_t)3*Ec*Ec];

// ================= helpers ===================================================
__device__ __forceinline__ u32 smem_u32(const void* p) {
    u32 a; asm("{ .reg .u64 t; cvta.to.shared.u64 t, %1; cvt.u32.u64 %0, t; }"
               : "=r"(a) : "l"(p));
    return a;
}
#define CP_ASYNC16(dst, src) \
    asm volatile("cp.async.cg.shared.global [%0], [%1], 16;\n" :: "r"(dst), "l"(src))
#define CP_COMMIT() asm volatile("cp.async.commit_group;\n" ::: "memory")
#define CP_WAIT1()  asm volatile("cp.async.wait_group 1;\n" ::: "memory")
#define CP_WAIT0()  asm volatile("cp.async.wait_group 0;\n" ::: "memory")

__device__ __forceinline__ void ldsm4(u32 &r0, u32 &r1, u32 &r2, u32 &r3, u32 a) {
    asm volatile("ldmatrix.sync.aligned.m8n8.x4.shared.b16 {%0,%1,%2,%3}, [%4];\n"
                 : "=r"(r0), "=r"(r1), "=r"(r2), "=r"(r3) : "r"(a));
}
__device__ __forceinline__ void ldsm4t(u32 &r0, u32 &r1, u32 &r2, u32 &r3, u32 a) {
    asm volatile("ldmatrix.sync.aligned.m8n8.x4.trans.shared.b16 {%0,%1,%2,%3}, [%4];\n"
                 : "=r"(r0), "=r"(r1), "=r"(r2), "=r"(r3) : "r"(a));
}
__device__ __forceinline__ void mma16816(float* c, const u32* a, u32 b0, u32 b1) {
    asm volatile(
        "mma.sync.aligned.m16n8k16.row.col.f32.bf16.bf16.f32 "
        "{%0,%1,%2,%3},{%4,%5,%6,%7},{%8,%9},{%0,%1,%2,%3};\n"
        : "+f"(c[0]), "+f"(c[1]), "+f"(c[2]), "+f"(c[3])
        : "r"(a[0]), "r"(a[1]), "r"(a[2]), "r"(a[3]), "r"(b0), "r"(b1));
}

// ================= fp32 -> bf16 hi/lo split ==================================
__global__ void split_bf16_k(const float* __restrict__ s,
                             __nv_bfloat16* __restrict__ h,
                             __nv_bfloat16* __restrict__ l)
{
    size_t i = ((size_t)blockIdx.x*256 + threadIdx.x)*4;
    float4 v = *(const float4*)(s + i);
    __nv_bfloat16 h0=__float2bfloat16(v.x), h1=__float2bfloat16(v.y);
    __nv_bfloat16 h2=__float2bfloat16(v.z), h3=__float2bfloat16(v.w);
    __nv_bfloat162 ha = {h0,h1}, hb = {h2,h3};
    __nv_bfloat162 la = {__float2bfloat16(v.x-__bfloat162float(h0)),
                         __float2bfloat16(v.y-__bfloat162float(h1))};
    __nv_bfloat162 lb = {__float2bfloat16(v.z-__bfloat162float(h2)),
                         __float2bfloat16(v.w-__bfloat162float(h3))};
    *(__nv_bfloat162*)(h+i) = ha; *(__nv_bfloat162*)(h+i+2) = hb;
    *(__nv_bfloat162*)(l+i) = la; *(__nv_bfloat162*)(l+i+2) = lb;
}

// ------ reshape g_o (B,H,T,D) -> rows (b*T+t, h*64+d), bf16 hi/lo ------------
__global__ void o2rows_k()
{
    size_t gidx = ((size_t)blockIdx.x*256 + threadIdx.x)*2;
    float2 v = *(const float2*)(g_o + gidx);
    int d = (int)(gidx & 63), t = (int)((gidx >> 6) & 4095);
    int h = (int)((gidx >> 18) & 15), b = (int)(gidx >> 22);
    size_t dst = ((size_t)(b*Tc + t))*Ec + h*64 + d;
    __nv_bfloat16 h0=__float2bfloat16(v.x), h1=__float2bfloat16(v.y);
    *(__nv_bfloat162*)(g_ah+dst) = {h0,h1};
    *(__nv_bfloat162*)(g_al+dst) = {__float2bfloat16(v.x-__bfloat162float(h0)),
                                    __float2bfloat16(v.y-__bfloat162float(h1))};
}

// ================= HMMA GEMM: C[M,N] = A @ W^T + bias (bf16x3 split) ========
#define S_STRIDE 40
#define S_ARR 10240
#define S_STAGE 40960

__global__ __launch_bounds__(256, 2)
void gemm_mma_k(const __nv_bfloat16* __restrict__ Abase_h,
                const __nv_bfloat16* __restrict__ Abase_l,
                const __nv_bfloat16* __restrict__ Wbase_h,
                const __nv_bfloat16* __restrict__ Wbase_l,
                const float* __restrict__ bias, float* __restrict__ C, int N)
{
    extern __shared__ char smem[];
    u32 sb = smem_u32(smem);
    const int K = 1024;
    int tid = threadIdx.x;
    int lane = tid & 31, warp = tid >> 5;
    int wm = warp >> 1, wn = warp & 1;
    int bm = blockIdx.y * 128, bn = blockIdx.x * 128;

    const __nv_bfloat16* Ah = Abase_h + (size_t)bm * K;
    const __nv_bfloat16* Al = Abase_l + (size_t)bm * K;
    const __nv_bfloat16* Wh = Wbase_h + (size_t)bn * K;
    const __nv_bfloat16* Wl = Wbase_l + (size_t)bn * K;

    int r0 = (tid*2) >> 2, s0 = (tid*2) & 3;
    int r1 = (tid*2+1) >> 2, s1 = (tid*2+1) & 3;

    int lr = lane & 7;
    int a_row = lr + (((lane >> 3) & 1) << 3);
    int a_col = ((lane >> 4) & 1) << 3;
    int b_row = lr + (((lane >> 4) & 1) << 3);
    int b_col = ((lane >> 3) & 1) << 3;

    float acc[2][8][4];
    #pragma unroll
    for (int i = 0; i < 2; i++)
        #pragma unroll
        for (int j = 0; j < 8; j++)
            #pragma unroll
            for (int q = 0; q < 4; q++) acc[i][j][q] = 0.f;

    auto load_chunk = [&](int ch, int stage) {
        int k0 = ch * 32;
        u32 st = sb + stage * S_STAGE;
        u32 d0 = st + r0*80 + s0*16;
        u32 d1 = st + r1*80 + s1*16;
        CP_ASYNC16(d0, Ah + (size_t)r0*K + k0 + s0*8);
        CP_ASYNC16(d1, Ah + (size_t)r1*K + k0 + s1*8);
        CP_ASYNC16(d0 + S_ARR, Al + (size_t)r0*K + k0 + s0*8);
        CP_ASYNC16(d1 + S_ARR, Al + (size_t)r1*K + k0 + s1*8);
        CP_ASYNC16(d0 + 2*S_ARR, Wh + (size_t)r0*K + k0 + s0*8);
        CP_ASYNC16(d1 + 2*S_ARR, Wh + (size_t)r1*K + k0 + s1*8);
        CP_ASYNC16(d0 + 3*S_ARR, Wl + (size_t)r0*K + k0 + s0*8);
        CP_ASYNC16(d1 + 3*S_ARR, Wl + (size_t)r1*K + k0 + s1*8);
        CP_COMMIT();
    };

    load_chunk(0, 0);

    for (int ch = 0; ch < 32; ch++) {
        int stage = ch & 1;
        if (ch + 1 < 32) { load_chunk(ch + 1, stage ^ 1); CP_WAIT1(); }
        else             { CP_WAIT0(); }
        __syncthreads();

        u32 st = sb + stage * S_STAGE;
        #pragma unroll
        for (int ks = 0; ks < 2; ks++) {
            u32 afh[2][4], afl[2][4], bfh[4][4], bfl[4][4];
            #pragma unroll
            for (int mi = 0; mi < 2; mi++) {
                u32 addr = st + ((wm*32 + mi*16 + a_row)*S_STRIDE + ks*16 + a_col)*2;
                ldsm4(afh[mi][0], afh[mi][1], afh[mi][2], afh[mi][3], addr);
                ldsm4(afl[mi][0], afl[mi][1], afl[mi][2], afl[mi][3], addr + S_ARR);
            }
            #pragma unroll
            for (int nj = 0; nj < 4; nj++) {
                u32 addr = st + 2*S_ARR +
                           ((wn*64 + nj*16 + b_row)*S_STRIDE + ks*16 + b_col)*2;
                ldsm4(bfh[nj][0], bfh[nj][1], bfh[nj][2], bfh[nj][3], addr);
                ldsm4(bfl[nj][0], bfl[nj][1], bfl[nj][2], bfl[nj][3], addr + S_ARR);
            }
            #pragma unroll
            for (int mi = 0; mi < 2; mi++) {
                #pragma unroll
                for (int ni = 0; ni < 8; ni++) {
                    int nj = ni >> 1, off = (ni & 1) << 1;
                    mma16816(acc[mi][ni], afh[mi], bfh[nj][off], bfh[nj][off+1]);
                    mma16816(acc[mi][ni], afh[mi], bfl[nj][off], bfl[nj][off+1]);
                    mma16816(acc[mi][ni], afl[mi], bfh[nj][off], bfh[nj][off+1]);
                }
            }
        }
        __syncthreads();
    }

    #pragma unroll
    for (int mi = 0; mi < 2; mi++) {
        #pragma unroll
        for (int ni = 0; ni < 8; ni++) {
            int m = bm + wm*32 + mi*16 + (lane >> 2);
            int n = bn + wn*64 + ni*8 + (lane & 3)*2;
            float2 o0, o1;
            o0.x = acc[mi][ni][0] + bias[n];
            o0.y = acc[mi][ni][1] + bias[n+1];
            o1.x = acc[mi][ni][2] + bias[n];
            o1.y = acc[mi][ni][3] + bias[n+1];
            *(float2*)(C + (size_t)m*N + n)     = o0;
            *(float2*)(C + (size_t)(m+8)*N + n) = o1;
        }
    }
}

// ---------------- feature map -> bf16 (hi only) [token][feature] ------------
#define F_XS   0
#define F_PS   (128*68)
#define F_OM   (F_PS + 64*68)
#define F_PRF  (F_OM + 512)
#define F_RN   (F_PRF + 1024)
#define F_SMEM ((F_RN + 128)*4)

__global__ __launch_bounds__(256, 3) void features_k(
    const float* __restrict__ omega, const float* __restrict__ poly_w,
    const float* __restrict__ qnodes, const float* __restrict__ qweights)
{
    extern __shared__ float fsm[];
    float* xs  = fsm + F_XS;           // [token][68]
    float* ps  = fsm + F_PS;           // [d][68]
    float* om  = fsm + F_OM;
    float* prf = fsm + F_PRF;
    float* rn  = fsm + F_RN;
    int bhc = blockIdx.x;
    int isK = blockIdx.y;
    int bh = bhc >> 5, c = bhc & 31;
    int h = bh & 15, b = bh >> 4;
    const float* src = g_qkv + ((size_t)(b*Tc + c*CHc))*(3*Ec) + isK*Ec + h*64;
    __nv_bfloat16* dh = (isK ? g_kf : g_qf) + (size_t)bhc*CHc*PMc;
    int tid = threadIdx.x;
    #pragma unroll
    for (int l = 0; l < 8; l++) {
        int idx = tid + l*256;
        int i = idx >> 4, dd = (idx & 15) << 2;
        float4 v = *(const float4*)(src + (size_t)i*(3*Ec) + dd);
        *(float4*)&xs[i*68 + dd] = v;
    }
    {
        const float* pwp = poly_w + h*4096;
        #pragma unroll
        for (int l = 0; l < 4; l++) {
            int idx = tid + l*256;
            int d = idx >> 4, pc = (idx & 15) << 2;
            *(float4*)&ps[d*68 + pc] = *(const float4*)(pwp + d*64 + pc);
        }
    }
    om[tid]       = omega[h*512 + tid];
    om[tid + 256] = omega[h*512 + tid + 256];
    __syncthreads();
    if (tid < 128) {
        const float* xr = &xs[tid*68];
        float s = 0.f;
        #pragma unroll
        for (int d = 0; d < 64; d++) { float x = xr[d]; s += x*x; }
        rn[tid] = 1.f / fmaxf(sqrtf(s), 1e-12f);
    }
    __syncthreads();
    float s0 = qnodes[0];
    float sq2s = sqrtf(fmaxf(2.f*s0, 0.f));
    float wq = sqrtf(fmaxf(qweights[0], 0.f));
    float prescale = 0.3535533905932738f * wq;
    #pragma unroll
    for (int l = 0; l < 4; l++) {
        int pair = tid + l*256;
        int i = pair >> 3, m = pair & 7;
        const float* xr = &xs[i*68];
        float a = 0.f;
        #pragma unroll
        for (int d = 0; d < 64; d++) a += xr[d] * om[d*8 + m];
        float e = fminf(fmaxf(a * rn[i] * sq2s - s0, -20.f), 20.f);
        prf[i*8 + m] = expf(e) * prescale;
    }
    __syncthreads();
    int ti = (tid >> 4) << 3, tp = tid & 15;
    float acc[8][4] = {};
    for (int d = 0; d < 64; d++) {
        float a[8];
        #pragma unroll
        for (int x = 0; x < 8; x++) a[x] = xs[(ti+x)*68 + d];
        float b0 = ps[d*68 + tp];
        float b1 = ps[d*68 + tp + 16];
        float b2 = ps[d*68 + tp + 32];
        float b3 = ps[d*68 + tp + 48];
        #pragma unroll
        for (int i2 = 0; i2 < 8; i2++) {
            acc[i2][0] += a[i2]*b0; acc[i2][1] += a[i2]*b1;
            acc[i2][2] += a[i2]*b2; acc[i2][3] += a[i2]*b3;
        }
    }
    #pragma unroll
    for (int i2 = 0; i2 < 8; i2++) {
        float r = rn[ti + i2];
        #pragma unroll
        for (int j = 0; j < 4; j++) {
            float t = acc[i2][j] * r;
            acc[i2][j] = t*t*0.125f;
        }
    }
    #pragma unroll
    for (int i2 = 0; i2 < 8; i2++) {
        int tok = ti + i2;
        const float* pr = &prf[tok*8];
        #pragma unroll
        for (int j = 0; j < 4; j++) {
            float base = acc[i2][j];
            __nv_bfloat16 hb[8];
            #pragma unroll
            for (int m = 0; m < 8; m++)
                hb[m] = __float2bfloat16(base * pr[m]);
            size_t off = (size_t)tok*PMc + (tp + j*16)*8;
            *(uint4*)(dh + off) = *(uint4*)hb;
        }
    }
}

// ---------------- pass A (HMMA): kv[f][d] = sum_i kf[i][f] v[i][d] ----------
// kf bf16-only; v split hi/lo. smem: KF[128][272] | VH[128][144] | VL
__global__ __launch_bounds__(256, 2) void passA_mma_k()
{
    extern __shared__ char sm[];
    u32 sb = smem_u32(sm);
    const u32 KF = 0, VH = 34816, VL = 53248;
    int bhc = blockIdx.x, fb = blockIdx.y;
    int bh = bhc >> 5, c = bhc & 31;
    int tid = threadIdx.x, lane = tid & 31, warp = tid >> 5;
    int wm = warp >> 1, wn = warp & 1;

    const __nv_bfloat16* kh = g_kf + (size_t)bhc*CHc*PMc + fb*128;
    #pragma unroll
    for (int l = 0; l < 8; l++) {
        int idx = tid + l*256;
        int row = idx >> 4, seg = idx & 15;
        CP_ASYNC16(sb + KF + row*272 + seg*16, kh + (size_t)row*PMc + seg*8);
    }
    CP_COMMIT();
    const float* vb = g_qkv + ((size_t)((bh>>4)*Tc + c*CHc))*(3*Ec) + 2*Ec + (bh&15)*64;
    #pragma unroll
    for (int l = 0; l < 8; l++) {
        int idx = tid + l*256;
        int i = idx >> 4, dd = (idx & 15)*4;
        float4 v = *(const float4*)(vb + (size_t)i*(3*Ec) + dd);
        __nv_bfloat16 h0=__float2bfloat16(v.x), h1=__float2bfloat16(v.y);
        __nv_bfloat16 h2=__float2bfloat16(v.z), h3=__float2bfloat16(v.w);
        u32 off = i*144 + dd*2;
        *(__nv_bfloat162*)(sm + VH + off)     = {h0,h1};
        *(__nv_bfloat162*)(sm + VH + off + 4) = {h2,h3};
        *(__nv_bfloat162*)(sm + VL + off)     = {__float2bfloat16(v.x-__bfloat162float(h0)),
                                                 __float2bfloat16(v.y-__bfloat162float(h1))};
        *(__nv_bfloat162*)(sm + VL + off + 4) = {__float2bfloat16(v.z-__bfloat162float(h2)),
                                                 __float2bfloat16(v.w-__bfloat162float(h3))};
    }
    CP_WAIT0();
    __syncthreads();

    if (tid < 128) {
        float s = 0.f;
        for (int i = 0; i < 128; i++)
            s += __bfloat162float(*(const __nv_bfloat16*)(sm + KF + i*272 + tid*2));
        g_ks[(size_t)bhc*PMc + fb*128 + tid] = s;
    }

    int t_row = (lane & 7) + (((lane >> 4) & 1) << 3);
    int t_colbit = ((lane >> 3) & 1) << 3;

    float acc[2][4][4];
    #pragma unroll
    for (int i = 0; i < 2; i++)
        #pragma unroll
        for (int j = 0; j < 4; j++)
            #pragma unroll
            for (int q = 0; q < 4; q++) acc[i][j][q] = 0.f;

    #pragma unroll
    for (int ks16 = 0; ks16 < 8; ks16++) {
        int krow = ks16*16 + t_row;
        u32 af[2][4], bvh[2][4], bvl[2][4];
        #pragma unroll
        for (int mi = 0; mi < 2; mi++) {
            int fc = wm*32 + mi*16 + t_colbit;
            ldsm4t(af[mi][0], af[mi][1], af[mi][2], af[mi][3],
                   sb + KF + krow*272 + fc*2);
        }
        #pragma unroll
        for (int nj = 0; nj < 2; nj++) {
            int dc = wn*32 + nj*16 + t_colbit;
            u32 addr = sb + VH + krow*144 + dc*2;
            ldsm4t(bvh[nj][0], bvh[nj][1], bvh[nj][2], bvh[nj][3], addr);
            ldsm4t(bvl[nj][0], bvl[nj][1], bvl[nj][2], bvl[nj][3], addr + (VL-VH));
        }
        #pragma unroll
        for (int mi = 0; mi < 2; mi++) {
            #pragma unroll
            for (int ng = 0; ng < 4; ng++) {
                int nj = ng >> 1, sel = ng & 1;
                mma16816(acc[mi][ng], af[mi], bvh[nj][sel], bvh[nj][2+sel]);
                mma16816(acc[mi][ng], af[mi], bvl[nj][sel], bvl[nj][2+sel]);
            }
        }
    }
    float* outp = g_ckv + (size_t)bhc*PMc*Dc + (size_t)fb*128*Dc;
    #pragma unroll
    for (int mi = 0; mi < 2; mi++) {
        #pragma unroll
        for (int ng = 0; ng < 4; ng++) {
            int f = wm*32 + mi*16 + (lane >> 2);
            int d = wn*32 + ng*8 + (lane & 3)*2;
            *(float2*)(outp + (size_t)f*64 + d)     = make_float2(acc[mi][ng][0], acc[mi][ng][1]);
            *(float2*)(outp + (size_t)(f+8)*64 + d) = make_float2(acc[mi][ng][2], acc[mi][ng][3]);
        }
    }
}

// ------- fused exclusive prefix over chunks + bf16 hi/lo convert -------------
__global__ void prefix_kv_cvt_k()
{
    size_t e = ((size_t)blockIdx.x*256 + threadIdx.x)*4;
    size_t bh = e / (PMc*Dc);
    size_t rem = e % (PMc*Dc);
    float4 acc = make_float4(0.f,0.f,0.f,0.f);
    #pragma unroll
    for (int c = 0; c < NCc; c++) {
        size_t p = (bh*NCc + c)*(size_t)(PMc*Dc) + rem;
        float4 v = *(const float4*)(g_ckv + p);
        __nv_bfloat16 h0=__float2bfloat16(acc.x), h1=__float2bfloat16(acc.y);
        __nv_bfloat16 h2=__float2bfloat16(acc.z), h3=__float2bfloat16(acc.w);
        *(__nv_bfloat162*)(g_ckvh+p)   = {h0,h1};
        *(__nv_bfloat162*)(g_ckvh+p+2) = {h2,h3};
        *(__nv_bfloat162*)(g_ckvl+p)   = {__float2bfloat16(acc.x-__bfloat162float(h0)),
                                          __float2bfloat16(acc.y-__bfloat162float(h1))};
        *(__nv_bfloat162*)(g_ckvl+p+2) = {__float2bfloat16(acc.z-__bfloat162float(h2)),
                                          __float2bfloat16(acc.w-__bfloat162float(h3))};
        acc.x += v.x; acc.y += v.y; acc.z += v.z; acc.w += v.w;
    }
}
__global__ void prefix_ks_k()
{
    size_t e = ((size_t)blockIdx.x*256 + threadIdx.x)*4;
    size_t bh = e / PMc;
    size_t rem = e % PMc;
    float4 acc = make_float4(0.f,0.f,0.f,0.f);
    #pragma unroll
    for (int c = 0; c < NCc; c++) {
        size_t p = (bh*NCc + c)*(size_t)PMc + rem;
        float4 v = *(const float4*)(g_ks + p);
        *(float4*)(g_ks + p) = acc;
        acc.x += v.x; acc.y += v.y; acc.z += v.z; acc.w += v.w;
    }
}

// ---------------- scores (HMMA): S = qf kf^T (bf16), mask, rowsum, S@v ------
// phase1 stage: QF at +0, KF at +10240; stage size 20480
// phase2: SH 0, SL 34816, VH2 69632, VL2 88064 (smem 106496)
__global__ __launch_bounds__(256, 2) void scores_mma_k()
{
    extern __shared__ char sm[];
    __shared__ float rowsum[128];
    u32 sb = smem_u32(sm);
    int bhc = blockIdx.x;
    int bh = bhc >> 5, c = bhc & 31;
    int tid = threadIdx.x, lane = tid & 31, warp = tid >> 5;
    int wm = warp >> 1, wn = warp & 1;
    if (tid < 128) rowsum[tid] = 0.f;

    const __nv_bfloat16* qf = g_qf + (size_t)bhc*CHc*PMc;
    const __nv_bfloat16* kf = g_kf + (size_t)bhc*CHc*PMc;

    int r0 = (tid*2) >> 2, s0 = (tid*2) & 3;
    int r1 = (tid*2+1) >> 2, s1 = (tid*2+1) & 3;
    int lr = lane & 7;
    int a_row = lr + (((lane >> 3) & 1) << 3);
    int a_col = ((lane >> 4) & 1) << 3;
    int b_row = lr + (((lane >> 4) & 1) << 3);
    int b_col = ((lane >> 3) & 1) << 3;

    float acc[2][8][4];
    #pragma unroll
    for (int i = 0; i < 2; i++)
        #pragma unroll
        for (int j = 0; j < 8; j++)
            #pragma unroll
            for (int q = 0; q < 4; q++) acc[i][j][q] = 0.f;

    auto load_chunk = [&](int ch, int stage) {
        int k0 = ch * 32;
        u32 st = sb + stage * 20480;
        u32 d0 = st + r0*80 + s0*16;
        u32 d1 = st + r1*80 + s1*16;
        CP_ASYNC16(d0,         qf + (size_t)r0*PMc + k0 + s0*8);
        CP_ASYNC16(d1,         qf + (size_t)r1*PMc + k0 + s1*8);
        CP_ASYNC16(d0 + 10240, kf + (size_t)r0*PMc + k0 + s0*8);
        CP_ASYNC16(d1 + 10240, kf + (size_t)r1*PMc + k0 + s1*8);
        CP_COMMIT();
    };

    load_chunk(0, 0);
    for (int ch = 0; ch < 16; ch++) {
        int stage = ch & 1;
        if (ch + 1 < 16) { load_chunk(ch + 1, stage ^ 1); CP_WAIT1(); }
        else             { CP_WAIT0(); }
        __syncthreads();
        u32 st = sb + stage * 20480;
        #pragma unroll
        for (int ks = 0; ks < 2; ks++) {
            u32 af[2][4], bf[4][4];
            #pragma unroll
            for (int mi = 0; mi < 2; mi++) {
                u32 addr = st + ((wm*32 + mi*16 + a_row)*40 + ks*16 + a_col)*2;
                ldsm4(af[mi][0], af[mi][1], af[mi][2], af[mi][3], addr);
            }
            #pragma unroll
            for (int nj = 0; nj < 4; nj++) {
                u32 addr = st + 10240 + ((wn*64 + nj*16 + b_row)*40 + ks*16 + b_col)*2;
                ldsm4(bf[nj][0], bf[nj][1], bf[nj][2], bf[nj][3], addr);
            }
            #pragma unroll
            for (int mi = 0; mi < 2; mi++) {
                #pragma unroll
                for (int ni = 0; ni < 8; ni++) {
                    int nj = ni >> 1, off = (ni & 1) << 1;
                    mma16816(acc[mi][ni], af[mi], bf[nj][off], bf[nj][off+1]);
                }
            }
        }
        __syncthreads();
    }

    #pragma unroll
    for (int mi = 0; mi < 2; mi++) {
        float rs0 = 0.f, rs1 = 0.f;
        int ri0 = wm*32 + mi*16 + (lane >> 2);
        #pragma unroll
        for (int ni = 0; ni < 8; ni++) {
            int cj = wn*64 + ni*8 + (lane & 3)*2;
            float v00 = (cj   <= ri0)   ? acc[mi][ni][0] : 0.f;
            float v01 = (cj+1 <= ri0)   ? acc[mi][ni][1] : 0.f;
            float v10 = (cj   <= ri0+8) ? acc[mi][ni][2] : 0.f;
            float v11 = (cj+1 <= ri0+8) ? acc[mi][ni][3] : 0.f;
            rs0 += v00 + v01; rs1 += v10 + v11;
            __nv_bfloat16 h00=__float2bfloat16(v00), h01=__float2bfloat16(v01);
            __nv_bfloat16 h10=__float2bfloat16(v10), h11=__float2bfloat16(v11);
            u32 o0 = ri0*272 + cj*2, o1 = (ri0+8)*272 + cj*2;
            *(__nv_bfloat162*)(sm + o0)         = {h00,h01};
            *(__nv_bfloat162*)(sm + o1)         = {h10,h11};
            *(__nv_bfloat162*)(sm + 34816 + o0) = {__float2bfloat16(v00-__bfloat162float(h00)),
                                                   __float2bfloat16(v01-__bfloat162float(h01))};
            *(__nv_bfloat162*)(sm + 34816 + o1) = {__float2bfloat16(v10-__bfloat162float(h10)),
                                                   __float2bfloat16(v11-__bfloat162float(h11))};
        }
        rs0 += __shfl_xor_sync(0xffffffffu, rs0, 1);
        rs0 += __shfl_xor_sync(0xffffffffu, rs0, 2);
        rs1 += __shfl_xor_sync(0xffffffffu, rs1, 1);
        rs1 += __shfl_xor_sync(0xffffffffu, rs1, 2);
        if ((lane & 3) == 0) {
            atomicAdd(&rowsum[ri0], rs0);
            atomicAdd(&rowsum[ri0+8], rs1);
        }
    }
    const float* vb = g_qkv + ((size_t)((bh>>4)*Tc + c*CHc))*(3*Ec) + 2*Ec + (bh&15)*64;
    #pragma unroll
    for (int l = 0; l < 8; l++) {
        int idx = tid + l*256;
        int i = idx >> 4, dd = (idx & 15)*4;
        float4 v = *(const float4*)(vb + (size_t)i*(3*Ec) + dd);
        __nv_bfloat16 h0=__float2bfloat16(v.x), h1=__float2bfloat16(v.y);
        __nv_bfloat16 h2=__float2bfloat16(v.z), h3=__float2bfloat16(v.w);
        u32 off = 69632 + i*144 + dd*2;
        *(__nv_bfloat162*)(sm + off)     = {h0,h1};
        *(__nv_bfloat162*)(sm + off + 4) = {h2,h3};
        *(__nv_bfloat162*)(sm + off + (88064-69632))     = {__float2bfloat16(v.x-__bfloat162float(h0)),
                                                            __float2bfloat16(v.y-__bfloat162float(h1))};
        *(__nv_bfloat162*)(sm + off + (88064-69632) + 4) = {__float2bfloat16(v.z-__bfloat162float(h2)),
                                                            __float2bfloat16(v.w-__bfloat162float(h3))};
    }
    __syncthreads();
    if (tid < 128) g_nrm[(size_t)bh*Tc + c*CHc + tid] = rowsum[tid];

    int t_row = (lane & 7) + (((lane >> 4) & 1) << 3);
    int t_colbit = ((lane >> 3) & 1) << 3;
    float acc2[2][4][4];
    #pragma unroll
    for (int i = 0; i < 2; i++)
        #pragma unroll
        for (int j = 0; j < 4; j++)
            #pragma unroll
            for (int q = 0; q < 4; q++) acc2[i][j][q] = 0.f;

    #pragma unroll
    for (int ks16 = 0; ks16 < 8; ks16++) {
        u32 ah2[2][4], al2[2][4], bvh[2][4], bvl[2][4];
        #pragma unroll
        for (int mi = 0; mi < 2; mi++) {
            u32 addr = sb + ((wm*32 + mi*16 + a_row)*136 + ks16*16 + a_col)*2;
            ldsm4(ah2[mi][0], ah2[mi][1], ah2[mi][2], ah2[mi][3], addr);
            ldsm4(al2[mi][0], al2[mi][1], al2[mi][2], al2[mi][3], addr + 34816);
        }
        int krow = ks16*16 + t_row;
        #pragma unroll
        for (int nj = 0; nj < 2; nj++) {
            int dc = wn*32 + nj*16 + t_colbit;
            u32 addr = sb + 69632 + krow*144 + dc*2;
            ldsm4t(bvh[nj][0], bvh[nj][1], bvh[nj][2], bvh[nj][3], addr);
            ldsm4t(bvl[nj][0], bvl[nj][1], bvl[nj][2], bvl[nj][3], addr + (88064-69632));
        }
        #pragma unroll
        for (int mi = 0; mi < 2; mi++) {
            #pragma unroll
            for (int ng = 0; ng < 4; ng++) {
                int nj = ng >> 1, sel = ng & 1;
                mma16816(acc2[mi][ng], ah2[mi], bvh[nj][sel], bvh[nj][2+sel]);
                mma16816(acc2[mi][ng], ah2[mi], bvl[nj][sel], bvl[nj][2+sel]);
                mma16816(acc2[mi][ng], al2[mi], bvh[nj][sel], bvh[nj][2+sel]);
            }
        }
    }
    float* ob = g_o + ((size_t)bh*Tc + c*CHc)*Dc;
    #pragma unroll
    for (int mi = 0; mi < 2; mi++) {
        #pragma unroll
        for (int ng = 0; ng < 4; ng++) {
            int tok = wm*32 + mi*16 + (lane >> 2);
            int d = wn*32 + ng*8 + (lane & 3)*2;
            *(float2*)(ob + (size_t)tok*64 + d)     = make_float2(acc2[mi][ng][0], acc2[mi][ng][1]);
            *(float2*)(ob + (size_t)(tok+8)*64 + d) = make_float2(acc2[mi][ng][2], acc2[mi][ng][3]);
        }
    }
}

// ---------------- hist (HMMA): ctx = qf(bf16) @ kv_state^T(hi/lo) -----------
// stage: QF +0 (10240), KVH +10240 (4608), KVL +14848 (4608); stage 19456
__global__ __launch_bounds__(256, 2) void hist_mma_k()
{
    extern __shared__ char sm[];
    __shared__ float ks_sm[512];
    __shared__ float nrm_sm[128];
    u32 sb = smem_u32(sm);
    int bhc = blockIdx.x;
    int bh = bhc >> 5, c = bhc & 31;
    int tid = threadIdx.x, lane = tid & 31, warp = tid >> 5;
    int wm = warp >> 1, wn = warp & 1;

    const __nv_bfloat16* qf = g_qf + (size_t)bhc*CHc*PMc;
    const __nv_bfloat16* kvh = g_ckvh + (size_t)bhc*PMc*Dc;
    const __nv_bfloat16* kvl = g_ckvl + (size_t)bhc*PMc*Dc;
    const float* ksb = g_ks + (size_t)bhc*PMc;
    ks_sm[tid] = ksb[tid];
    ks_sm[tid+256] = ksb[tid+256];

    int r0 = (tid*2) >> 2, s0 = (tid*2) & 3;
    int r1 = (tid*2+1) >> 2, s1 = (tid*2+1) & 3;
    int kvr = tid >> 3, kvs = tid & 7;
    int lr = lane & 7;
    int a_row = lr + (((lane >> 3) & 1) << 3);
    int a_col = ((lane >> 4) & 1) << 3;
    int t_row = lr + (((lane >> 4) & 1) << 3);
    int t_colbit = ((lane >> 3) & 1) << 3;

    float acc[2][4][4];
    #pragma unroll
    for (int i = 0; i < 2; i++)
        #pragma unroll
        for (int j = 0; j < 4; j++)
            #pragma unroll
            for (int q = 0; q < 4; q++) acc[i][j][q] = 0.f;
    float nacc = 0.f;

    auto load_chunk = [&](int ch, int stage) {
        int k0 = ch * 32;
        u32 st = sb + stage * 19456;
        u32 d0 = st + r0*80 + s0*16;
        u32 d1 = st + r1*80 + s1*16;
        CP_ASYNC16(d0, qf + (size_t)r0*PMc + k0 + s0*8);
        CP_ASYNC16(d1, qf + (size_t)r1*PMc + k0 + s1*8);
        u32 dk = st + 10240 + kvr*144 + kvs*16;
        CP_ASYNC16(dk,        kvh + (size_t)(k0+kvr)*64 + kvs*8);
        CP_ASYNC16(dk + 4608, kvl + (size_t)(k0+kvr)*64 + kvs*8);
        CP_COMMIT();
    };

    load_chunk(0, 0);
    for (int ch = 0; ch < 16; ch++) {
        int stage = ch & 1;
        if (ch + 1 < 16) { load_chunk(ch + 1, stage ^ 1); CP_WAIT1(); }
        else             { CP_WAIT0(); }
        __syncthreads();
        u32 st = sb + stage * 19456;
        #pragma unroll
        for (int ks16 = 0; ks16 < 2; ks16++) {
            u32 af[2][4], bvh[2][4], bvl[2][4];
            #pragma unroll
            for (int mi = 0; mi < 2; mi++) {
                u32 addr = st + ((wm*32 + mi*16 + a_row)*40 + ks16*16 + a_col)*2;
                ldsm4(af[mi][0], af[mi][1], af[mi][2], af[mi][3], addr);
            }
            int krow = ks16*16 + t_row;
            #pragma unroll
            for (int nj = 0; nj < 2; nj++) {
                int dc = wn*32 + nj*16 + t_colbit;
                u32 addr = st + 10240 + krow*144 + dc*2;
                ldsm4t(bvh[nj][0], bvh[nj][1], bvh[nj][2], bvh[nj][3], addr);
                ldsm4t(bvl[nj][0], bvl[nj][1], bvl[nj][2], bvl[nj][3], addr + 4608);
            }
            #pragma unroll
            for (int mi = 0; mi < 2; mi++) {
                #pragma unroll
                for (int ng = 0; ng < 4; ng++) {
                    int nj = ng >> 1, sel = ng & 1;
                    mma16816(acc[mi][ng], af[mi], bvh[nj][sel], bvh[nj][2+sel]);
                    mma16816(acc[mi][ng], af[mi], bvl[nj][sel], bvl[nj][2+sel]);
                }
            }
        }
        {
            int tt = tid >> 1, fh = (tid & 1)*16;
            const __nv_bfloat16* qs = (const __nv_bfloat16*)(sm + stage*19456 + tt*80);
            #pragma unroll
            for (int f = 0; f < 16; f++) {
                int fl = fh + f;
                nacc += __bfloat162float(qs[fl]) * ks_sm[ch*32 + fl];
            }
        }
        __syncthreads();
    }
    nacc += __shfl_xor_sync(0xffffffffu, nacc, 1);
    if ((tid & 1) == 0) nrm_sm[tid >> 1] = nacc;
    __syncthreads();
    if (tid < 128) {
        float tot = nrm_sm[tid] + g_nrm[(size_t)bh*Tc + c*CHc + tid] + 1e-6f;
        nrm_sm[tid] = 1.f / tot;
    }
    __syncthreads();

    float* ob = g_o + ((size_t)bh*Tc + c*CHc)*Dc;
    #pragma unroll
    for (int mi = 0; mi < 2; mi++) {
        #pragma unroll
        for (int ng = 0; ng < 4; ng++) {
            int tok = wm*32 + mi*16 + (lane >> 2);
            int d = wn*32 + ng*8 + (lane & 3)*2;
            float inv0 = nrm_sm[tok], inv1 = nrm_sm[tok+8];
            float2* p0 = (float2*)(ob + (size_t)tok*64 + d);
            float2* p1 = (float2*)(ob + (size_t)(tok+8)*64 + d);
            float2 c0 = *p0, c1 = *p1;
            c0.x = (c0.x + acc[mi][ng][0]) * inv0;
            c0.y = (c0.y + acc[mi][ng][1]) * inv0;
            c1.x = (c1.x + acc[mi][ng][2]) * inv1;
            c1.y = (c1.y + acc[mi][ng][3]) * inv1;
            *p0 = c0; *p1 = c1;
        }
    }
}

// ---------------- host launcher ---------------------------------------------
extern "C" void kernel_launch(void* const* d_in, const int* in_sizes, int n_in,
                              void* d_out, int out_size)
{
    const float* x        = (const float*)d_in[0];
    const float* qkv_w    = (const float*)d_in[1];
    const float* qkv_b    = (const float*)d_in[2];
    const float* out_w    = (const float*)d_in[3];
    const float* out_b    = (const float*)d_in[4];
    const float* omega    = (const float*)d_in[5];
    const float* poly_w   = (const float*)d_in[6];
    const float* qnodes   = (const float*)d_in[7];
    const float* qweights = (const float*)d_in[8];
    float* out = (float*)d_out;

    float* qkv_ptr = 0;
    cudaGetSymbolAddress((void**)&qkv_ptr, g_qkv);
    __nv_bfloat16 *ah, *al, *wh, *wl;
    cudaGetSymbolAddress((void**)&ah, g_ah);
    cudaGetSymbolAddress((void**)&al, g_al);
    cudaGetSymbolAddress((void**)&wh, g_wh);
    cudaGetSymbolAddress((void**)&wl, g_wl);

    cudaFuncSetAttribute(gemm_mma_k, cudaFuncAttributeMaxDynamicSharedMemorySize, 2*S_STAGE);
    cudaFuncSetAttribute(features_k, cudaFuncAttributeMaxDynamicSharedMemorySize, F_SMEM);
    cudaFuncSetAttribute(passA_mma_k, cudaFuncAttributeMaxDynamicSharedMemorySize, 71680);
    cudaFuncSetAttribute(scores_mma_k, cudaFuncAttributeMaxDynamicSharedMemorySize, 106496);
    cudaFuncSetAttribute(hist_mma_k, cudaFuncAttributeMaxDynamicSharedMemorySize, 38912);

    // 1) split operands to bf16 hi/lo
    split_bf16_k<<<(Bc*Tc*Ec)/1024, 256>>>(x, ah, al);
    split_bf16_k<<<(3*Ec*Ec)/1024, 256>>>(qkv_w, wh, wl);
    // 2) QKV GEMM (HMMA, bf16x3)
    gemm_mma_k<<<dim3(3*Ec/128, (Bc*Tc)/128), 256, 2*S_STAGE>>>(
        ah, al, wh, wl, qkv_b, qkv_ptr, 3*Ec);
    // 3) feature maps -> bf16 (hi only)
    features_k<<<dim3(BHc*NCc, 2), 256, F_SMEM>>>(omega, poly_w, qnodes, qweights);
    // 4) per-chunk kv + ks (HMMA, kf bf16 x v split)
    passA_mma_k<<<dim3(BHc*NCc, 4), 256, 71680>>>();
    // 5) fused exclusive prefix + bf16 convert
    prefix_kv_cvt_k<<<(BHc*PMc*Dc)/1024, 256>>>();
    prefix_ks_k<<<(BHc*PMc)/1024, 256>>>();
    // 6) intra-chunk scores + intra context (HMMA)
    scores_mma_k<<<BHc*NCc, 256, 106496>>>();
    // 7) history context + normalize (HMMA)
    hist_mma_k<<<BHc*NCc, 256, 38912>>>();
    // 8) output projection (HMMA, bf16x3)
    o2rows_k<<<(BHc*Tc*Dc)/512, 256>>>();
    split_bf16_k<<<(Ec*Ec)/1024, 256>>>(out_w, wh, wl);
    gemm_mma_k<<<dim3(Ec/128, (Bc*Tc)/128), 256, 2*S_STAGE>>>(
        ah, al, wh, wl, out_b, out, Ec);
}